// round 2
// baseline (speedup 1.0000x reference)
#include <cuda_runtime.h>
#include <math.h>

// ---------------------------------------------------------------------------
// Problem constants (B=1, C=256, H=W=64, FC=256, kernels 3/5/7 -> 83 points)
// ---------------------------------------------------------------------------
#define HWSZ 4096          // 64*64
#define CIN  256
#define NPTS 83            // 9 + 25 + 49
#define RTOT 21248         // 83*256  (total reduction length across all points)

// ---------------------------------------------------------------------------
// Device scratch (no allocation allowed -> __device__ globals). ~114 MB total.
// ---------------------------------------------------------------------------
__device__ __align__(16) int   g_cidx[NPTS * HWSZ * 4];   // clipped corner indices
__device__ __align__(16) float g_cw  [NPTS * HWSZ * 4];   // bilinear weight * validity
__device__ float g_wt[3][(size_t)256 * RTOT];             // transposed weights (cls,kpt,bbox)
__device__ float g_dfm[3][(size_t)768 * HWSZ];            // relu(deform conv) per branch

// ---------------------------------------------------------------------------
// Packed f32x2 helpers (Blackwell: FFMA2 only reachable via PTX fma.rn.f32x2)
// ---------------------------------------------------------------------------
__device__ __forceinline__ unsigned long long pack2(float lo, float hi) {
    unsigned long long r;
    asm("mov.b64 %0, {%1, %2};" : "=l"(r) : "f"(lo), "f"(hi));
    return r;
}
__device__ __forceinline__ void unpack2(unsigned long long v, float& lo, float& hi) {
    asm("mov.b64 {%0, %1}, %2;" : "=f"(lo), "=f"(hi) : "l"(v));
}
#define FFMA2(d, a, b) \
    asm("fma.rn.f32x2 %0, %1, %2, %0;" : "+l"(d) : "l"(a), "l"(b))

// ---------------------------------------------------------------------------
// Kernel 1: fused offset 1x1 conv + bilinear corner table.
//   For point kk at (h,w): y = h + doff_y, x = w + doff_x  (base offsets cancel)
//   doff channels: k3 [0,18), k5 [18,68), k7 [68,166); layout [point][y,x]
// ---------------------------------------------------------------------------
__global__ void k_corners(const float* __restrict__ kprev,
                          const float* __restrict__ w_do,
                          const float* __restrict__ b_do)
{
    int kk = blockIdx.x;                       // 0..82
    int hw = blockIdx.y * 256 + threadIdx.x;   // 0..4095
    int h = hw >> 6, w = hw & 63;

    int base, kkl;
    if (kk < 9)       { base = 0;  kkl = kk;      }
    else if (kk < 34) { base = 18; kkl = kk - 9;  }
    else              { base = 68; kkl = kk - 34; }
    int chy = base + 2 * kkl;
    int chx = chy + 1;

    float dy = b_do[chy], dx = b_do[chx];
    #pragma unroll 2
    for (int i = 0; i < 34; i++) {
        float v = kprev[i * HWSZ + hw];
        dy = fmaf(w_do[chy * 34 + i], v, dy);
        dx = fmaf(w_do[chx * 34 + i], v, dx);
    }

    float y = (float)h + dy;
    float x = (float)w + dx;
    float y0f = floorf(y), x0f = floorf(x);
    int y0 = (int)y0f, x0 = (int)x0f;
    float wy = y - y0f, wx = x - x0f;

    int   yi[4] = { y0, y0, y0 + 1, y0 + 1 };
    int   xi[4] = { x0, x0 + 1, x0, x0 + 1 };
    float wb[4] = { (1.f - wy) * (1.f - wx), (1.f - wy) * wx,
                    wy * (1.f - wx),         wy * wx };

    int o = (kk * HWSZ + hw) * 4;
    #pragma unroll
    for (int j = 0; j < 4; j++) {
        bool valid = (yi[j] >= 0) && (yi[j] < 64) && (xi[j] >= 0) && (xi[j] < 64);
        int yc = min(max(yi[j], 0), 63);
        int xc = min(max(xi[j], 0), 63);
        g_cidx[o + j] = yc * 64 + xc;
        g_cw  [o + j] = valid ? wb[j] : 0.0f;
    }
}

// ---------------------------------------------------------------------------
// Kernel 2: weight transpose into GEMM layout.
//   src w[o][c][kkl]  ->  g_wt[branch][o*RTOT + (kbase+kkl)*256 + c]
// ---------------------------------------------------------------------------
struct W9 { const float* p[9]; };

__global__ void k_wt(W9 ws)
{
    int sub = blockIdx.z;                // 0..8  (branch*3 + ks)
    int branch = sub / 3;
    int ks = sub - branch * 3;
    int Kp    = (ks == 0) ? 9 : (ks == 1) ? 25 : 49;
    int kbase = (ks == 0) ? 0 : (ks == 1) ? 9  : 34;
    int n = 256 * 256 * Kp;
    const float* src = ws.p[sub];
    float* dst = g_wt[branch];
    for (int e = blockIdx.x * blockDim.x + threadIdx.x; e < n;
         e += gridDim.x * blockDim.x) {
        int o   = e / (256 * Kp);
        int rem = e - o * (256 * Kp);
        int c   = rem / Kp;
        int kkl = rem - c * Kp;
        dst[(size_t)o * RTOT + (size_t)(kbase + kkl) * 256 + c] = src[e];
    }
}

// ---------------------------------------------------------------------------
// Kernel 3: batched SGEMM with FUSED bilinear gather (9 sub-GEMMs, blockIdx.z).
//   C[256,4096] = A[256,Ksub] * B[Ksub,4096], ReLU fused.
//   B rows are built on the fly: row gk = gp*256 + c samples feat[c] at the
//   4 corner taps of point gp (corner table cached in smem per point).
//   Tile 128x128x8, 256 threads, 8x8 per thread, packed f32x2 FMA.
// ---------------------------------------------------------------------------
__global__ void __launch_bounds__(256, 2) k_gemm(const float* __restrict__ f0,
                                                 const float* __restrict__ f1)
{
    const int P0_[3] = {0, 9, 34};   // first global point per kernel size
    const int NP_[3] = {9, 25, 49};  // points per kernel size

    int sub = blockIdx.z;
    int branch = sub / 3;
    int ks = sub - branch * 3;
    int p0 = P0_[ks];
    int np = NP_[ks];
    const float* __restrict__ feat = (branch == 0) ? f0 : f1;
    const float* __restrict__ A = g_wt[branch];                       // row stride RTOT
    float* __restrict__ Cp = g_dfm[branch] + (size_t)ks * 256 * HWSZ; // row stride HWSZ

    int m0 = blockIdx.y * 128;
    int n0 = blockIdx.x * 128;

    __shared__ __align__(16) float As[8][128];
    __shared__ __align__(16) float Bs[8][128];
    __shared__ __align__(16) int4   sIdx[128];
    __shared__ __align__(16) float4 sW[128];

    int tid = threadIdx.x;
    int tx = tid & 15;          // 16 cols of threads (8 n each)
    int ty = tid >> 4;          // 16 rows of threads (8 m each)

    unsigned long long acc2[8][4];
    #pragma unroll
    for (int i = 0; i < 8; i++)
        #pragma unroll
        for (int j = 0; j < 4; j++) acc2[i][j] = 0ULL;

    for (int p = 0; p < np; p++) {
        int gp = p0 + p;
        __syncthreads();   // previous tiles fully consumed before corner reload
        if (tid < 128) {
            int o = (gp * HWSZ + n0 + tid) * 4;
            sIdx[tid] = *reinterpret_cast<const int4*>(&g_cidx[o]);
            sW[tid]   = *reinterpret_cast<const float4*>(&g_cw[o]);
        }
        __syncthreads();

        for (int cs = 0; cs < 32; cs++) {        // 8 channels per step
            int c0 = cs * 8;
            int gk0 = gp * 256 + c0;             // global K index of slab start

            // A tile: 128x8, one float4 per thread (all offsets /4 aligned)
            {
                int e = tid * 4;
                int m = e >> 3;
                int kc = e & 7;
                const float4 av = *reinterpret_cast<const float4*>(
                    A + (size_t)(m0 + m) * RTOT + gk0 + kc);
                As[kc + 0][m] = av.x;
                As[kc + 1][m] = av.y;
                As[kc + 2][m] = av.z;
                As[kc + 3][m] = av.w;
            }
            // B tile: 8x128 built by bilinear gather from feat
            #pragma unroll
            for (int j = 0; j < 4; j++) {
                int e = tid + j * 256;
                int kk = e >> 7;
                int n = e & 127;
                const float* fc = feat + (size_t)(c0 + kk) * HWSZ;
                int4   id = sIdx[n];
                float4 wv = sW[n];
                float v = wv.x * fc[id.x];
                v = fmaf(wv.y, fc[id.y], v);
                v = fmaf(wv.z, fc[id.z], v);
                v = fmaf(wv.w, fc[id.w], v);
                Bs[kk][n] = v;
            }
            __syncthreads();

            #pragma unroll
            for (int kk = 0; kk < 8; kk++) {
                unsigned long long a2[8], b2[4];
                #pragma unroll
                for (int j = 0; j < 4; j++)
                    b2[j] = *reinterpret_cast<const unsigned long long*>(
                        &Bs[kk][tx * 8 + j * 2]);
                #pragma unroll
                for (int i = 0; i < 8; i++) {
                    float a = As[kk][ty * 8 + i];
                    a2[i] = pack2(a, a);
                }
                #pragma unroll
                for (int i = 0; i < 8; i++)
                    #pragma unroll
                    for (int j = 0; j < 4; j++)
                        FFMA2(acc2[i][j], a2[i], b2[j]);
            }
            __syncthreads();
        }
    }

    #pragma unroll
    for (int i = 0; i < 8; i++) {
        size_t row = (size_t)(m0 + ty * 8 + i) * HWSZ + n0 + tx * 8;
        #pragma unroll
        for (int j = 0; j < 4; j++) {
            float lo, hi;
            unpack2(acc2[i][j], lo, hi);
            Cp[row + j * 2 + 0] = fmaxf(lo, 0.f);
            Cp[row + j * 2 + 1] = fmaxf(hi, 0.f);
        }
    }
}

// ---------------------------------------------------------------------------
// Kernel 4: cls head.  out[0 .. 13*HWSZ) = w_cls[13,768] @ dfm0 + b_cls
// ---------------------------------------------------------------------------
__global__ void __launch_bounds__(128) k_head_cls(const float* __restrict__ wcls,
                                                  const float* __restrict__ bcls,
                                                  float* __restrict__ out)
{
    int hw = blockIdx.x * 128 + threadIdx.x;
    float acc[13];
    #pragma unroll
    for (int o = 0; o < 13; o++) acc[o] = bcls[o];
    const float* __restrict__ d = g_dfm[0];
    for (int c = 0; c < 768; c++) {
        float v = d[(size_t)c * HWSZ + hw];
        #pragma unroll
        for (int o = 0; o < 13; o++)
            acc[o] = fmaf(wcls[o * 768 + c], v, acc[o]);
    }
    #pragma unroll
    for (int o = 0; o < 13; o++) out[o * HWSZ + hw] = acc[o];
}

// ---------------------------------------------------------------------------
// Kernel 5: kpt head + bbox head + minmax bbox decode (fused).
//   kpt_offset = w_kpt @ dfm1 + b_kpt + kpt_offset_prev   -> out[17*HWSZ ...)
//   bbox_param = w_bbox @ dfm2 + b_bbox
//   bbox decode (min/max over 17 pts, exp scaling)        -> out[13*HWSZ ...)
// ---------------------------------------------------------------------------
__global__ void __launch_bounds__(128) k_head_pts(const float* __restrict__ wkpt,
                                                  const float* __restrict__ bkpt,
                                                  const float* __restrict__ wbb,
                                                  const float* __restrict__ bbb,
                                                  const float* __restrict__ kprev,
                                                  float* __restrict__ out)
{
    int hw = blockIdx.x * 128 + threadIdx.x;
    float acck[34], accb[4];
    #pragma unroll
    for (int o = 0; o < 34; o++) acck[o] = bkpt[o];
    #pragma unroll
    for (int o = 0; o < 4; o++)  accb[o] = bbb[o];

    const float* __restrict__ dk = g_dfm[1];
    const float* __restrict__ db = g_dfm[2];
    for (int c = 0; c < 768; c++) {
        float vk = dk[(size_t)c * HWSZ + hw];
        float vb = db[(size_t)c * HWSZ + hw];
        #pragma unroll
        for (int o = 0; o < 34; o++)
            acck[o] = fmaf(wkpt[o * 768 + c], vk, acck[o]);
        #pragma unroll
        for (int o = 0; o < 4; o++)
            accb[o] = fmaf(wbb[o * 768 + c], vb, accb[o]);
    }

    #pragma unroll
    for (int o = 0; o < 34; o++) {
        acck[o] += kprev[o * HWSZ + hw];
        out[(17 + o) * HWSZ + hw] = acck[o];
    }

    float left = 1e30f, right = -1e30f, top = 1e30f, bot = -1e30f;
    #pragma unroll
    for (int i = 0; i < 17; i++) {
        float py = acck[2 * i];
        float px = acck[2 * i + 1];
        top   = fminf(top, py);   bot   = fmaxf(bot, py);
        left  = fminf(left, px);  right = fmaxf(right, px);
    }
    float cx = (left + right) * 0.5f;
    float cy = (top + bot) * 0.5f;
    float hwid = (cx - left) * expf(accb[0]);
    float hhei = (cy - top)  * expf(accb[1]);
    cx += accb[2];
    cy += accb[3];
    out[(13 + 0) * HWSZ + hw] = cx - hwid;
    out[(13 + 1) * HWSZ + hw] = cy - hhei;
    out[(13 + 2) * HWSZ + hw] = cx + hwid;
    out[(13 + 3) * HWSZ + hw] = cy + hhei;
}

// ---------------------------------------------------------------------------
// Launch
// ---------------------------------------------------------------------------
extern "C" void kernel_launch(void* const* d_in, const int* in_sizes, int n_in,
                              void* d_out, int out_size)
{
    const float* cls_feat = (const float*)d_in[0];
    const float* pts_feat = (const float*)d_in[1];
    const float* kprev    = (const float*)d_in[2];
    const float* w_do     = (const float*)d_in[3];
    const float* b_do     = (const float*)d_in[4];
    // branch weights: cls 5..7, kpt 8..10, bbox 11..13
    const float* w_cls    = (const float*)d_in[14];
    const float* b_cls    = (const float*)d_in[15];
    const float* w_kpt    = (const float*)d_in[16];
    const float* b_kpt    = (const float*)d_in[17];
    const float* w_bbox   = (const float*)d_in[18];
    const float* b_bbox   = (const float*)d_in[19];
    float* out = (float*)d_out;

    // 1) offsets + bilinear corner table
    k_corners<<<dim3(NPTS, HWSZ / 256), 256>>>(kprev, w_do, b_do);

    // 2) weight transpose
    W9 ws;
    for (int i = 0; i < 9; i++) ws.p[i] = (const float*)d_in[5 + i];
    k_wt<<<dim3(64, 1, 9), 256>>>(ws);

    // 3) 9 sub-GEMMs (3 branches x 3 kernel sizes), gather fused, ReLU fused
    k_gemm<<<dim3(HWSZ / 128, 2, 9), 256>>>(cls_feat, pts_feat);

    // 4) heads
    k_head_cls<<<HWSZ / 128, 128>>>(w_cls, b_cls, out);
    k_head_pts<<<HWSZ / 128, 128>>>(w_kpt, b_kpt, w_bbox, b_bbox, kprev, out);
}

// round 3
// speedup vs baseline: 1.3468x; 1.3468x over previous
#include <cuda_runtime.h>
#include <math.h>

// ---------------------------------------------------------------------------
// Problem constants (B=1, C=256, H=W=64, FC=256, kernels 3/5/7 -> 83 points)
// ---------------------------------------------------------------------------
#define HWSZ 4096          // 64*64
#define CIN  256
#define NPTS 83            // 9 + 25 + 49
#define RTOT 21248         // 83*256  (total reduction length across all points)

// ---------------------------------------------------------------------------
// Device scratch (no allocation allowed -> __device__ globals). ~114 MB total.
// ---------------------------------------------------------------------------
__device__ __align__(16) int   g_cidx[NPTS * HWSZ * 4];   // clipped corner indices
__device__ __align__(16) float g_cw  [NPTS * HWSZ * 4];   // bilinear weight * validity
__device__ float g_wt[3][(size_t)256 * RTOT];             // transposed weights (cls,kpt,bbox)
__device__ float g_dfm[3][(size_t)768 * HWSZ];            // relu(deform conv) per branch

// ---------------------------------------------------------------------------
// Packed f32x2 helpers (FFMA2 only reachable via PTX fma.rn.f32x2)
// ---------------------------------------------------------------------------
__device__ __forceinline__ unsigned long long pack2(float lo, float hi) {
    unsigned long long r;
    asm("mov.b64 %0, {%1, %2};" : "=l"(r) : "f"(lo), "f"(hi));
    return r;
}
__device__ __forceinline__ void unpack2(unsigned long long v, float& lo, float& hi) {
    asm("mov.b64 {%0, %1}, %2;" : "=f"(lo), "=f"(hi) : "l"(v));
}
#define FFMA2(d, a, b) \
    asm("fma.rn.f32x2 %0, %1, %2, %0;" : "+l"(d) : "l"(a), "l"(b))

// ---------------------------------------------------------------------------
// Kernel 1: fused offset 1x1 conv + bilinear corner table.
// ---------------------------------------------------------------------------
__global__ void k_corners(const float* __restrict__ kprev,
                          const float* __restrict__ w_do,
                          const float* __restrict__ b_do)
{
    int kk = blockIdx.x;                       // 0..82
    int hw = blockIdx.y * 256 + threadIdx.x;   // 0..4095
    int h = hw >> 6, w = hw & 63;

    int base, kkl;
    if (kk < 9)       { base = 0;  kkl = kk;      }
    else if (kk < 34) { base = 18; kkl = kk - 9;  }
    else              { base = 68; kkl = kk - 34; }
    int chy = base + 2 * kkl;
    int chx = chy + 1;

    float dy = b_do[chy], dx = b_do[chx];
    #pragma unroll 2
    for (int i = 0; i < 34; i++) {
        float v = kprev[i * HWSZ + hw];
        dy = fmaf(w_do[chy * 34 + i], v, dy);
        dx = fmaf(w_do[chx * 34 + i], v, dx);
    }

    float y = (float)h + dy;
    float x = (float)w + dx;
    float y0f = floorf(y), x0f = floorf(x);
    int y0 = (int)y0f, x0 = (int)x0f;
    float wy = y - y0f, wx = x - x0f;

    int   yi[4] = { y0, y0, y0 + 1, y0 + 1 };
    int   xi[4] = { x0, x0 + 1, x0, x0 + 1 };
    float wb[4] = { (1.f - wy) * (1.f - wx), (1.f - wy) * wx,
                    wy * (1.f - wx),         wy * wx };

    int o = (kk * HWSZ + hw) * 4;
    #pragma unroll
    for (int j = 0; j < 4; j++) {
        bool valid = (yi[j] >= 0) && (yi[j] < 64) && (xi[j] >= 0) && (xi[j] < 64);
        int yc = min(max(yi[j], 0), 63);
        int xc = min(max(xi[j], 0), 63);
        g_cidx[o + j] = yc * 64 + xc;
        g_cw  [o + j] = valid ? wb[j] : 0.0f;
    }
}

// ---------------------------------------------------------------------------
// Kernel 2: weight transpose into GEMM layout.
//   src w[o][c][kkl]  ->  g_wt[branch][o*RTOT + (kbase+kkl)*256 + c]
// ---------------------------------------------------------------------------
struct W9 { const float* p[9]; };

__global__ void k_wt(W9 ws)
{
    int sub = blockIdx.z;                // 0..8  (branch*3 + ks)
    int branch = sub / 3;
    int ks = sub - branch * 3;
    int Kp    = (ks == 0) ? 9 : (ks == 1) ? 25 : 49;
    int kbase = (ks == 0) ? 0 : (ks == 1) ? 9  : 34;
    int n = 256 * 256 * Kp;
    const float* src = ws.p[sub];
    float* dst = g_wt[branch];
    for (int e = blockIdx.x * blockDim.x + threadIdx.x; e < n;
         e += gridDim.x * blockDim.x) {
        int o   = e / (256 * Kp);
        int rem = e - o * (256 * Kp);
        int c   = rem / Kp;
        int kkl = rem - c * Kp;
        dst[(size_t)o * RTOT + (size_t)(kbase + kkl) * 256 + c] = src[e];
    }
}

// ---------------------------------------------------------------------------
// Kernel 3: batched SGEMM with FUSED bilinear gather (9 sub-GEMMs, blockIdx.z).
//   C[256,4096] = A[256,Ksub] * B[Ksub,4096], ReLU fused.
//   A tile stored DUPLICATED in smem so LDS.128 yields packed (a,a) pairs
//   directly -> zero per-iteration packing movs. 6x LDS.128 + 32 FFMA2 per kk.
// ---------------------------------------------------------------------------
__global__ void __launch_bounds__(256, 2) k_gemm(const float* __restrict__ f0,
                                                 const float* __restrict__ f1)
{
    // heavy-first sub order: k7 (K=12544) blocks launch before k5/k3
    const int SUBMAP[9] = {2, 5, 8, 1, 4, 7, 0, 3, 6};
    const int P0_[3] = {0, 9, 34};   // first global point per kernel size
    const int NP_[3] = {9, 25, 49};  // points per kernel size

    int sub = SUBMAP[blockIdx.z];
    int branch = sub / 3;
    int ks = sub - branch * 3;
    int p0 = P0_[ks];
    int np = NP_[ks];
    const float* __restrict__ feat = (branch == 0) ? f0 : f1;
    const float* __restrict__ A = g_wt[branch];                       // row stride RTOT
    float* __restrict__ Cp = g_dfm[branch] + (size_t)ks * 256 * HWSZ; // row stride HWSZ

    int m0 = blockIdx.y * 128;
    int n0 = blockIdx.x * 128;

    __shared__ __align__(16) float As[8][256];   // duplicated: As[k][2m]=As[k][2m+1]
    __shared__ __align__(16) float Bs[8][128];
    __shared__ __align__(16) int4   sIdx[128];
    __shared__ __align__(16) float4 sW[128];

    int tid = threadIdx.x;
    int tx = tid & 15;          // 16 cols of threads (8 n each)
    int ty = tid >> 4;          // 16 rows of threads (8 m each)

    int am = tid >> 1;              // A-load: row within tile
    int akc = (tid & 1) * 4;        // A-load: k offset (0 or 4)

    unsigned long long acc2[8][4];
    #pragma unroll
    for (int i = 0; i < 8; i++)
        #pragma unroll
        for (int j = 0; j < 4; j++) acc2[i][j] = 0ULL;

    for (int p = 0; p < np; p++) {
        int gp = p0 + p;
        __syncthreads();   // previous tiles fully consumed before corner reload
        if (tid < 128) {
            int o = (gp * HWSZ + n0 + tid) * 4;
            sIdx[tid] = *reinterpret_cast<const int4*>(&g_cidx[o]);
            sW[tid]   = *reinterpret_cast<const float4*>(&g_cw[o]);
        }
        __syncthreads();

        for (int cs = 0; cs < 32; cs++) {        // 8 channels per step
            int c0 = cs * 8;
            int gk0 = gp * 256 + c0;             // global K index of slab start

            // A tile: 128x8, one float4 per thread, written duplicated (STS.64)
            {
                const float4 av = *reinterpret_cast<const float4*>(
                    A + (size_t)(m0 + am) * RTOT + gk0 + akc);
                *reinterpret_cast<unsigned long long*>(&As[akc + 0][2 * am]) = pack2(av.x, av.x);
                *reinterpret_cast<unsigned long long*>(&As[akc + 1][2 * am]) = pack2(av.y, av.y);
                *reinterpret_cast<unsigned long long*>(&As[akc + 2][2 * am]) = pack2(av.z, av.z);
                *reinterpret_cast<unsigned long long*>(&As[akc + 3][2 * am]) = pack2(av.w, av.w);
            }
            // B tile: 8x128 built by bilinear gather from feat
            #pragma unroll
            for (int j = 0; j < 4; j++) {
                int e = tid + j * 256;
                int kk = e >> 7;
                int n = e & 127;
                const float* fc = feat + (size_t)(c0 + kk) * HWSZ;
                int4   id = sIdx[n];
                float4 wv = sW[n];
                float v = wv.x * fc[id.x];
                v = fmaf(wv.y, fc[id.y], v);
                v = fmaf(wv.z, fc[id.z], v);
                v = fmaf(wv.w, fc[id.w], v);
                Bs[kk][n] = v;
            }
            __syncthreads();

            #pragma unroll
            for (int kk = 0; kk < 8; kk++) {
                ulonglong2 aA = *reinterpret_cast<const ulonglong2*>(&As[kk][ty * 16 + 0]);
                ulonglong2 aB = *reinterpret_cast<const ulonglong2*>(&As[kk][ty * 16 + 4]);
                ulonglong2 aC = *reinterpret_cast<const ulonglong2*>(&As[kk][ty * 16 + 8]);
                ulonglong2 aD = *reinterpret_cast<const ulonglong2*>(&As[kk][ty * 16 + 12]);
                ulonglong2 bA = *reinterpret_cast<const ulonglong2*>(&Bs[kk][tx * 8 + 0]);
                ulonglong2 bB = *reinterpret_cast<const ulonglong2*>(&Bs[kk][tx * 8 + 4]);
                unsigned long long a2[8] = {aA.x, aA.y, aB.x, aB.y, aC.x, aC.y, aD.x, aD.y};
                unsigned long long b2[4] = {bA.x, bA.y, bB.x, bB.y};
                #pragma unroll
                for (int i = 0; i < 8; i++)
                    #pragma unroll
                    for (int j = 0; j < 4; j++)
                        FFMA2(acc2[i][j], a2[i], b2[j]);
            }
            __syncthreads();
        }
    }

    #pragma unroll
    for (int i = 0; i < 8; i++) {
        size_t row = (size_t)(m0 + ty * 8 + i) * HWSZ + n0 + tx * 8;
        #pragma unroll
        for (int j = 0; j < 4; j++) {
            float lo, hi;
            unpack2(acc2[i][j], lo, hi);
            Cp[row + j * 2 + 0] = fmaxf(lo, 0.f);
            Cp[row + j * 2 + 1] = fmaxf(hi, 0.f);
        }
    }
}

// ---------------------------------------------------------------------------
// Kernel 4: cls head, parallelized.
//   64 blocks x 256 threads; 4 channel-groups of 192 x 64 hw; smem reduce.
// ---------------------------------------------------------------------------
__global__ void __launch_bounds__(256) k_head_cls(const float* __restrict__ wcls,
                                                  const float* __restrict__ bcls,
                                                  float* __restrict__ out)
{
    __shared__ float red[4][13 * 64];
    int tid = threadIdx.x;
    int cg = tid >> 6;          // 0..3
    int hwl = tid & 63;
    int hw = blockIdx.x * 64 + hwl;

    float acc[13];
    #pragma unroll
    for (int o = 0; o < 13; o++) acc[o] = 0.f;
    const float* __restrict__ d = g_dfm[0];
    int c0 = cg * 192;
    #pragma unroll 2
    for (int c = c0; c < c0 + 192; c++) {
        float v = d[(size_t)c * HWSZ + hw];
        #pragma unroll
        for (int o = 0; o < 13; o++)
            acc[o] = fmaf(wcls[o * 768 + c], v, acc[o]);
    }
    #pragma unroll
    for (int o = 0; o < 13; o++) red[cg][o * 64 + hwl] = acc[o];
    __syncthreads();

    if (tid < 64) {
        #pragma unroll
        for (int o = 0; o < 13; o++) {
            float s = bcls[o] + red[0][o * 64 + tid] + red[1][o * 64 + tid]
                              + red[2][o * 64 + tid] + red[3][o * 64 + tid];
            out[(size_t)o * HWSZ + blockIdx.x * 64 + tid] = s;
        }
    }
}

// ---------------------------------------------------------------------------
// Kernel 5: kpt head + bbox head + minmax bbox decode (fused), parallelized.
// ---------------------------------------------------------------------------
__global__ void __launch_bounds__(256) k_head_pts(const float* __restrict__ wkpt,
                                                  const float* __restrict__ bkpt,
                                                  const float* __restrict__ wbb,
                                                  const float* __restrict__ bbb,
                                                  const float* __restrict__ kprev,
                                                  float* __restrict__ out)
{
    __shared__ float red[4][38 * 64];
    int tid = threadIdx.x;
    int cg = tid >> 6;
    int hwl = tid & 63;
    int hw = blockIdx.x * 64 + hwl;

    float acck[34], accb[4];
    #pragma unroll
    for (int o = 0; o < 34; o++) acck[o] = 0.f;
    #pragma unroll
    for (int o = 0; o < 4; o++)  accb[o] = 0.f;

    const float* __restrict__ dk = g_dfm[1];
    const float* __restrict__ db = g_dfm[2];
    int c0 = cg * 192;
    for (int c = c0; c < c0 + 192; c++) {
        float vk = dk[(size_t)c * HWSZ + hw];
        float vb = db[(size_t)c * HWSZ + hw];
        #pragma unroll
        for (int o = 0; o < 34; o++)
            acck[o] = fmaf(wkpt[o * 768 + c], vk, acck[o]);
        #pragma unroll
        for (int o = 0; o < 4; o++)
            accb[o] = fmaf(wbb[o * 768 + c], vb, accb[o]);
    }
    #pragma unroll
    for (int o = 0; o < 34; o++) red[cg][o * 64 + hwl] = acck[o];
    #pragma unroll
    for (int o = 0; o < 4; o++)  red[cg][(34 + o) * 64 + hwl] = accb[o];
    __syncthreads();

    if (tid < 64) {
        int hwg = blockIdx.x * 64 + tid;
        float k2[34], b2[4];
        #pragma unroll
        for (int o = 0; o < 34; o++) {
            float s = bkpt[o] + red[0][o * 64 + tid] + red[1][o * 64 + tid]
                              + red[2][o * 64 + tid] + red[3][o * 64 + tid];
            s += kprev[(size_t)o * HWSZ + hwg];
            k2[o] = s;
            out[(size_t)(17 + o) * HWSZ + hwg] = s;
        }
        #pragma unroll
        for (int o = 0; o < 4; o++)
            b2[o] = bbb[o] + red[0][(34 + o) * 64 + tid] + red[1][(34 + o) * 64 + tid]
                           + red[2][(34 + o) * 64 + tid] + red[3][(34 + o) * 64 + tid];

        float left = 1e30f, right = -1e30f, top = 1e30f, bot = -1e30f;
        #pragma unroll
        for (int i = 0; i < 17; i++) {
            float py = k2[2 * i];
            float px = k2[2 * i + 1];
            top   = fminf(top, py);   bot   = fmaxf(bot, py);
            left  = fminf(left, px);  right = fmaxf(right, px);
        }
        float cx = (left + right) * 0.5f;
        float cy = (top + bot) * 0.5f;
        float hwid = (cx - left) * expf(b2[0]);
        float hhei = (cy - top)  * expf(b2[1]);
        cx += b2[2];
        cy += b2[3];
        out[(size_t)(13 + 0) * HWSZ + hwg] = cx - hwid;
        out[(size_t)(13 + 1) * HWSZ + hwg] = cy - hhei;
        out[(size_t)(13 + 2) * HWSZ + hwg] = cx + hwid;
        out[(size_t)(13 + 3) * HWSZ + hwg] = cy + hhei;
    }
}

// ---------------------------------------------------------------------------
// Launch
// ---------------------------------------------------------------------------
extern "C" void kernel_launch(void* const* d_in, const int* in_sizes, int n_in,
                              void* d_out, int out_size)
{
    const float* cls_feat = (const float*)d_in[0];
    const float* pts_feat = (const float*)d_in[1];
    const float* kprev    = (const float*)d_in[2];
    const float* w_do     = (const float*)d_in[3];
    const float* b_do     = (const float*)d_in[4];
    // branch weights: cls 5..7, kpt 8..10, bbox 11..13
    const float* w_cls    = (const float*)d_in[14];
    const float* b_cls    = (const float*)d_in[15];
    const float* w_kpt    = (const float*)d_in[16];
    const float* b_kpt    = (const float*)d_in[17];
    const float* w_bbox   = (const float*)d_in[18];
    const float* b_bbox   = (const float*)d_in[19];
    float* out = (float*)d_out;

    // 1) offsets + bilinear corner table
    k_corners<<<dim3(NPTS, HWSZ / 256), 256>>>(kprev, w_do, b_do);

    // 2) weight transpose
    W9 ws;
    for (int i = 0; i < 9; i++) ws.p[i] = (const float*)d_in[5 + i];
    k_wt<<<dim3(64, 1, 9), 256>>>(ws);

    // 3) 9 sub-GEMMs (3 branches x 3 kernel sizes), gather fused, ReLU fused
    k_gemm<<<dim3(HWSZ / 128, 2, 9), 256>>>(cls_feat, pts_feat);

    // 4) heads
    k_head_cls<<<HWSZ / 64, 256>>>(w_cls, b_cls, out);
    k_head_pts<<<HWSZ / 64, 256>>>(w_kpt, b_kpt, w_bbox, b_bbox, kprev, out);
}

// round 6
// speedup vs baseline: 2.5003x; 1.8565x over previous
#include <cuda_runtime.h>
#include <cuda_bf16.h>
#include <math.h>
#include <stdint.h>

// ---------------------------------------------------------------------------
// Problem constants (B=1, C=256, H=W=64, FC=256, kernels 3/5/7 -> 83 points)
// ---------------------------------------------------------------------------
#define HWSZ 4096
#define NPTS 83
#define KTOT 21248         // 83*256 packed weight K layout

// ---------------------------------------------------------------------------
// Device scratch
// ---------------------------------------------------------------------------
__device__ __align__(16) int   g_cidx[NPTS * HWSZ * 4];
__device__ __align__(16) float g_cw  [NPTS * HWSZ * 4];
__device__ __nv_bfloat16 g_wa_hi[3][(size_t)256 * KTOT];  // weights hi, [m][k]
__device__ __nv_bfloat16 g_wa_lo[3][(size_t)256 * KTOT];  // weights lo
__device__ float g_ft[2][(size_t)HWSZ * 256];             // feat transposed [hw][c]
__device__ float g_dfm[3][(size_t)768 * HWSZ];            // relu(deform conv)

// ---------------------------------------------------------------------------
// helpers
// ---------------------------------------------------------------------------
__device__ __forceinline__ uint32_t smem_to_u32(const void* p) {
    uint32_t a;
    asm("{ .reg .u64 t; cvta.to.shared.u64 t, %1; cvt.u32.u64 %0, t; }"
        : "=r"(a) : "l"(p));
    return a;
}
#define SWZ(o) ((o) ^ (((o) >> 3) & 0x70))

__device__ __forceinline__ void ldsm4(uint32_t addr, uint32_t* r) {
    asm volatile("ldmatrix.sync.aligned.m8n8.x4.shared.b16 {%0,%1,%2,%3}, [%4];"
        : "=r"(r[0]), "=r"(r[1]), "=r"(r[2]), "=r"(r[3]) : "r"(addr));
}
__device__ __forceinline__ void mma16816(float* c, const uint32_t* a,
                                         uint32_t b0, uint32_t b1) {
    asm volatile(
        "mma.sync.aligned.m16n8k16.row.col.f32.bf16.bf16.f32 "
        "{%0,%1,%2,%3}, {%4,%5,%6,%7}, {%8,%9}, {%0,%1,%2,%3};"
        : "+f"(c[0]), "+f"(c[1]), "+f"(c[2]), "+f"(c[3])
        : "r"(a[0]), "r"(a[1]), "r"(a[2]), "r"(a[3]), "r"(b0), "r"(b1));
}

// smem offsets (static 48KB exactly)
#define S_AHI 0
#define S_ALO 16384
#define S_BHI 32768
#define S_BLO 40960

// ---------------------------------------------------------------------------
// Kernel 1: fused offset 1x1 conv + bilinear corner table.
// ---------------------------------------------------------------------------
__global__ void k_corners(const float* __restrict__ kprev,
                          const float* __restrict__ w_do,
                          const float* __restrict__ b_do)
{
    int kk = blockIdx.x;
    int hw = blockIdx.y * 256 + threadIdx.x;
    int h = hw >> 6, w = hw & 63;

    int base, kkl;
    if (kk < 9)       { base = 0;  kkl = kk;      }
    else if (kk < 34) { base = 18; kkl = kk - 9;  }
    else              { base = 68; kkl = kk - 34; }
    int chy = base + 2 * kkl;
    int chx = chy + 1;

    float dy = b_do[chy], dx = b_do[chx];
    #pragma unroll 2
    for (int i = 0; i < 34; i++) {
        float v = kprev[i * HWSZ + hw];
        dy = fmaf(w_do[chy * 34 + i], v, dy);
        dx = fmaf(w_do[chx * 34 + i], v, dx);
    }

    float y = (float)h + dy;
    float x = (float)w + dx;
    float y0f = floorf(y), x0f = floorf(x);
    int y0 = (int)y0f, x0 = (int)x0f;
    float wy = y - y0f, wx = x - x0f;

    int   yi[4] = { y0, y0, y0 + 1, y0 + 1 };
    int   xi[4] = { x0, x0 + 1, x0, x0 + 1 };
    float wb[4] = { (1.f - wy) * (1.f - wx), (1.f - wy) * wx,
                    wy * (1.f - wx),         wy * wx };

    int o = (kk * HWSZ + hw) * 4;
    #pragma unroll
    for (int j = 0; j < 4; j++) {
        bool valid = (yi[j] >= 0) && (yi[j] < 64) && (xi[j] >= 0) && (xi[j] < 64);
        int yc = min(max(yi[j], 0), 63);
        int xc = min(max(xi[j], 0), 63);
        g_cidx[o + j] = yc * 64 + xc;
        g_cw  [o + j] = valid ? wb[j] : 0.0f;
    }
}

// ---------------------------------------------------------------------------
// Kernel 2: weight transpose + bf16 hi/lo split.
//   src w[o][c][kkl] -> g_wa_{hi,lo}[branch][o*KTOT + (kbase+kkl)*256 + c]
//   (k3 occupies k [0,2304), k5 [2304,8704), k7 [8704,21248); each sub-GEMM
//    reads only its own range -> concatenation semantics preserved)
// ---------------------------------------------------------------------------
struct W9 { const float* p[9]; };

__global__ void k_wt(W9 ws)
{
    int sub = blockIdx.z;
    int branch = sub / 3;
    int ks = sub - branch * 3;
    int Kp    = (ks == 0) ? 9 : (ks == 1) ? 25 : 49;
    int kbase = (ks == 0) ? 0 : (ks == 1) ? 9  : 34;
    int n = 256 * 256 * Kp;
    const float* src = ws.p[sub];
    __nv_bfloat16* dh = g_wa_hi[branch];
    __nv_bfloat16* dl = g_wa_lo[branch];
    for (int e = blockIdx.x * blockDim.x + threadIdx.x; e < n;
         e += gridDim.x * blockDim.x) {
        int o   = e / (256 * Kp);
        int rem = e - o * (256 * Kp);
        int c   = rem / Kp;
        int kkl = rem - c * Kp;
        float v = src[e];
        __nv_bfloat16 h = __float2bfloat16(v);
        size_t idx = (size_t)o * KTOT + (size_t)(kbase + kkl) * 256 + c;
        dh[idx] = h;
        dl[idx] = __float2bfloat16(v - __bfloat162float(h));
    }
}

// ---------------------------------------------------------------------------
// Kernel 3: feature transpose [c][hw] -> [hw][c]
// ---------------------------------------------------------------------------
__global__ void k_ft(const float* __restrict__ f0, const float* __restrict__ f1)
{
    __shared__ float t[32][33];
    int f = blockIdx.z;
    const float* __restrict__ src = f ? f1 : f0;
    int hw0 = blockIdx.x * 32, c0 = blockIdx.y * 32;
    #pragma unroll
    for (int i = 0; i < 4; i++) {
        int c = c0 + threadIdx.y + i * 8;
        t[threadIdx.y + i * 8][threadIdx.x] = src[(size_t)c * HWSZ + hw0 + threadIdx.x];
    }
    __syncthreads();
    #pragma unroll
    for (int i = 0; i < 4; i++) {
        int hw = hw0 + threadIdx.y + i * 8;
        g_ft[f][(size_t)hw * 256 + c0 + threadIdx.x] = t[threadIdx.x][threadIdx.y + i * 8];
    }
}

// ---------------------------------------------------------------------------
// Kernel 4: HMMA (mma.sync bf16x3) GEMM with fused bilinear gather.
//   9 sub-GEMMs via blockIdx.z (branch x kernel-size, BLOCK-DIAGONAL).
//   Each sub: C[256,4096] = A[256,Ksub] * B[Ksub,4096] -> its own 256-row
//   slab of g_dfm[branch] (concatenated [k3;k5;k7] = 768 channels).
//   Block tile M128 x N64, 8 warps (2M x 4N), warp tile 64x16.
//   Per chunk (K=64): gather B hi/lo + copy A hi/lo into SW128 smem,
//   then 4 ksteps x 24 mma.sync per warp (3-product bf16 split, fp32 acc).
// ---------------------------------------------------------------------------
__global__ void __launch_bounds__(256, 2) k_mma()
{
    // heavy-first: k7 subs (ks=2) first, then k5, then k3
    const int SUBMAP[9] = {2, 5, 8, 1, 4, 7, 0, 3, 6};
    const int P0_[3] = {0, 9, 34};
    const int NP_[3] = {9, 25, 49};

    __shared__ __align__(128) char smem[49152];
    uint32_t sb = smem_to_u32(smem);

    int tid = threadIdx.x;
    int wid = tid >> 5;
    int lid = tid & 31;

    int sub = SUBMAP[blockIdx.z];
    int branch = sub / 3;
    int ks = sub - branch * 3;
    int p0 = P0_[ks];
    int np = NP_[ks];

    int m0 = blockIdx.y * 128;
    int n0 = blockIdx.x * 64;
    const float* __restrict__ ft = g_ft[branch == 0 ? 0 : 1];
    const __nv_bfloat16* __restrict__ Ah = g_wa_hi[branch];
    const __nv_bfloat16* __restrict__ Al = g_wa_lo[branch];
    float* __restrict__ Cp = g_dfm[branch] + (size_t)ks * 256 * HWSZ;

    // warp tiling: 2 (M) x 4 (N)
    int wm = wid >> 2;
    int wn = wid & 3;
    int mbase = wm * 64;
    int nbase = wn * 16;

    // gather mapping: 4 threads per B row
    int n_l = tid >> 2;           // 0..63 local n
    int qg  = tid & 3;            // channel group (16 ch each)
    int n_g = n0 + n_l;

    // ldmatrix lane address components
    uint32_t a_row = mbase + ((lid >> 3) & 1) * 8 + (lid & 7);
    uint32_t a_byt = (lid >> 4) * 16;
    uint32_t b_row = nbase + (lid & 7) + ((lid >> 4) & 1) * 8;
    uint32_t b_byt = ((lid >> 3) & 1) * 16;

    float acc[4][2][4];
    #pragma unroll
    for (int i = 0; i < 4; i++)
        #pragma unroll
        for (int j = 0; j < 2; j++)
            #pragma unroll
            for (int r = 0; r < 4; r++) acc[i][j][r] = 0.f;

    int4   id4;
    float4 wv4;

    int nchunk = np * 4;                  // 4 x K64 chunks per point
    for (int ch = 0; ch < nchunk; ch++) {
        int gp = p0 + (ch >> 2);          // global point
        int c0v = (ch & 3) * 64;          // channel offset within point
        int k0 = gp * 256 + c0v;          // global k in packed weight layout

        if ((ch & 3) == 0) {              // new point: reload corners
            int o = (gp * HWSZ + n_g) * 4;
            id4 = *reinterpret_cast<const int4*>(&g_cidx[o]);
            wv4 = *reinterpret_cast<const float4*>(&g_cw[o]);
        }

        __syncthreads();                  // prev math done, smem reusable

        // ---- A tile copy: 128 rows x 64 bf16, hi+lo ----
        #pragma unroll
        for (int i = 0; i < 4; i++) {
            int e = tid + i * 256;
            int m = e >> 3;
            int seg = e & 7;
            size_t src = (size_t)(m0 + m) * KTOT + k0 + seg * 8;
            uint32_t dof = SWZ((uint32_t)(m * 128 + seg * 16));
            *reinterpret_cast<int4*>(smem + S_AHI + dof) =
                *reinterpret_cast<const int4*>(Ah + src);
            *reinterpret_cast<int4*>(smem + S_ALO + dof) =
                *reinterpret_cast<const int4*>(Al + src);
        }

        // ---- B gather: row n_l, channels [c0v+qg*16, +16) ----
        {
            int cb = c0v + qg * 16;
            const float* t0 = ft + (size_t)id4.x * 256 + cb;
            const float* t1 = ft + (size_t)id4.y * 256 + cb;
            const float* t2 = ft + (size_t)id4.z * 256 + cb;
            const float* t3 = ft + (size_t)id4.w * 256 + cb;
            #pragma unroll
            for (int qq = 0; qq < 4; qq++) {
                float4 a = *reinterpret_cast<const float4*>(t0 + qq * 4);
                float4 b = *reinterpret_cast<const float4*>(t1 + qq * 4);
                float4 c = *reinterpret_cast<const float4*>(t2 + qq * 4);
                float4 d = *reinterpret_cast<const float4*>(t3 + qq * 4);
                float v0 = wv4.x*a.x + wv4.y*b.x + wv4.z*c.x + wv4.w*d.x;
                float v1 = wv4.x*a.y + wv4.y*b.y + wv4.z*c.y + wv4.w*d.y;
                float v2 = wv4.x*a.z + wv4.y*b.z + wv4.z*c.z + wv4.w*d.z;
                float v3 = wv4.x*a.w + wv4.y*b.w + wv4.z*c.w + wv4.w*d.w;
                __nv_bfloat162 h01 = __floats2bfloat162_rn(v0, v1);
                __nv_bfloat162 h23 = __floats2bfloat162_rn(v2, v3);
                __nv_bfloat162 l01 = __floats2bfloat162_rn(
                    v0 - __bfloat162float(h01.x), v1 - __bfloat162float(h01.y));
                __nv_bfloat162 l23 = __floats2bfloat162_rn(
                    v2 - __bfloat162float(h23.x), v3 - __bfloat162float(h23.y));
                uint32_t bof = SWZ((uint32_t)(n_l * 128 + (qg * 16 + qq * 4) * 2));
                uint2 hv, lv;
                hv.x = *reinterpret_cast<uint32_t*>(&h01);
                hv.y = *reinterpret_cast<uint32_t*>(&h23);
                lv.x = *reinterpret_cast<uint32_t*>(&l01);
                lv.y = *reinterpret_cast<uint32_t*>(&l23);
                *reinterpret_cast<uint2*>(smem + S_BHI + bof) = hv;
                *reinterpret_cast<uint2*>(smem + S_BLO + bof) = lv;
            }
        }

        __syncthreads();                  // tiles ready

        // ---- math: 4 ksteps x (4 mi x 2 nj x 3 products) ----
        #pragma unroll
        for (int kss = 0; kss < 4; kss++) {
            uint32_t kb = kss * 32;
            uint32_t ah[4][4], al[4][4], bh[4], bl[4];
            #pragma unroll
            for (int mi = 0; mi < 4; mi++) {
                uint32_t off = SWZ((a_row + mi * 16) * 128 + kb + a_byt);
                ldsm4(sb + S_AHI + off, ah[mi]);
                ldsm4(sb + S_ALO + off, al[mi]);
            }
            {
                uint32_t off = SWZ(b_row * 128 + kb + b_byt);
                ldsm4(sb + S_BHI + off, bh);
                ldsm4(sb + S_BLO + off, bl);
            }
            #pragma unroll
            for (int mi = 0; mi < 4; mi++) {
                #pragma unroll
                for (int nj = 0; nj < 2; nj++) {
                    mma16816(acc[mi][nj], ah[mi], bh[nj*2], bh[nj*2+1]);
                    mma16816(acc[mi][nj], ah[mi], bl[nj*2], bl[nj*2+1]);
                    mma16816(acc[mi][nj], al[mi], bh[nj*2], bh[nj*2+1]);
                }
            }
        }
    }

    // ---- epilogue: relu + store ----
    int l4 = lid >> 2;
    int l2 = (lid & 3) * 2;
    #pragma unroll
    for (int mi = 0; mi < 4; mi++) {
        #pragma unroll
        for (int nj = 0; nj < 2; nj++) {
            int m = m0 + mbase + mi * 16 + l4;
            int n = n0 + nbase + nj * 8 + l2;
            float2 v0, v1;
            v0.x = fmaxf(acc[mi][nj][0], 0.f);
            v0.y = fmaxf(acc[mi][nj][1], 0.f);
            v1.x = fmaxf(acc[mi][nj][2], 0.f);
            v1.y = fmaxf(acc[mi][nj][3], 0.f);
            *reinterpret_cast<float2*>(Cp + (size_t)m * HWSZ + n) = v0;
            *reinterpret_cast<float2*>(Cp + (size_t)(m + 8) * HWSZ + n) = v1;
        }
    }
}

// ---------------------------------------------------------------------------
// Kernel 5: cls head.
// ---------------------------------------------------------------------------
__global__ void __launch_bounds__(256) k_head_cls(const float* __restrict__ wcls,
                                                  const float* __restrict__ bcls,
                                                  float* __restrict__ out)
{
    __shared__ float red[8][13 * 32];
    int tid = threadIdx.x;
    int cg = tid >> 5;
    int hwl = tid & 31;
    int hw = blockIdx.x * 32 + hwl;

    float acc[13];
    #pragma unroll
    for (int o = 0; o < 13; o++) acc[o] = 0.f;
    const float* __restrict__ d = g_dfm[0];
    int c0 = cg * 96;
    for (int c = c0; c < c0 + 96; c++) {
        float v = d[(size_t)c * HWSZ + hw];
        #pragma unroll
        for (int o = 0; o < 13; o++)
            acc[o] = fmaf(wcls[o * 768 + c], v, acc[o]);
    }
    #pragma unroll
    for (int o = 0; o < 13; o++) red[cg][o * 32 + hwl] = acc[o];
    __syncthreads();

    if (tid < 32) {
        #pragma unroll
        for (int o = 0; o < 13; o++) {
            float s = bcls[o];
            #pragma unroll
            for (int g = 0; g < 8; g++) s += red[g][o * 32 + tid];
            out[(size_t)o * HWSZ + blockIdx.x * 32 + tid] = s;
        }
    }
}

// ---------------------------------------------------------------------------
// Kernel 6: kpt + bbox heads + minmax bbox decode (fused).
// ---------------------------------------------------------------------------
__global__ void __launch_bounds__(256) k_head_pts(const float* __restrict__ wkpt,
                                                  const float* __restrict__ bkpt,
                                                  const float* __restrict__ wbb,
                                                  const float* __restrict__ bbb,
                                                  const float* __restrict__ kprev,
                                                  float* __restrict__ out)
{
    __shared__ float red[8][38 * 32];
    int tid = threadIdx.x;
    int cg = tid >> 5;
    int hwl = tid & 31;
    int hw = blockIdx.x * 32 + hwl;

    float acck[34], accb[4];
    #pragma unroll
    for (int o = 0; o < 34; o++) acck[o] = 0.f;
    #pragma unroll
    for (int o = 0; o < 4; o++)  accb[o] = 0.f;

    const float* __restrict__ dk = g_dfm[1];
    const float* __restrict__ db = g_dfm[2];
    int c0 = cg * 96;
    for (int c = c0; c < c0 + 96; c++) {
        float vk = dk[(size_t)c * HWSZ + hw];
        float vb = db[(size_t)c * HWSZ + hw];
        #pragma unroll
        for (int o = 0; o < 34; o++)
            acck[o] = fmaf(wkpt[o * 768 + c], vk, acck[o]);
        #pragma unroll
        for (int o = 0; o < 4; o++)
            accb[o] = fmaf(wbb[o * 768 + c], vb, accb[o]);
    }
    #pragma unroll
    for (int o = 0; o < 34; o++) red[cg][o * 32 + hwl] = acck[o];
    #pragma unroll
    for (int o = 0; o < 4; o++)  red[cg][(34 + o) * 32 + hwl] = accb[o];
    __syncthreads();

    if (tid < 32) {
        int hwg = blockIdx.x * 32 + tid;
        float k2[34], b2[4];
        #pragma unroll
        for (int o = 0; o < 34; o++) {
            float s = bkpt[o];
            #pragma unroll
            for (int g = 0; g < 8; g++) s += red[g][o * 32 + tid];
            s += kprev[(size_t)o * HWSZ + hwg];
            k2[o] = s;
            out[(size_t)(17 + o) * HWSZ + hwg] = s;
        }
        #pragma unroll
        for (int o = 0; o < 4; o++) {
            float s = bbb[o];
            #pragma unroll
            for (int g = 0; g < 8; g++) s += red[g][(34 + o) * 32 + tid];
            b2[o] = s;
        }

        float left = 1e30f, right = -1e30f, top = 1e30f, bot = -1e30f;
        #pragma unroll
        for (int i = 0; i < 17; i++) {
            float py = k2[2 * i];
            float px = k2[2 * i + 1];
            top   = fminf(top, py);   bot   = fmaxf(bot, py);
            left  = fminf(left, px);  right = fmaxf(right, px);
        }
        float cx = (left + right) * 0.5f;
        float cy = (top + bot) * 0.5f;
        float hwid = (cx - left) * expf(b2[0]);
        float hhei = (cy - top)  * expf(b2[1]);
        cx += b2[2];
        cy += b2[3];
        out[(size_t)(13 + 0) * HWSZ + hwg] = cx - hwid;
        out[(size_t)(13 + 1) * HWSZ + hwg] = cy - hhei;
        out[(size_t)(13 + 2) * HWSZ + hwg] = cx + hwid;
        out[(size_t)(13 + 3) * HWSZ + hwg] = cy + hhei;
    }
}

// ---------------------------------------------------------------------------
// Launch
// ---------------------------------------------------------------------------
extern "C" void kernel_launch(void* const* d_in, const int* in_sizes, int n_in,
                              void* d_out, int out_size)
{
    const float* cls_feat = (const float*)d_in[0];
    const float* pts_feat = (const float*)d_in[1];
    const float* kprev    = (const float*)d_in[2];
    const float* w_do     = (const float*)d_in[3];
    const float* b_do     = (const float*)d_in[4];
    const float* w_cls    = (const float*)d_in[14];
    const float* b_cls    = (const float*)d_in[15];
    const float* w_kpt    = (const float*)d_in[16];
    const float* b_kpt    = (const float*)d_in[17];
    const float* w_bbox   = (const float*)d_in[18];
    const float* b_bbox   = (const float*)d_in[19];
    float* out = (float*)d_out;

    k_corners<<<dim3(NPTS, HWSZ / 256), 256>>>(kprev, w_do, b_do);

    W9 ws;
    for (int i = 0; i < 9; i++) ws.p[i] = (const float*)d_in[5 + i];
    k_wt<<<dim3(64, 1, 9), 256>>>(ws);

    k_ft<<<dim3(HWSZ / 32, 256 / 32, 2), dim3(32, 8)>>>(cls_feat, pts_feat);

    // 9 block-diagonal sub-GEMMs (branch x kernel size), HMMA bf16x3
    k_mma<<<dim3(64, 2, 9), 256>>>();

    k_head_cls<<<HWSZ / 32, 256>>>(w_cls, b_cls, out);
    k_head_pts<<<HWSZ / 32, 256>>>(w_kpt, b_kpt, w_bbox, b_bbox, kprev, out);
}

// round 7
// speedup vs baseline: 2.6937x; 1.0774x over previous
#include <cuda_runtime.h>
#include <cuda_bf16.h>
#include <math.h>
#include <stdint.h>

// ---------------------------------------------------------------------------
// Problem constants (B=1, C=256, H=W=64, FC=256, kernels 3/5/7 -> 83 points)
// ---------------------------------------------------------------------------
#define HWSZ 4096
#define NPTS 83
#define KTOT 21248         // 83*256 packed weight K layout

// ---------------------------------------------------------------------------
// Device scratch
// ---------------------------------------------------------------------------
__device__ __align__(16) int   g_cidx[NPTS * HWSZ * 4];
__device__ __align__(16) float g_cw  [NPTS * HWSZ * 4];
__device__ __nv_bfloat16 g_wa_hi[3][(size_t)256 * KTOT];  // weights hi, [m][k]
__device__ __nv_bfloat16 g_wa_lo[3][(size_t)256 * KTOT];  // weights lo
__device__ float g_ft[2][(size_t)HWSZ * 256];             // feat transposed [hw][c]
__device__ float g_dfm[3][(size_t)768 * HWSZ];            // relu(deform conv)

// ---------------------------------------------------------------------------
// helpers
// ---------------------------------------------------------------------------
__device__ __forceinline__ uint32_t smem_to_u32(const void* p) {
    uint32_t a;
    asm("{ .reg .u64 t; cvta.to.shared.u64 t, %1; cvt.u32.u64 %0, t; }"
        : "=r"(a) : "l"(p));
    return a;
}
// SW64 swizzle for 64-byte rows (atom = 8 rows x 64B)
#define SWZ64(o) ((o) ^ (((o) >> 3) & 0x30))

__device__ __forceinline__ void ldsm4(uint32_t addr, uint32_t* r) {
    asm volatile("ldmatrix.sync.aligned.m8n8.x4.shared.b16 {%0,%1,%2,%3}, [%4];"
        : "=r"(r[0]), "=r"(r[1]), "=r"(r[2]), "=r"(r[3]) : "r"(addr));
}
__device__ __forceinline__ void mma16816(float* c, const uint32_t* a,
                                         uint32_t b0, uint32_t b1) {
    asm volatile(
        "mma.sync.aligned.m16n8k16.row.col.f32.bf16.bf16.f32 "
        "{%0,%1,%2,%3}, {%4,%5,%6,%7}, {%8,%9}, {%0,%1,%2,%3};"
        : "+f"(c[0]), "+f"(c[1]), "+f"(c[2]), "+f"(c[3])
        : "r"(a[0]), "r"(a[1]), "r"(a[2]), "r"(a[3]), "r"(b0), "r"(b1));
}

// smem layout: A hi 16KB | A lo 16KB | B hi 8KB | B lo 8KB = 48KB static
#define S_AHI 0
#define S_ALO 16384
#define S_BHI 32768
#define S_BLO 40960

// ---------------------------------------------------------------------------
// Kernel 1: fused offset 1x1 conv + bilinear corner table.
// ---------------------------------------------------------------------------
__global__ void k_corners(const float* __restrict__ kprev,
                          const float* __restrict__ w_do,
                          const float* __restrict__ b_do)
{
    int kk = blockIdx.x;
    int hw = blockIdx.y * 256 + threadIdx.x;
    int h = hw >> 6, w = hw & 63;

    int base, kkl;
    if (kk < 9)       { base = 0;  kkl = kk;      }
    else if (kk < 34) { base = 18; kkl = kk - 9;  }
    else              { base = 68; kkl = kk - 34; }
    int chy = base + 2 * kkl;
    int chx = chy + 1;

    float dy = b_do[chy], dx = b_do[chx];
    #pragma unroll 2
    for (int i = 0; i < 34; i++) {
        float v = kprev[i * HWSZ + hw];
        dy = fmaf(w_do[chy * 34 + i], v, dy);
        dx = fmaf(w_do[chx * 34 + i], v, dx);
    }

    float y = (float)h + dy;
    float x = (float)w + dx;
    float y0f = floorf(y), x0f = floorf(x);
    int y0 = (int)y0f, x0 = (int)x0f;
    float wy = y - y0f, wx = x - x0f;

    int   yi[4] = { y0, y0, y0 + 1, y0 + 1 };
    int   xi[4] = { x0, x0 + 1, x0, x0 + 1 };
    float wb[4] = { (1.f - wy) * (1.f - wx), (1.f - wy) * wx,
                    wy * (1.f - wx),         wy * wx };

    int o = (kk * HWSZ + hw) * 4;
    #pragma unroll
    for (int j = 0; j < 4; j++) {
        bool valid = (yi[j] >= 0) && (yi[j] < 64) && (xi[j] >= 0) && (xi[j] < 64);
        int yc = min(max(yi[j], 0), 63);
        int xc = min(max(xi[j], 0), 63);
        g_cidx[o + j] = yc * 64 + xc;
        g_cw  [o + j] = valid ? wb[j] : 0.0f;
    }
}

// ---------------------------------------------------------------------------
// Kernel 2: weight transpose + bf16 hi/lo split.
// ---------------------------------------------------------------------------
struct W9 { const float* p[9]; };

__global__ void k_wt(W9 ws)
{
    int sub = blockIdx.z;
    int branch = sub / 3;
    int ks = sub - branch * 3;
    int Kp    = (ks == 0) ? 9 : (ks == 1) ? 25 : 49;
    int kbase = (ks == 0) ? 0 : (ks == 1) ? 9  : 34;
    int n = 256 * 256 * Kp;
    const float* src = ws.p[sub];
    __nv_bfloat16* dh = g_wa_hi[branch];
    __nv_bfloat16* dl = g_wa_lo[branch];
    for (int e = blockIdx.x * blockDim.x + threadIdx.x; e < n;
         e += gridDim.x * blockDim.x) {
        int o   = e / (256 * Kp);
        int rem = e - o * (256 * Kp);
        int c   = rem / Kp;
        int kkl = rem - c * Kp;
        float v = src[e];
        __nv_bfloat16 h = __float2bfloat16(v);
        size_t idx = (size_t)o * KTOT + (size_t)(kbase + kkl) * 256 + c;
        dh[idx] = h;
        dl[idx] = __float2bfloat16(v - __bfloat162float(h));
    }
}

// ---------------------------------------------------------------------------
// Kernel 3: feature transpose [c][hw] -> [hw][c]
// ---------------------------------------------------------------------------
__global__ void k_ft(const float* __restrict__ f0, const float* __restrict__ f1)
{
    __shared__ float t[32][33];
    int f = blockIdx.z;
    const float* __restrict__ src = f ? f1 : f0;
    int hw0 = blockIdx.x * 32, c0 = blockIdx.y * 32;
    #pragma unroll
    for (int i = 0; i < 4; i++) {
        int c = c0 + threadIdx.y + i * 8;
        t[threadIdx.y + i * 8][threadIdx.x] = src[(size_t)c * HWSZ + hw0 + threadIdx.x];
    }
    __syncthreads();
    #pragma unroll
    for (int i = 0; i < 4; i++) {
        int hw = hw0 + threadIdx.y + i * 8;
        g_ft[f][(size_t)hw * 256 + c0 + threadIdx.x] = t[threadIdx.x][threadIdx.y + i * 8];
    }
}

// ---------------------------------------------------------------------------
// Kernel 4: HMMA (mma.sync bf16x3) GEMM with fused bilinear gather.
//   9 block-diagonal sub-GEMMs via blockIdx.y (branch x kernel-size).
//   Block tile M256 x N128 x K32, 512 threads = 16 warps (4M x 4N),
//   warp tile 64x32.  A hi/lo 32KB + B hi/lo 16KB = 48KB static smem, SW64.
// ---------------------------------------------------------------------------
__global__ void __launch_bounds__(512, 1) k_mma()
{
    const int SUBMAP[9] = {2, 5, 8, 1, 4, 7, 0, 3, 6};  // heavy (k7) first
    const int P0_[3] = {0, 9, 34};
    const int NP_[3] = {9, 25, 49};

    __shared__ __align__(128) char smem[49152];
    uint32_t sb = smem_to_u32(smem);

    int tid = threadIdx.x;
    int wid = tid >> 5;
    int lid = tid & 31;

    int sub = SUBMAP[blockIdx.y];
    int branch = sub / 3;
    int ks = sub - branch * 3;
    int p0 = P0_[ks];
    int np = NP_[ks];

    int n0 = blockIdx.x * 128;
    const float* __restrict__ ft = g_ft[branch == 0 ? 0 : 1];
    const __nv_bfloat16* __restrict__ Ah = g_wa_hi[branch];
    const __nv_bfloat16* __restrict__ Al = g_wa_lo[branch];
    float* __restrict__ Cp = g_dfm[branch] + (size_t)ks * 256 * HWSZ;

    // warp tiling: 4 (M) x 4 (N); warp tile 64x32
    int wm = wid >> 2;
    int wn = wid & 3;

    // gather mapping: 4 threads per B row (8 channels each)
    int n_l = tid >> 2;           // 0..127
    int qg  = tid & 3;            // channel subgroup
    int n_g = n0 + n_l;

    // A copy mapping: tid<256 -> hi rows, tid>=256 -> lo rows (64B per row)
    int arow = tid & 255;
    int asel = tid >> 8;

    // ldmatrix lane address components
    uint32_t a_row = wm * 64 + ((lid >> 3) & 1) * 8 + (lid & 7);
    uint32_t a_byt = (lid >> 4) * 16;
    uint32_t b_row = wn * 32 + (lid & 7) + ((lid >> 4) & 1) * 8;
    uint32_t b_byt = ((lid >> 3) & 1) * 16;

    float acc[4][4][4];
    #pragma unroll
    for (int i = 0; i < 4; i++)
        #pragma unroll
        for (int j = 0; j < 4; j++)
            #pragma unroll
            for (int r = 0; r < 4; r++) acc[i][j][r] = 0.f;

    int4   id4;
    float4 wv4;

    const __nv_bfloat16* Asrc_base = asel ? Al : Ah;
    char* Adst_base = smem + (asel ? S_ALO : S_AHI);

    int nchunk = np * 8;                  // 8 x K32 chunks per point
    for (int ch = 0; ch < nchunk; ch++) {
        int gp = p0 + (ch >> 3);
        int c0v = (ch & 7) * 32;
        int k0 = gp * 256 + c0v;

        if ((ch & 7) == 0) {              // new point: reload corners
            int o = (gp * HWSZ + n_g) * 4;
            id4 = *reinterpret_cast<const int4*>(&g_cidx[o]);
            wv4 = *reinterpret_cast<const float4*>(&g_cw[o]);
        }

        __syncthreads();                  // prev math done, smem reusable

        // ---- A tile copy: 256 rows x 32ch bf16 (64B/row), hi or lo ----
        {
            const __nv_bfloat16* Asrc = Asrc_base + (size_t)arow * KTOT + k0;
            #pragma unroll
            for (int j = 0; j < 4; j++) {
                uint32_t dof = SWZ64((uint32_t)(arow * 64 + j * 16));
                *reinterpret_cast<int4*>(Adst_base + dof) =
                    *reinterpret_cast<const int4*>(Asrc + j * 8);
            }
        }

        // ---- B gather: row n_l, 8 channels [c0v+qg*8, +8) ----
        {
            int cb = c0v + qg * 8;
            const float* t0 = ft + (size_t)id4.x * 256 + cb;
            const float* t1 = ft + (size_t)id4.y * 256 + cb;
            const float* t2 = ft + (size_t)id4.z * 256 + cb;
            const float* t3 = ft + (size_t)id4.w * 256 + cb;
            #pragma unroll
            for (int qq = 0; qq < 2; qq++) {
                float4 a = *reinterpret_cast<const float4*>(t0 + qq * 4);
                float4 b = *reinterpret_cast<const float4*>(t1 + qq * 4);
                float4 c = *reinterpret_cast<const float4*>(t2 + qq * 4);
                float4 d = *reinterpret_cast<const float4*>(t3 + qq * 4);
                float v0 = wv4.x*a.x + wv4.y*b.x + wv4.z*c.x + wv4.w*d.x;
                float v1 = wv4.x*a.y + wv4.y*b.y + wv4.z*c.y + wv4.w*d.y;
                float v2 = wv4.x*a.z + wv4.y*b.z + wv4.z*c.z + wv4.w*d.z;
                float v3 = wv4.x*a.w + wv4.y*b.w + wv4.z*c.w + wv4.w*d.w;
                __nv_bfloat162 h01 = __floats2bfloat162_rn(v0, v1);
                __nv_bfloat162 h23 = __floats2bfloat162_rn(v2, v3);
                __nv_bfloat162 l01 = __floats2bfloat162_rn(
                    v0 - __bfloat162float(h01.x), v1 - __bfloat162float(h01.y));
                __nv_bfloat162 l23 = __floats2bfloat162_rn(
                    v2 - __bfloat162float(h23.x), v3 - __bfloat162float(h23.y));
                uint32_t bof = SWZ64((uint32_t)(n_l * 64 + qg * 16 + qq * 8));
                uint2 hv, lv;
                hv.x = *reinterpret_cast<uint32_t*>(&h01);
                hv.y = *reinterpret_cast<uint32_t*>(&h23);
                lv.x = *reinterpret_cast<uint32_t*>(&l01);
                lv.y = *reinterpret_cast<uint32_t*>(&l23);
                *reinterpret_cast<uint2*>(smem + S_BHI + bof) = hv;
                *reinterpret_cast<uint2*>(smem + S_BLO + bof) = lv;
            }
        }

        __syncthreads();                  // tiles ready

        // ---- math: 2 ksteps, 3 staged products (reg-pressure ordered) ----
        #pragma unroll
        for (int ks2 = 0; ks2 < 2; ks2++) {
            uint32_t kb = ks2 * 32;
            uint32_t ah[4][4], bh[2][4];
            #pragma unroll
            for (int mi = 0; mi < 4; mi++)
                ldsm4(sb + S_AHI + SWZ64((a_row + mi * 16) * 64 + kb + a_byt), ah[mi]);
            #pragma unroll
            for (int bj = 0; bj < 2; bj++)
                ldsm4(sb + S_BHI + SWZ64((b_row + bj * 16) * 64 + kb + b_byt), bh[bj]);
            #pragma unroll
            for (int mi = 0; mi < 4; mi++)
                #pragma unroll
                for (int nj = 0; nj < 4; nj++)
                    mma16816(acc[mi][nj], ah[mi], bh[nj >> 1][(nj & 1) * 2],
                             bh[nj >> 1][(nj & 1) * 2 + 1]);
            {
                uint32_t bl[2][4];
                #pragma unroll
                for (int bj = 0; bj < 2; bj++)
                    ldsm4(sb + S_BLO + SWZ64((b_row + bj * 16) * 64 + kb + b_byt), bl[bj]);
                #pragma unroll
                for (int mi = 0; mi < 4; mi++)
                    #pragma unroll
                    for (int nj = 0; nj < 4; nj++)
                        mma16816(acc[mi][nj], ah[mi], bl[nj >> 1][(nj & 1) * 2],
                                 bl[nj >> 1][(nj & 1) * 2 + 1]);
            }
            {
                uint32_t al[4][4];
                #pragma unroll
                for (int mi = 0; mi < 4; mi++)
                    ldsm4(sb + S_ALO + SWZ64((a_row + mi * 16) * 64 + kb + a_byt), al[mi]);
                #pragma unroll
                for (int mi = 0; mi < 4; mi++)
                    #pragma unroll
                    for (int nj = 0; nj < 4; nj++)
                        mma16816(acc[mi][nj], al[mi], bh[nj >> 1][(nj & 1) * 2],
                                 bh[nj >> 1][(nj & 1) * 2 + 1]);
            }
        }
    }

    // ---- epilogue: relu + store ----
    int l4 = lid >> 2;
    int l2 = (lid & 3) * 2;
    #pragma unroll
    for (int mi = 0; mi < 4; mi++) {
        #pragma unroll
        for (int nj = 0; nj < 4; nj++) {
            int m = wm * 64 + mi * 16 + l4;
            int n = n0 + wn * 32 + nj * 8 + l2;
            float2 v0, v1;
            v0.x = fmaxf(acc[mi][nj][0], 0.f);
            v0.y = fmaxf(acc[mi][nj][1], 0.f);
            v1.x = fmaxf(acc[mi][nj][2], 0.f);
            v1.y = fmaxf(acc[mi][nj][3], 0.f);
            *reinterpret_cast<float2*>(Cp + (size_t)m * HWSZ + n) = v0;
            *reinterpret_cast<float2*>(Cp + (size_t)(m + 8) * HWSZ + n) = v1;
        }
    }
}

// ---------------------------------------------------------------------------
// Kernel 5: cls head.
// ---------------------------------------------------------------------------
__global__ void __launch_bounds__(256) k_head_cls(const float* __restrict__ wcls,
                                                  const float* __restrict__ bcls,
                                                  float* __restrict__ out)
{
    __shared__ float red[8][13 * 32];
    int tid = threadIdx.x;
    int cg = tid >> 5;
    int hwl = tid & 31;
    int hw = blockIdx.x * 32 + hwl;

    float acc[13];
    #pragma unroll
    for (int o = 0; o < 13; o++) acc[o] = 0.f;
    const float* __restrict__ d = g_dfm[0];
    int c0 = cg * 96;
    for (int c = c0; c < c0 + 96; c++) {
        float v = d[(size_t)c * HWSZ + hw];
        #pragma unroll
        for (int o = 0; o < 13; o++)
            acc[o] = fmaf(wcls[o * 768 + c], v, acc[o]);
    }
    #pragma unroll
    for (int o = 0; o < 13; o++) red[cg][o * 32 + hwl] = acc[o];
    __syncthreads();

    if (tid < 32) {
        #pragma unroll
        for (int o = 0; o < 13; o++) {
            float s = bcls[o];
            #pragma unroll
            for (int g = 0; g < 8; g++) s += red[g][o * 32 + tid];
            out[(size_t)o * HWSZ + blockIdx.x * 32 + tid] = s;
        }
    }
}

// ---------------------------------------------------------------------------
// Kernel 6: kpt + bbox heads + minmax bbox decode (fused).
// ---------------------------------------------------------------------------
__global__ void __launch_bounds__(256) k_head_pts(const float* __restrict__ wkpt,
                                                  const float* __restrict__ bkpt,
                                                  const float* __restrict__ wbb,
                                                  const float* __restrict__ bbb,
                                                  const float* __restrict__ kprev,
                                                  float* __restrict__ out)
{
    __shared__ float red[8][38 * 32];
    int tid = threadIdx.x;
    int cg = tid >> 5;
    int hwl = tid & 31;
    int hw = blockIdx.x * 32 + hwl;

    float acck[34], accb[4];
    #pragma unroll
    for (int o = 0; o < 34; o++) acck[o] = 0.f;
    #pragma unroll
    for (int o = 0; o < 4; o++)  accb[o] = 0.f;

    const float* __restrict__ dk = g_dfm[1];
    const float* __restrict__ db = g_dfm[2];
    int c0 = cg * 96;
    for (int c = c0; c < c0 + 96; c++) {
        float vk = dk[(size_t)c * HWSZ + hw];
        float vb = db[(size_t)c * HWSZ + hw];
        #pragma unroll
        for (int o = 0; o < 34; o++)
            acck[o] = fmaf(wkpt[o * 768 + c], vk, acck[o]);
        #pragma unroll
        for (int o = 0; o < 4; o++)
            accb[o] = fmaf(wbb[o * 768 + c], vb, accb[o]);
    }
    #pragma unroll
    for (int o = 0; o < 34; o++) red[cg][o * 32 + hwl] = acck[o];
    #pragma unroll
    for (int o = 0; o < 4; o++)  red[cg][(34 + o) * 32 + hwl] = accb[o];
    __syncthreads();

    if (tid < 32) {
        int hwg = blockIdx.x * 32 + tid;
        float k2[34], b2[4];
        #pragma unroll
        for (int o = 0; o < 34; o++) {
            float s = bkpt[o];
            #pragma unroll
            for (int g = 0; g < 8; g++) s += red[g][o * 32 + tid];
            s += kprev[(size_t)o * HWSZ + hwg];
            k2[o] = s;
            out[(size_t)(17 + o) * HWSZ + hwg] = s;
        }
        #pragma unroll
        for (int o = 0; o < 4; o++) {
            float s = bbb[o];
            #pragma unroll
            for (int g = 0; g < 8; g++) s += red[g][(34 + o) * 32 + tid];
            b2[o] = s;
        }

        float left = 1e30f, right = -1e30f, top = 1e30f, bot = -1e30f;
        #pragma unroll
        for (int i = 0; i < 17; i++) {
            float py = k2[2 * i];
            float px = k2[2 * i + 1];
            top   = fminf(top, py);   bot   = fmaxf(bot, py);
            left  = fminf(left, px);  right = fmaxf(right, px);
        }
        float cx = (left + right) * 0.5f;
        float cy = (top + bot) * 0.5f;
        float hwid = (cx - left) * expf(b2[0]);
        float hhei = (cy - top)  * expf(b2[1]);
        cx += b2[2];
        cy += b2[3];
        out[(size_t)(13 + 0) * HWSZ + hwg] = cx - hwid;
        out[(size_t)(13 + 1) * HWSZ + hwg] = cy - hhei;
        out[(size_t)(13 + 2) * HWSZ + hwg] = cx + hwid;
        out[(size_t)(13 + 3) * HWSZ + hwg] = cy + hhei;
    }
}

// ---------------------------------------------------------------------------
// Launch
// ---------------------------------------------------------------------------
extern "C" void kernel_launch(void* const* d_in, const int* in_sizes, int n_in,
                              void* d_out, int out_size)
{
    const float* cls_feat = (const float*)d_in[0];
    const float* pts_feat = (const float*)d_in[1];
    const float* kprev    = (const float*)d_in[2];
    const float* w_do     = (const float*)d_in[3];
    const float* b_do     = (const float*)d_in[4];
    const float* w_cls    = (const float*)d_in[14];
    const float* b_cls    = (const float*)d_in[15];
    const float* w_kpt    = (const float*)d_in[16];
    const float* b_kpt    = (const float*)d_in[17];
    const float* w_bbox   = (const float*)d_in[18];
    const float* b_bbox   = (const float*)d_in[19];
    float* out = (float*)d_out;

    k_corners<<<dim3(NPTS, HWSZ / 256), 256>>>(kprev, w_do, b_do);

    W9 ws;
    for (int i = 0; i < 9; i++) ws.p[i] = (const float*)d_in[5 + i];
    k_wt<<<dim3(64, 1, 9), 256>>>(ws);

    k_ft<<<dim3(HWSZ / 32, 256 / 32, 2), dim3(32, 8)>>>(cls_feat, pts_feat);

    // 9 block-diagonal sub-GEMMs, block M256 x N128 x K32, HMMA bf16x3
    k_mma<<<dim3(HWSZ / 128, 9), 512>>>();

    k_head_cls<<<HWSZ / 32, 256>>>(w_cls, b_cls, out);
    k_head_pts<<<HWSZ / 32, 256>>>(w_kpt, b_kpt, w_bbox, b_bbox, kprev, out);
}

// round 8
// speedup vs baseline: 3.3455x; 1.2420x over previous
#include <cuda_runtime.h>
#include <cuda_bf16.h>
#include <math.h>
#include <stdint.h>

// ---------------------------------------------------------------------------
// Problem constants (B=1, C=256, H=W=64, FC=256, kernels 3/5/7 -> 83 points)
// ---------------------------------------------------------------------------
#define HWSZ 4096
#define NPTS 83
#define KTOT 21248         // 83*256 packed weight K layout

// ---------------------------------------------------------------------------
// Device scratch
// ---------------------------------------------------------------------------
__device__ __align__(16) int   g_cidx[NPTS * HWSZ * 4];
__device__ __align__(16) float g_cw  [NPTS * HWSZ * 4];
__device__ __nv_bfloat16 g_wa_hi[3][(size_t)256 * KTOT];  // weights hi, [m][k]
__device__ __nv_bfloat16 g_wa_lo[3][(size_t)256 * KTOT];  // weights lo
__device__ float g_ft[2][(size_t)HWSZ * 256];             // feat transposed [hw][c]
__device__ float g_dfm[3][(size_t)768 * HWSZ];            // relu(deform conv)

// ---------------------------------------------------------------------------
// helpers
// ---------------------------------------------------------------------------
__device__ __forceinline__ uint32_t smem_to_u32(const void* p) {
    uint32_t a;
    asm("{ .reg .u64 t; cvta.to.shared.u64 t, %1; cvt.u32.u64 %0, t; }"
        : "=r"(a) : "l"(p));
    return a;
}
// SW64 swizzle for 64-byte rows (atom = 8 rows x 64B)
#define SWZ64(o) ((o) ^ (((o) >> 3) & 0x30))

__device__ __forceinline__ void ldsm4(uint32_t addr, uint32_t* r) {
    asm volatile("ldmatrix.sync.aligned.m8n8.x4.shared.b16 {%0,%1,%2,%3}, [%4];"
        : "=r"(r[0]), "=r"(r[1]), "=r"(r[2]), "=r"(r[3]) : "r"(addr));
}
__device__ __forceinline__ void mma16816(float* c, const uint32_t* a,
                                         uint32_t b0, uint32_t b1) {
    asm volatile(
        "mma.sync.aligned.m16n8k16.row.col.f32.bf16.bf16.f32 "
        "{%0,%1,%2,%3}, {%4,%5,%6,%7}, {%8,%9}, {%0,%1,%2,%3};"
        : "+f"(c[0]), "+f"(c[1]), "+f"(c[2]), "+f"(c[3])
        : "r"(a[0]), "r"(a[1]), "r"(a[2]), "r"(a[3]), "r"(b0), "r"(b1));
}
__device__ __forceinline__ void cpa16(uint32_t dst, const void* src) {
    asm volatile("cp.async.cg.shared.global [%0], [%1], 16;"
                 :: "r"(dst), "l"(src) : "memory");
}
#define CPA_COMMIT() asm volatile("cp.async.commit_group;" ::: "memory")
#define CPA_WAIT0()  asm volatile("cp.async.wait_group 0;" ::: "memory")
__device__ __forceinline__ void pref_l1(const void* p) {
    asm volatile("prefetch.global.L1 [%0];" :: "l"(p));
}

// per-stage smem layout: A hi 16KB | A lo 16KB | B hi 8KB | B lo 8KB = 48KB
#define S_AHI 0
#define S_ALO 16384
#define S_BHI 32768
#define S_BLO 40960
#define STAGE 49152
#define SMEM_DYN (2 * STAGE)

// ---------------------------------------------------------------------------
// Kernel 1: fused offset 1x1 conv + bilinear corner table.
// ---------------------------------------------------------------------------
__global__ void k_corners(const float* __restrict__ kprev,
                          const float* __restrict__ w_do,
                          const float* __restrict__ b_do)
{
    int kk = blockIdx.x;
    int hw = blockIdx.y * 256 + threadIdx.x;
    int h = hw >> 6, w = hw & 63;

    int base, kkl;
    if (kk < 9)       { base = 0;  kkl = kk;      }
    else if (kk < 34) { base = 18; kkl = kk - 9;  }
    else              { base = 68; kkl = kk - 34; }
    int chy = base + 2 * kkl;
    int chx = chy + 1;

    float dy = b_do[chy], dx = b_do[chx];
    #pragma unroll 2
    for (int i = 0; i < 34; i++) {
        float v = kprev[i * HWSZ + hw];
        dy = fmaf(w_do[chy * 34 + i], v, dy);
        dx = fmaf(w_do[chx * 34 + i], v, dx);
    }

    float y = (float)h + dy;
    float x = (float)w + dx;
    float y0f = floorf(y), x0f = floorf(x);
    int y0 = (int)y0f, x0 = (int)x0f;
    float wy = y - y0f, wx = x - x0f;

    int   yi[4] = { y0, y0, y0 + 1, y0 + 1 };
    int   xi[4] = { x0, x0 + 1, x0, x0 + 1 };
    float wb[4] = { (1.f - wy) * (1.f - wx), (1.f - wy) * wx,
                    wy * (1.f - wx),         wy * wx };

    int o = (kk * HWSZ + hw) * 4;
    #pragma unroll
    for (int j = 0; j < 4; j++) {
        bool valid = (yi[j] >= 0) && (yi[j] < 64) && (xi[j] >= 0) && (xi[j] < 64);
        int yc = min(max(yi[j], 0), 63);
        int xc = min(max(xi[j], 0), 63);
        g_cidx[o + j] = yc * 64 + xc;
        g_cw  [o + j] = valid ? wb[j] : 0.0f;
    }
}

// ---------------------------------------------------------------------------
// Kernel 2: weight transpose + bf16 hi/lo split (division-free).
//   grid (o=256, sub=9), block 256 (=c). Thread loops kkl.
// ---------------------------------------------------------------------------
struct W9 { const float* p[9]; };

__global__ void k_wt(W9 ws)
{
    int sub = blockIdx.y;
    int branch = sub / 3;                 // compile-time-ish tiny divs, once
    int ks = sub - branch * 3;
    int Kp    = (ks == 0) ? 9 : (ks == 1) ? 25 : 49;
    int kbase = (ks == 0) ? 0 : (ks == 1) ? 9  : 34;
    int o = blockIdx.x;
    int c = threadIdx.x;

    const float* src = ws.p[sub] + ((size_t)o * 256 + c) * Kp;
    __nv_bfloat16* dh = g_wa_hi[branch] + (size_t)o * KTOT + (size_t)kbase * 256 + c;
    __nv_bfloat16* dl = g_wa_lo[branch] + (size_t)o * KTOT + (size_t)kbase * 256 + c;

    for (int kkl = 0; kkl < Kp; kkl++) {
        float v = src[kkl];
        __nv_bfloat16 h = __float2bfloat16(v);
        dh[(size_t)kkl * 256] = h;
        dl[(size_t)kkl * 256] = __float2bfloat16(v - __bfloat162float(h));
    }
}

// ---------------------------------------------------------------------------
// Kernel 3: feature transpose [c][hw] -> [hw][c]
// ---------------------------------------------------------------------------
__global__ void k_ft(const float* __restrict__ f0, const float* __restrict__ f1)
{
    __shared__ float t[32][33];
    int f = blockIdx.z;
    const float* __restrict__ src = f ? f1 : f0;
    int hw0 = blockIdx.x * 32, c0 = blockIdx.y * 32;
    #pragma unroll
    for (int i = 0; i < 4; i++) {
        int c = c0 + threadIdx.y + i * 8;
        t[threadIdx.y + i * 8][threadIdx.x] = src[(size_t)c * HWSZ + hw0 + threadIdx.x];
    }
    __syncthreads();
    #pragma unroll
    for (int i = 0; i < 4; i++) {
        int hw = hw0 + threadIdx.y + i * 8;
        g_ft[f][(size_t)hw * 256 + c0 + threadIdx.x] = t[threadIdx.x][threadIdx.y + i * 8];
    }
}

// ---------------------------------------------------------------------------
// Kernel 4: pipelined HMMA (mma.sync bf16x3) GEMM with fused bilinear gather.
//   9 block-diagonal sub-GEMMs via blockIdx.y. Block M256 x N128 x K32,
//   512 threads = 16 warps (4M x 4N). Double-buffered smem (2 x 48KB):
//   A via cp.async into next stage pre-math; B taps L1-prefetched pre-math,
//   gathered post-math (L1 hits). One barrier per chunk.
// ---------------------------------------------------------------------------
__global__ void __launch_bounds__(512, 1) k_mma()
{
    const int SUBMAP[9] = {2, 5, 8, 1, 4, 7, 0, 3, 6};  // heavy (k7) first
    const int P0_[3] = {0, 9, 34};
    const int NP_[3] = {9, 25, 49};

    extern __shared__ __align__(128) char smem[];
    uint32_t sb = smem_to_u32(smem);

    int tid = threadIdx.x;
    int wid = tid >> 5;
    int lid = tid & 31;

    int sub = SUBMAP[blockIdx.y];
    int branch = sub / 3;
    int ks = sub - branch * 3;
    int p0 = P0_[ks];
    int np = NP_[ks];

    int n0 = blockIdx.x * 128;
    const float* __restrict__ ft = g_ft[branch == 0 ? 0 : 1];
    const __nv_bfloat16* __restrict__ Ah = g_wa_hi[branch];
    const __nv_bfloat16* __restrict__ Al = g_wa_lo[branch];
    float* __restrict__ Cp = g_dfm[branch] + (size_t)ks * 256 * HWSZ;

    int wm = wid >> 2;
    int wn = wid & 3;

    // gather mapping: 4 threads per B row (8 channels each)
    int n_l = tid >> 2;
    int qg  = tid & 3;
    int n_g = n0 + n_l;

    // A copy mapping: tid<256 -> hi rows, tid>=256 -> lo rows
    int arow = tid & 255;
    int asel = tid >> 8;
    const __nv_bfloat16* Asrc_base = asel ? Al : Ah;
    uint32_t a_stage_off = asel ? S_ALO : S_AHI;

    // ldmatrix lane address components
    uint32_t a_row = wm * 64 + ((lid >> 3) & 1) * 8 + (lid & 7);
    uint32_t a_byt = (lid >> 4) * 16;
    uint32_t b_row = wn * 32 + (lid & 7) + ((lid >> 4) & 1) * 8;
    uint32_t b_byt = ((lid >> 3) & 1) * 16;

    float acc[4][4][4];
    #pragma unroll
    for (int i = 0; i < 4; i++)
        #pragma unroll
        for (int j = 0; j < 4; j++)
            #pragma unroll
            for (int r = 0; r < 4; r++) acc[i][j][r] = 0.f;

    int4   id4;
    float4 wv4;
    int nchunk = np * 8;                  // 8 x K32 chunks per point

    // ---------------- pipeline helpers as lambdas ----------------
    auto fill_A = [&](int k0, uint32_t stage_base) {
        const __nv_bfloat16* Asrc = Asrc_base + (size_t)arow * KTOT + k0;
        uint32_t dbase = stage_base + a_stage_off;
        #pragma unroll
        for (int j = 0; j < 4; j++)
            cpa16(dbase + SWZ64((uint32_t)(arow * 64 + j * 16)), Asrc + j * 8);
    };
    auto gather_B = [&](int c0v, uint32_t stage_base) {
        int cb = c0v + qg * 8;
        const float* t0 = ft + (size_t)id4.x * 256 + cb;
        const float* t1 = ft + (size_t)id4.y * 256 + cb;
        const float* t2 = ft + (size_t)id4.z * 256 + cb;
        const float* t3 = ft + (size_t)id4.w * 256 + cb;
        #pragma unroll
        for (int qq = 0; qq < 2; qq++) {
            float4 a = *reinterpret_cast<const float4*>(t0 + qq * 4);
            float4 b = *reinterpret_cast<const float4*>(t1 + qq * 4);
            float4 c = *reinterpret_cast<const float4*>(t2 + qq * 4);
            float4 d = *reinterpret_cast<const float4*>(t3 + qq * 4);
            float v0 = wv4.x*a.x + wv4.y*b.x + wv4.z*c.x + wv4.w*d.x;
            float v1 = wv4.x*a.y + wv4.y*b.y + wv4.z*c.y + wv4.w*d.y;
            float v2 = wv4.x*a.z + wv4.y*b.z + wv4.z*c.z + wv4.w*d.z;
            float v3 = wv4.x*a.w + wv4.y*b.w + wv4.z*c.w + wv4.w*d.w;
            __nv_bfloat162 h01 = __floats2bfloat162_rn(v0, v1);
            __nv_bfloat162 h23 = __floats2bfloat162_rn(v2, v3);
            __nv_bfloat162 l01 = __floats2bfloat162_rn(
                v0 - __bfloat162float(h01.x), v1 - __bfloat162float(h01.y));
            __nv_bfloat162 l23 = __floats2bfloat162_rn(
                v2 - __bfloat162float(h23.x), v3 - __bfloat162float(h23.y));
            uint32_t bof = SWZ64((uint32_t)(n_l * 64 + qg * 16 + qq * 8));
            uint2 hv, lv;
            hv.x = *reinterpret_cast<uint32_t*>(&h01);
            hv.y = *reinterpret_cast<uint32_t*>(&h23);
            lv.x = *reinterpret_cast<uint32_t*>(&l01);
            lv.y = *reinterpret_cast<uint32_t*>(&l23);
            *reinterpret_cast<uint2*>(smem + (stage_base - sb) + S_BHI + bof) = hv;
            *reinterpret_cast<uint2*>(smem + (stage_base - sb) + S_BLO + bof) = lv;
        }
    };

    // ---------------- prologue: stage 0 = chunk 0 ----------------
    {
        int o = (p0 * HWSZ + n_g) * 4;
        id4 = *reinterpret_cast<const int4*>(&g_cidx[o]);
        wv4 = *reinterpret_cast<const float4*>(&g_cw[o]);
        fill_A(p0 * 256, sb);
        CPA_COMMIT();
        gather_B(0, sb);
        CPA_WAIT0();
    }
    __syncthreads();

    for (int ch = 0; ch < nchunk; ch++) {
        uint32_t cur_base = sb + (ch & 1) * STAGE;
        uint32_t nxt_base = sb + ((ch + 1) & 1) * STAGE;
        bool has_next = (ch + 1) < nchunk;
        int gp1 = p0 + ((ch + 1) >> 3);
        int c01 = ((ch + 1) & 7) * 32;

        if (has_next) {
            if (((ch + 1) & 7) == 0) {           // next chunk starts new point
                int o = (gp1 * HWSZ + n_g) * 4;  // loads hidden behind math
                id4 = *reinterpret_cast<const int4*>(&g_cidx[o]);
                wv4 = *reinterpret_cast<const float4*>(&g_cw[o]);
            } else if (qg == 0) {                // same point: prefetch tap lines
                pref_l1(ft + (size_t)id4.x * 256 + c01);
                pref_l1(ft + (size_t)id4.y * 256 + c01);
                pref_l1(ft + (size_t)id4.z * 256 + c01);
                pref_l1(ft + (size_t)id4.w * 256 + c01);
            }
            fill_A(gp1 * 256 + c01, nxt_base);
            CPA_COMMIT();
        }

        // ---- math on current stage: 2 ksteps, 3 staged products ----
        #pragma unroll
        for (int ks2 = 0; ks2 < 2; ks2++) {
            uint32_t kb = ks2 * 32;
            uint32_t ah[4][4], bh[2][4];
            #pragma unroll
            for (int mi = 0; mi < 4; mi++)
                ldsm4(cur_base + S_AHI + SWZ64((a_row + mi * 16) * 64 + kb + a_byt), ah[mi]);
            #pragma unroll
            for (int bj = 0; bj < 2; bj++)
                ldsm4(cur_base + S_BHI + SWZ64((b_row + bj * 16) * 64 + kb + b_byt), bh[bj]);
            #pragma unroll
            for (int mi = 0; mi < 4; mi++)
                #pragma unroll
                for (int nj = 0; nj < 4; nj++)
                    mma16816(acc[mi][nj], ah[mi], bh[nj >> 1][(nj & 1) * 2],
                             bh[nj >> 1][(nj & 1) * 2 + 1]);
            {
                uint32_t bl[2][4];
                #pragma unroll
                for (int bj = 0; bj < 2; bj++)
                    ldsm4(cur_base + S_BLO + SWZ64((b_row + bj * 16) * 64 + kb + b_byt), bl[bj]);
                #pragma unroll
                for (int mi = 0; mi < 4; mi++)
                    #pragma unroll
                    for (int nj = 0; nj < 4; nj++)
                        mma16816(acc[mi][nj], ah[mi], bl[nj >> 1][(nj & 1) * 2],
                                 bl[nj >> 1][(nj & 1) * 2 + 1]);
            }
            {
                uint32_t al[4][4];
                #pragma unroll
                for (int mi = 0; mi < 4; mi++)
                    ldsm4(cur_base + S_ALO + SWZ64((a_row + mi * 16) * 64 + kb + a_byt), al[mi]);
                #pragma unroll
                for (int mi = 0; mi < 4; mi++)
                    #pragma unroll
                    for (int nj = 0; nj < 4; nj++)
                        mma16816(acc[mi][nj], al[mi], bh[nj >> 1][(nj & 1) * 2],
                                 bh[nj >> 1][(nj & 1) * 2 + 1]);
            }
        }

        if (has_next) {
            gather_B(c01, nxt_base);    // LDGs: L1 hits (prefetched) most chunks
            CPA_WAIT0();
        }
        __syncthreads();
    }

    // ---- epilogue: relu + store ----
    int l4 = lid >> 2;
    int l2 = (lid & 3) * 2;
    #pragma unroll
    for (int mi = 0; mi < 4; mi++) {
        #pragma unroll
        for (int nj = 0; nj < 4; nj++) {
            int m = wm * 64 + mi * 16 + l4;
            int n = n0 + wn * 32 + nj * 8 + l2;
            float2 v0, v1;
            v0.x = fmaxf(acc[mi][nj][0], 0.f);
            v0.y = fmaxf(acc[mi][nj][1], 0.f);
            v1.x = fmaxf(acc[mi][nj][2], 0.f);
            v1.y = fmaxf(acc[mi][nj][3], 0.f);
            *reinterpret_cast<float2*>(Cp + (size_t)m * HWSZ + n) = v0;
            *reinterpret_cast<float2*>(Cp + (size_t)(m + 8) * HWSZ + n) = v1;
        }
    }
}

// ---------------------------------------------------------------------------
// Kernel 5: cls head.
// ---------------------------------------------------------------------------
__global__ void __launch_bounds__(256) k_head_cls(const float* __restrict__ wcls,
                                                  const float* __restrict__ bcls,
                                                  float* __restrict__ out)
{
    __shared__ float red[8][13 * 32];
    int tid = threadIdx.x;
    int cg = tid >> 5;
    int hwl = tid & 31;
    int hw = blockIdx.x * 32 + hwl;

    float acc[13];
    #pragma unroll
    for (int o = 0; o < 13; o++) acc[o] = 0.f;
    const float* __restrict__ d = g_dfm[0];
    int c0 = cg * 96;
    for (int c = c0; c < c0 + 96; c++) {
        float v = d[(size_t)c * HWSZ + hw];
        #pragma unroll
        for (int o = 0; o < 13; o++)
            acc[o] = fmaf(wcls[o * 768 + c], v, acc[o]);
    }
    #pragma unroll
    for (int o = 0; o < 13; o++) red[cg][o * 32 + hwl] = acc[o];
    __syncthreads();

    if (tid < 32) {
        #pragma unroll
        for (int o = 0; o < 13; o++) {
            float s = bcls[o];
            #pragma unroll
            for (int g = 0; g < 8; g++) s += red[g][o * 32 + tid];
            out[(size_t)o * HWSZ + blockIdx.x * 32 + tid] = s;
        }
    }
}

// ---------------------------------------------------------------------------
// Kernel 6: kpt + bbox heads + minmax bbox decode (fused).
// ---------------------------------------------------------------------------
__global__ void __launch_bounds__(256) k_head_pts(const float* __restrict__ wkpt,
                                                  const float* __restrict__ bkpt,
                                                  const float* __restrict__ wbb,
                                                  const float* __restrict__ bbb,
                                                  const float* __restrict__ kprev,
                                                  float* __restrict__ out)
{
    __shared__ float red[8][38 * 32];
    int tid = threadIdx.x;
    int cg = tid >> 5;
    int hwl = tid & 31;
    int hw = blockIdx.x * 32 + hwl;

    float acck[34], accb[4];
    #pragma unroll
    for (int o = 0; o < 34; o++) acck[o] = 0.f;
    #pragma unroll
    for (int o = 0; o < 4; o++)  accb[o] = 0.f;

    const float* __restrict__ dk = g_dfm[1];
    const float* __restrict__ db = g_dfm[2];
    int c0 = cg * 96;
    for (int c = c0; c < c0 + 96; c++) {
        float vk = dk[(size_t)c * HWSZ + hw];
        float vb = db[(size_t)c * HWSZ + hw];
        #pragma unroll
        for (int o = 0; o < 34; o++)
            acck[o] = fmaf(wkpt[o * 768 + c], vk, acck[o]);
        #pragma unroll
        for (int o = 0; o < 4; o++)
            accb[o] = fmaf(wbb[o * 768 + c], vb, accb[o]);
    }
    #pragma unroll
    for (int o = 0; o < 34; o++) red[cg][o * 32 + hwl] = acck[o];
    #pragma unroll
    for (int o = 0; o < 4; o++)  red[cg][(34 + o) * 32 + hwl] = accb[o];
    __syncthreads();

    if (tid < 32) {
        int hwg = blockIdx.x * 32 + tid;
        float k2[34], b2[4];
        #pragma unroll
        for (int o = 0; o < 34; o++) {
            float s = bkpt[o];
            #pragma unroll
            for (int g = 0; g < 8; g++) s += red[g][o * 32 + tid];
            s += kprev[(size_t)o * HWSZ + hwg];
            k2[o] = s;
            out[(size_t)(17 + o) * HWSZ + hwg] = s;
        }
        #pragma unroll
        for (int o = 0; o < 4; o++) {
            float s = bbb[o];
            #pragma unroll
            for (int g = 0; g < 8; g++) s += red[g][(34 + o) * 32 + tid];
            b2[o] = s;
        }

        float left = 1e30f, right = -1e30f, top = 1e30f, bot = -1e30f;
        #pragma unroll
        for (int i = 0; i < 17; i++) {
            float py = k2[2 * i];
            float px = k2[2 * i + 1];
            top   = fminf(top, py);   bot   = fmaxf(bot, py);
            left  = fminf(left, px);  right = fmaxf(right, px);
        }
        float cx = (left + right) * 0.5f;
        float cy = (top + bot) * 0.5f;
        float hwid = (cx - left) * expf(b2[0]);
        float hhei = (cy - top)  * expf(b2[1]);
        cx += b2[2];
        cy += b2[3];
        out[(size_t)(13 + 0) * HWSZ + hwg] = cx - hwid;
        out[(size_t)(13 + 1) * HWSZ + hwg] = cy - hhei;
        out[(size_t)(13 + 2) * HWSZ + hwg] = cx + hwid;
        out[(size_t)(13 + 3) * HWSZ + hwg] = cy + hhei;
    }
}

// ---------------------------------------------------------------------------
// Launch
// ---------------------------------------------------------------------------
extern "C" void kernel_launch(void* const* d_in, const int* in_sizes, int n_in,
                              void* d_out, int out_size)
{
    const float* cls_feat = (const float*)d_in[0];
    const float* pts_feat = (const float*)d_in[1];
    const float* kprev    = (const float*)d_in[2];
    const float* w_do     = (const float*)d_in[3];
    const float* b_do     = (const float*)d_in[4];
    const float* w_cls    = (const float*)d_in[14];
    const float* b_cls    = (const float*)d_in[15];
    const float* w_kpt    = (const float*)d_in[16];
    const float* b_kpt    = (const float*)d_in[17];
    const float* w_bbox   = (const float*)d_in[18];
    const float* b_bbox   = (const float*)d_in[19];
    float* out = (float*)d_out;

    // idempotent, immediate (not a stream op) — safe under graph capture
    cudaFuncSetAttribute(k_mma, cudaFuncAttributeMaxDynamicSharedMemorySize,
                         SMEM_DYN);

    k_corners<<<dim3(NPTS, HWSZ / 256), 256>>>(kprev, w_do, b_do);

    W9 ws;
    for (int i = 0; i < 9; i++) ws.p[i] = (const float*)d_in[5 + i];
    k_wt<<<dim3(256, 9), 256>>>(ws);

    k_ft<<<dim3(HWSZ / 32, 256 / 32, 2), dim3(32, 8)>>>(cls_feat, pts_feat);

    // 9 block-diagonal sub-GEMMs, M256 x N128 x K32, double-buffered pipeline
    k_mma<<<dim3(HWSZ / 128, 9), 512, SMEM_DYN>>>();

    k_head_cls<<<HWSZ / 32, 256>>>(w_cls, b_cls, out);
    k_head_pts<<<HWSZ / 32, 256>>>(w_kpt, b_kpt, w_bbox, b_bbox, kprev, out);
}

// round 9
// speedup vs baseline: 3.6056x; 1.0777x over previous
#include <cuda_runtime.h>
#include <cuda_fp16.h>
#include <math.h>
#include <stdint.h>

// ---------------------------------------------------------------------------
// Problem constants (B=1, C=256, H=W=64, FC=256, kernels 3/5/7 -> 83 points)
// ---------------------------------------------------------------------------
#define HWSZ 4096
#define NPTS 83
#define KTOT 21248         // 83*256 packed weight K layout

// ---------------------------------------------------------------------------
// Device scratch
// ---------------------------------------------------------------------------
__device__ __align__(16) int   g_cidx[NPTS * HWSZ * 4];
__device__ __align__(16) float g_cw  [NPTS * HWSZ * 4];
__device__ __half g_wa_hi[3][(size_t)256 * KTOT];         // weights hi, [m][k]
__device__ __half g_wa_lo[3][(size_t)256 * KTOT];         // weights lo
__device__ float g_ft[2][(size_t)HWSZ * 256];             // feat transposed [hw][c]
__device__ float g_dfm[3][(size_t)768 * HWSZ];            // relu(deform conv)

// ---------------------------------------------------------------------------
// helpers
// ---------------------------------------------------------------------------
__device__ __forceinline__ uint32_t smem_to_u32(const void* p) {
    uint32_t a;
    asm("{ .reg .u64 t; cvta.to.shared.u64 t, %1; cvt.u32.u64 %0, t; }"
        : "=r"(a) : "l"(p));
    return a;
}
// SW128 swizzle for 128-byte rows
#define SWZ(o) ((o) ^ (((o) >> 3) & 0x70))

__device__ __forceinline__ void ldsm4(uint32_t addr, uint32_t* r) {
    asm volatile("ldmatrix.sync.aligned.m8n8.x4.shared.b16 {%0,%1,%2,%3}, [%4];"
        : "=r"(r[0]), "=r"(r[1]), "=r"(r[2]), "=r"(r[3]) : "r"(addr));
}
__device__ __forceinline__ void mma16816(float* c, const uint32_t* a,
                                         uint32_t b0, uint32_t b1) {
    asm volatile(
        "mma.sync.aligned.m16n8k16.row.col.f32.f16.f16.f32 "
        "{%0,%1,%2,%3}, {%4,%5,%6,%7}, {%8,%9}, {%0,%1,%2,%3};"
        : "+f"(c[0]), "+f"(c[1]), "+f"(c[2]), "+f"(c[3])
        : "r"(a[0]), "r"(a[1]), "r"(a[2]), "r"(a[3]), "r"(b0), "r"(b1));
}
__device__ __forceinline__ void cpa16(uint32_t dst, const void* src) {
    asm volatile("cp.async.cg.shared.global [%0], [%1], 16;"
                 :: "r"(dst), "l"(src) : "memory");
}
#define CPA_COMMIT() asm volatile("cp.async.commit_group;" ::: "memory")
#define CPA_WAIT0()  asm volatile("cp.async.wait_group 0;" ::: "memory")
__device__ __forceinline__ void pref_l1(const void* p) {
    asm volatile("prefetch.global.L1 [%0];" :: "l"(p));
}

// per-stage smem: A hi 32KB | A lo 32KB | B 16KB = 80KB, x2 stages = 160KB
#define S_AHI 0
#define S_ALO 32768
#define S_BH  65536
#define STAGE 81920
#define SMEM_DYN (2 * STAGE)

// ---------------------------------------------------------------------------
// Kernel 1: fused offset 1x1 conv + bilinear corner table.
// ---------------------------------------------------------------------------
__global__ void k_corners(const float* __restrict__ kprev,
                          const float* __restrict__ w_do,
                          const float* __restrict__ b_do)
{
    int kk = blockIdx.x;
    int hw = blockIdx.y * 256 + threadIdx.x;
    int h = hw >> 6, w = hw & 63;

    int base, kkl;
    if (kk < 9)       { base = 0;  kkl = kk;      }
    else if (kk < 34) { base = 18; kkl = kk - 9;  }
    else              { base = 68; kkl = kk - 34; }
    int chy = base + 2 * kkl;
    int chx = chy + 1;

    float dy = b_do[chy], dx = b_do[chx];
    #pragma unroll 2
    for (int i = 0; i < 34; i++) {
        float v = kprev[i * HWSZ + hw];
        dy = fmaf(w_do[chy * 34 + i], v, dy);
        dx = fmaf(w_do[chx * 34 + i], v, dx);
    }

    float y = (float)h + dy;
    float x = (float)w + dx;
    float y0f = floorf(y), x0f = floorf(x);
    int y0 = (int)y0f, x0 = (int)x0f;
    float wy = y - y0f, wx = x - x0f;

    int   yi[4] = { y0, y0, y0 + 1, y0 + 1 };
    int   xi[4] = { x0, x0 + 1, x0, x0 + 1 };
    float wb[4] = { (1.f - wy) * (1.f - wx), (1.f - wy) * wx,
                    wy * (1.f - wx),         wy * wx };

    int o = (kk * HWSZ + hw) * 4;
    #pragma unroll
    for (int j = 0; j < 4; j++) {
        bool valid = (yi[j] >= 0) && (yi[j] < 64) && (xi[j] >= 0) && (xi[j] < 64);
        int yc = min(max(yi[j], 0), 63);
        int xc = min(max(xi[j], 0), 63);
        g_cidx[o + j] = yc * 64 + xc;
        g_cw  [o + j] = valid ? wb[j] : 0.0f;
    }
}

// ---------------------------------------------------------------------------
// Kernel 2: weight transpose + fp16 hi/lo split (division-free).
// ---------------------------------------------------------------------------
struct W9 { const float* p[9]; };

__global__ void k_wt(W9 ws)
{
    int sub = blockIdx.y;
    int branch = sub / 3;
    int ks = sub - branch * 3;
    int Kp    = (ks == 0) ? 9 : (ks == 1) ? 25 : 49;
    int kbase = (ks == 0) ? 0 : (ks == 1) ? 9  : 34;
    int o = blockIdx.x;
    int c = threadIdx.x;

    const float* src = ws.p[sub] + ((size_t)o * 256 + c) * Kp;
    __half* dh = g_wa_hi[branch] + (size_t)o * KTOT + (size_t)kbase * 256 + c;
    __half* dl = g_wa_lo[branch] + (size_t)o * KTOT + (size_t)kbase * 256 + c;

    for (int kkl = 0; kkl < Kp; kkl++) {
        float v = src[kkl];
        __half h = __float2half_rn(v);
        dh[(size_t)kkl * 256] = h;
        dl[(size_t)kkl * 256] = __float2half_rn(v - __half2float(h));
    }
}

// ---------------------------------------------------------------------------
// Kernel 3: feature transpose [c][hw] -> [hw][c]
// ---------------------------------------------------------------------------
__global__ void k_ft(const float* __restrict__ f0, const float* __restrict__ f1)
{
    __shared__ float t[32][33];
    int f = blockIdx.z;
    const float* __restrict__ src = f ? f1 : f0;
    int hw0 = blockIdx.x * 32, c0 = blockIdx.y * 32;
    #pragma unroll
    for (int i = 0; i < 4; i++) {
        int c = c0 + threadIdx.y + i * 8;
        t[threadIdx.y + i * 8][threadIdx.x] = src[(size_t)c * HWSZ + hw0 + threadIdx.x];
    }
    __syncthreads();
    #pragma unroll
    for (int i = 0; i < 4; i++) {
        int hw = hw0 + threadIdx.y + i * 8;
        g_ft[f][(size_t)hw * 256 + c0 + threadIdx.x] = t[threadIdx.x][threadIdx.y + i * 8];
    }
}

// ---------------------------------------------------------------------------
// Kernel 4: pipelined HMMA fp16x2-split GEMM with fused bilinear gather.
//   9 block-diagonal sub-GEMMs via blockIdx.y. Block M256 x N128 x K64,
//   512 threads = 16 warps (4M x 4N). Double-buffered 2x80KB smem.
//   Per chunk: A hi/lo via cp.async (next stage), B gathered+converted to
//   fp16 (single precision-rounded copy), then 4 ksteps x 32 mma/warp
//   (2 products: Ah*B + Al*B; error ~ B fp16 rounding ~1e-4).
// ---------------------------------------------------------------------------
__global__ void __launch_bounds__(512, 1) k_mma()
{
    const int SUBMAP[9] = {2, 5, 8, 1, 4, 7, 0, 3, 6};  // heavy (k7) first
    const int P0_[3] = {0, 9, 34};
    const int NP_[3] = {9, 25, 49};

    extern __shared__ __align__(128) char smem[];
    uint32_t sb = smem_to_u32(smem);

    int tid = threadIdx.x;
    int wid = tid >> 5;
    int lid = tid & 31;

    int sub = SUBMAP[blockIdx.y];
    int branch = sub / 3;
    int ks = sub - branch * 3;
    int p0 = P0_[ks];
    int np = NP_[ks];

    int n0 = blockIdx.x * 128;
    const float* __restrict__ ft = g_ft[branch == 0 ? 0 : 1];
    const __half* __restrict__ Ah = g_wa_hi[branch];
    const __half* __restrict__ Al = g_wa_lo[branch];
    float* __restrict__ Cp = g_dfm[branch] + (size_t)ks * 256 * HWSZ;

    int wm = wid >> 2;
    int wn = wid & 3;

    // gather mapping: 4 threads per B row (16 channels each)
    int n_l = tid >> 2;
    int qg  = tid & 3;
    int n_g = n0 + n_l;

    // A copy mapping: tid<256 -> hi rows, tid>=256 -> lo rows (128B/row)
    int arow = tid & 255;
    int asel = tid >> 8;
    const __half* Asrc_base = asel ? Al : Ah;
    uint32_t a_stage_off = asel ? S_ALO : S_AHI;

    // ldmatrix lane address components (128B rows, SW128)
    uint32_t a_row = wm * 64 + ((lid >> 3) & 1) * 8 + (lid & 7);
    uint32_t a_byt = (lid >> 4) * 16;
    uint32_t b_row = wn * 32 + (lid & 7) + ((lid >> 4) & 1) * 8;
    uint32_t b_byt = ((lid >> 3) & 1) * 16;

    float acc[4][4][4];
    #pragma unroll
    for (int i = 0; i < 4; i++)
        #pragma unroll
        for (int j = 0; j < 4; j++)
            #pragma unroll
            for (int r = 0; r < 4; r++) acc[i][j][r] = 0.f;

    int4   id4;
    float4 wv4;
    int nchunk = np * 4;                  // 4 x K64 chunks per point

    auto fill_A = [&](int k0, uint32_t stage_base) {
        const __half* Asrc = Asrc_base + (size_t)arow * KTOT + k0;
        uint32_t dbase = stage_base + a_stage_off;
        #pragma unroll
        for (int j = 0; j < 8; j++)
            cpa16(dbase + SWZ((uint32_t)(arow * 128 + j * 16)), Asrc + j * 8);
    };
    auto gather_B = [&](int c0v, uint32_t stage_base) {
        int cb = c0v + qg * 16;
        const float* t0 = ft + (size_t)id4.x * 256 + cb;
        const float* t1 = ft + (size_t)id4.y * 256 + cb;
        const float* t2 = ft + (size_t)id4.z * 256 + cb;
        const float* t3 = ft + (size_t)id4.w * 256 + cb;
        char* bp = smem + (stage_base - sb) + S_BH;
        #pragma unroll
        for (int qq = 0; qq < 4; qq++) {
            float4 a = *reinterpret_cast<const float4*>(t0 + qq * 4);
            float4 b = *reinterpret_cast<const float4*>(t1 + qq * 4);
            float4 c = *reinterpret_cast<const float4*>(t2 + qq * 4);
            float4 d = *reinterpret_cast<const float4*>(t3 + qq * 4);
            float v0 = wv4.x*a.x + wv4.y*b.x + wv4.z*c.x + wv4.w*d.x;
            float v1 = wv4.x*a.y + wv4.y*b.y + wv4.z*c.y + wv4.w*d.y;
            float v2 = wv4.x*a.z + wv4.y*b.z + wv4.z*c.z + wv4.w*d.z;
            float v3 = wv4.x*a.w + wv4.y*b.w + wv4.z*c.w + wv4.w*d.w;
            __half2 h01 = __floats2half2_rn(v0, v1);
            __half2 h23 = __floats2half2_rn(v2, v3);
            uint32_t bof = SWZ((uint32_t)(n_l * 128 + (qg * 16 + qq * 4) * 2));
            uint2 hv;
            hv.x = *reinterpret_cast<uint32_t*>(&h01);
            hv.y = *reinterpret_cast<uint32_t*>(&h23);
            *reinterpret_cast<uint2*>(bp + bof) = hv;
        }
    };

    // ---------------- prologue: stage 0 = chunk 0 ----------------
    {
        int o = (p0 * HWSZ + n_g) * 4;
        id4 = *reinterpret_cast<const int4*>(&g_cidx[o]);
        wv4 = *reinterpret_cast<const float4*>(&g_cw[o]);
        fill_A(p0 * 256, sb);
        CPA_COMMIT();
        gather_B(0, sb);
        CPA_WAIT0();
    }
    __syncthreads();

    for (int ch = 0; ch < nchunk; ch++) {
        uint32_t cur_base = sb + (ch & 1) * STAGE;
        uint32_t nxt_base = sb + ((ch + 1) & 1) * STAGE;
        bool has_next = (ch + 1) < nchunk;
        int gp1 = p0 + ((ch + 1) >> 2);
        int c01 = ((ch + 1) & 3) * 64;

        if (has_next) {
            if (((ch + 1) & 3) == 0) {           // next chunk starts new point
                int o = (gp1 * HWSZ + n_g) * 4;
                id4 = *reinterpret_cast<const int4*>(&g_cidx[o]);
                wv4 = *reinterpret_cast<const float4*>(&g_cw[o]);
            } else if (qg < 2) {                 // prefetch next tap lines
                const float* ta = qg ? (ft + (size_t)id4.z * 256 + c01)
                                     : (ft + (size_t)id4.x * 256 + c01);
                const float* tb = qg ? (ft + (size_t)id4.w * 256 + c01)
                                     : (ft + (size_t)id4.y * 256 + c01);
                pref_l1(ta); pref_l1(ta + 32);
                pref_l1(tb); pref_l1(tb + 32);
            }
            fill_A(gp1 * 256 + c01, nxt_base);
            CPA_COMMIT();
        }

        // ---- math on current stage: 4 ksteps x 2 products ----
        #pragma unroll
        for (int ks2 = 0; ks2 < 4; ks2++) {
            uint32_t kb = ks2 * 32;
            uint32_t ah[4][4], bh[2][4];
            #pragma unroll
            for (int mi = 0; mi < 4; mi++)
                ldsm4(cur_base + S_AHI + SWZ((a_row + mi * 16) * 128 + kb + a_byt), ah[mi]);
            #pragma unroll
            for (int bj = 0; bj < 2; bj++)
                ldsm4(cur_base + S_BH + SWZ((b_row + bj * 16) * 128 + kb + b_byt), bh[bj]);
            #pragma unroll
            for (int mi = 0; mi < 4; mi++)
                #pragma unroll
                for (int nj = 0; nj < 4; nj++)
                    mma16816(acc[mi][nj], ah[mi], bh[nj >> 1][(nj & 1) * 2],
                             bh[nj >> 1][(nj & 1) * 2 + 1]);
            {
                uint32_t al[4][4];
                #pragma unroll
                for (int mi = 0; mi < 4; mi++)
                    ldsm4(cur_base + S_ALO + SWZ((a_row + mi * 16) * 128 + kb + a_byt), al[mi]);
                #pragma unroll
                for (int mi = 0; mi < 4; mi++)
                    #pragma unroll
                    for (int nj = 0; nj < 4; nj++)
                        mma16816(acc[mi][nj], al[mi], bh[nj >> 1][(nj & 1) * 2],
                                 bh[nj >> 1][(nj & 1) * 2 + 1]);
            }
        }

        if (has_next) {
            gather_B(c01, nxt_base);
            CPA_WAIT0();
        }
        __syncthreads();
    }

    // ---- epilogue: relu + store ----
    int l4 = lid >> 2;
    int l2 = (lid & 3) * 2;
    #pragma unroll
    for (int mi = 0; mi < 4; mi++) {
        #pragma unroll
        for (int nj = 0; nj < 4; nj++) {
            int m = wm * 64 + mi * 16 + l4;
            int n = n0 + wn * 32 + nj * 8 + l2;
            float2 v0, v1;
            v0.x = fmaxf(acc[mi][nj][0], 0.f);
            v0.y = fmaxf(acc[mi][nj][1], 0.f);
            v1.x = fmaxf(acc[mi][nj][2], 0.f);
            v1.y = fmaxf(acc[mi][nj][3], 0.f);
            *reinterpret_cast<float2*>(Cp + (size_t)m * HWSZ + n) = v0;
            *reinterpret_cast<float2*>(Cp + (size_t)(m + 8) * HWSZ + n) = v1;
        }
    }
}

// ---------------------------------------------------------------------------
// Kernel 5: cls head.
// ---------------------------------------------------------------------------
__global__ void __launch_bounds__(256) k_head_cls(const float* __restrict__ wcls,
                                                  const float* __restrict__ bcls,
                                                  float* __restrict__ out)
{
    __shared__ float red[8][13 * 32];
    int tid = threadIdx.x;
    int cg = tid >> 5;
    int hwl = tid & 31;
    int hw = blockIdx.x * 32 + hwl;

    float acc[13];
    #pragma unroll
    for (int o = 0; o < 13; o++) acc[o] = 0.f;
    const float* __restrict__ d = g_dfm[0];
    int c0 = cg * 96;
    for (int c = c0; c < c0 + 96; c++) {
        float v = d[(size_t)c * HWSZ + hw];
        #pragma unroll
        for (int o = 0; o < 13; o++)
            acc[o] = fmaf(wcls[o * 768 + c], v, acc[o]);
    }
    #pragma unroll
    for (int o = 0; o < 13; o++) red[cg][o * 32 + hwl] = acc[o];
    __syncthreads();

    if (tid < 32) {
        #pragma unroll
        for (int o = 0; o < 13; o++) {
            float s = bcls[o];
            #pragma unroll
            for (int g = 0; g < 8; g++) s += red[g][o * 32 + tid];
            out[(size_t)o * HWSZ + blockIdx.x * 32 + tid] = s;
        }
    }
}

// ---------------------------------------------------------------------------
// Kernel 6: kpt + bbox heads + minmax bbox decode (fused).
// ---------------------------------------------------------------------------
__global__ void __launch_bounds__(256) k_head_pts(const float* __restrict__ wkpt,
                                                  const float* __restrict__ bkpt,
                                                  const float* __restrict__ wbb,
                                                  const float* __restrict__ bbb,
                                                  const float* __restrict__ kprev,
                                                  float* __restrict__ out)
{
    __shared__ float red[8][38 * 32];
    int tid = threadIdx.x;
    int cg = tid >> 5;
    int hwl = tid & 31;
    int hw = blockIdx.x * 32 + hwl;

    float acck[34], accb[4];
    #pragma unroll
    for (int o = 0; o < 34; o++) acck[o] = 0.f;
    #pragma unroll
    for (int o = 0; o < 4; o++)  accb[o] = 0.f;

    const float* __restrict__ dk = g_dfm[1];
    const float* __restrict__ db = g_dfm[2];
    int c0 = cg * 96;
    for (int c = c0; c < c0 + 96; c++) {
        float vk = dk[(size_t)c * HWSZ + hw];
        float vb = db[(size_t)c * HWSZ + hw];
        #pragma unroll
        for (int o = 0; o < 34; o++)
            acck[o] = fmaf(wkpt[o * 768 + c], vk, acck[o]);
        #pragma unroll
        for (int o = 0; o < 4; o++)
            accb[o] = fmaf(wbb[o * 768 + c], vb, accb[o]);
    }
    #pragma unroll
    for (int o = 0; o < 34; o++) red[cg][o * 32 + hwl] = acck[o];
    #pragma unroll
    for (int o = 0; o < 4; o++)  red[cg][(34 + o) * 32 + hwl] = accb[o];
    __syncthreads();

    if (tid < 32) {
        int hwg = blockIdx.x * 32 + tid;
        float k2[34], b2[4];
        #pragma unroll
        for (int o = 0; o < 34; o++) {
            float s = bkpt[o];
            #pragma unroll
            for (int g = 0; g < 8; g++) s += red[g][o * 32 + tid];
            s += kprev[(size_t)o * HWSZ + hwg];
            k2[o] = s;
            out[(size_t)(17 + o) * HWSZ + hwg] = s;
        }
        #pragma unroll
        for (int o = 0; o < 4; o++) {
            float s = bbb[o];
            #pragma unroll
            for (int g = 0; g < 8; g++) s += red[g][(34 + o) * 32 + tid];
            b2[o] = s;
        }

        float left = 1e30f, right = -1e30f, top = 1e30f, bot = -1e30f;
        #pragma unroll
        for (int i = 0; i < 17; i++) {
            float py = k2[2 * i];
            float px = k2[2 * i + 1];
            top   = fminf(top, py);   bot   = fmaxf(bot, py);
            left  = fminf(left, px);  right = fmaxf(right, px);
        }
        float cx = (left + right) * 0.5f;
        float cy = (top + bot) * 0.5f;
        float hwid = (cx - left) * expf(b2[0]);
        float hhei = (cy - top)  * expf(b2[1]);
        cx += b2[2];
        cy += b2[3];
        out[(size_t)(13 + 0) * HWSZ + hwg] = cx - hwid;
        out[(size_t)(13 + 1) * HWSZ + hwg] = cy - hhei;
        out[(size_t)(13 + 2) * HWSZ + hwg] = cx + hwid;
        out[(size_t)(13 + 3) * HWSZ + hwg] = cy + hhei;
    }
}

// ---------------------------------------------------------------------------
// Launch
// ---------------------------------------------------------------------------
extern "C" void kernel_launch(void* const* d_in, const int* in_sizes, int n_in,
                              void* d_out, int out_size)
{
    const float* cls_feat = (const float*)d_in[0];
    const float* pts_feat = (const float*)d_in[1];
    const float* kprev    = (const float*)d_in[2];
    const float* w_do     = (const float*)d_in[3];
    const float* b_do     = (const float*)d_in[4];
    const float* w_cls    = (const float*)d_in[14];
    const float* b_cls    = (const float*)d_in[15];
    const float* w_kpt    = (const float*)d_in[16];
    const float* b_kpt    = (const float*)d_in[17];
    const float* w_bbox   = (const float*)d_in[18];
    const float* b_bbox   = (const float*)d_in[19];
    float* out = (float*)d_out;

    // idempotent, immediate (not a stream op) — safe under graph capture
    cudaFuncSetAttribute(k_mma, cudaFuncAttributeMaxDynamicSharedMemorySize,
                         SMEM_DYN);

    k_corners<<<dim3(NPTS, HWSZ / 256), 256>>>(kprev, w_do, b_do);

    W9 ws;
    for (int i = 0; i < 9; i++) ws.p[i] = (const float*)d_in[5 + i];
    k_wt<<<dim3(256, 9), 256>>>(ws);

    k_ft<<<dim3(HWSZ / 32, 256 / 32, 2), dim3(32, 8)>>>(cls_feat, pts_feat);

    // 9 block-diagonal sub-GEMMs, M256 x N128 x K64, fp16 2-product pipeline
    k_mma<<<dim3(HWSZ / 128, 9), 512, SMEM_DYN>>>();

    k_head_cls<<<HWSZ / 32, 256>>>(w_cls, b_cls, out);
    k_head_pts<<<HWSZ / 32, 256>>>(w_kpt, b_kpt, w_bbox, b_bbox, kprev, out);
}

// round 11
// speedup vs baseline: 4.4663x; 1.2387x over previous
#include <cuda_runtime.h>
#include <cuda_fp16.h>
#include <math.h>
#include <stdint.h>

// ---------------------------------------------------------------------------
// Problem constants (B=1, C=256, H=W=64, FC=256, kernels 3/5/7 -> 83 points)
// ---------------------------------------------------------------------------
#define HWSZ 4096
#define NPTS 83
#define KTOT 21248         // 83*256 packed weight K layout

// ---------------------------------------------------------------------------
// Device scratch
// ---------------------------------------------------------------------------
__device__ __align__(16) int   g_cidx[NPTS * HWSZ * 4];
__device__ __align__(16) float g_cw  [NPTS * HWSZ * 4];
__device__ __half g_wa[3][(size_t)256 * KTOT];            // fp16 weights [m][k]
__device__ float g_ft[2][(size_t)HWSZ * 256];             // feat transposed [hw][c]
__device__ float g_dfm[3][(size_t)768 * HWSZ];            // relu(deform conv)

// ---------------------------------------------------------------------------
// helpers
// ---------------------------------------------------------------------------
__device__ __forceinline__ uint32_t smem_to_u32(const void* p) {
    uint32_t a;
    asm("{ .reg .u64 t; cvta.to.shared.u64 t, %1; cvt.u32.u64 %0, t; }"
        : "=r"(a) : "l"(p));
    return a;
}
// SW128 swizzle for 128-byte rows
#define SWZ(o) ((o) ^ (((o) >> 3) & 0x70))

__device__ __forceinline__ void ldsm4(uint32_t addr, uint32_t* r) {
    asm volatile("ldmatrix.sync.aligned.m8n8.x4.shared.b16 {%0,%1,%2,%3}, [%4];"
        : "=r"(r[0]), "=r"(r[1]), "=r"(r[2]), "=r"(r[3]) : "r"(addr));
}
__device__ __forceinline__ void mma16816(float* c, const uint32_t* a,
                                         uint32_t b0, uint32_t b1) {
    asm volatile(
        "mma.sync.aligned.m16n8k16.row.col.f32.f16.f16.f32 "
        "{%0,%1,%2,%3}, {%4,%5,%6,%7}, {%8,%9}, {%0,%1,%2,%3};"
        : "+f"(c[0]), "+f"(c[1]), "+f"(c[2]), "+f"(c[3])
        : "r"(a[0]), "r"(a[1]), "r"(a[2]), "r"(a[3]), "r"(b0), "r"(b1));
}
__device__ __forceinline__ void cpa16(uint32_t dst, const void* src) {
    asm volatile("cp.async.cg.shared.global [%0], [%1], 16;"
                 :: "r"(dst), "l"(src) : "memory");
}
#define CPA_COMMIT() asm volatile("cp.async.commit_group;" ::: "memory")
#define CPA_WAIT0()  asm volatile("cp.async.wait_group 0;" ::: "memory")
__device__ __forceinline__ void pref_l1(const void* p) {
    asm volatile("prefetch.global.L1 [%0];" :: "l"(p));
}

// per-stage smem: A 32KB | B 8KB = 40KB, x2 stages = 80KB (2 CTA/SM)
#define S_A 0
#define S_B 32768
#define STAGE 40960
#define SMEM_DYN (2 * STAGE)

// ---------------------------------------------------------------------------
// Kernel 1: fused offset 1x1 conv + bilinear corner table.
// ---------------------------------------------------------------------------
__global__ void k_corners(const float* __restrict__ kprev,
                          const float* __restrict__ w_do,
                          const float* __restrict__ b_do)
{
    int kk = blockIdx.x;
    int hw = blockIdx.y * 256 + threadIdx.x;
    int h = hw >> 6, w = hw & 63;

    int base, kkl;
    if (kk < 9)       { base = 0;  kkl = kk;      }
    else if (kk < 34) { base = 18; kkl = kk - 9;  }
    else              { base = 68; kkl = kk - 34; }
    int chy = base + 2 * kkl;
    int chx = chy + 1;

    float dy = b_do[chy], dx = b_do[chx];
    #pragma unroll 2
    for (int i = 0; i < 34; i++) {
        float v = kprev[i * HWSZ + hw];
        dy = fmaf(w_do[chy * 34 + i], v, dy);
        dx = fmaf(w_do[chx * 34 + i], v, dx);
    }

    float y = (float)h + dy;
    float x = (float)w + dx;
    float y0f = floorf(y), x0f = floorf(x);
    int y0 = (int)y0f, x0 = (int)x0f;
    float wy = y - y0f, wx = x - x0f;

    int   yi[4] = { y0, y0, y0 + 1, y0 + 1 };
    int   xi[4] = { x0, x0 + 1, x0, x0 + 1 };
    float wb[4] = { (1.f - wy) * (1.f - wx), (1.f - wy) * wx,
                    wy * (1.f - wx),         wy * wx };

    int o = (kk * HWSZ + hw) * 4;
    #pragma unroll
    for (int j = 0; j < 4; j++) {
        bool valid = (yi[j] >= 0) && (yi[j] < 64) && (xi[j] >= 0) && (xi[j] < 64);
        int yc = min(max(yi[j], 0), 63);
        int xc = min(max(xi[j], 0), 63);
        g_cidx[o + j] = yc * 64 + xc;
        g_cw  [o + j] = valid ? wb[j] : 0.0f;
    }
}

// ---------------------------------------------------------------------------
// Kernel 2: weight transpose to fp16 (division-free).
// ---------------------------------------------------------------------------
struct W9 { const float* p[9]; };

__global__ void k_wt(W9 ws)
{
    int sub = blockIdx.y;
    int branch = sub / 3;
    int ks = sub - branch * 3;
    int Kp    = (ks == 0) ? 9 : (ks == 1) ? 25 : 49;
    int kbase = (ks == 0) ? 0 : (ks == 1) ? 9  : 34;
    int o = blockIdx.x;
    int c = threadIdx.x;

    const float* src = ws.p[sub] + ((size_t)o * 256 + c) * Kp;
    __half* dh = g_wa[branch] + (size_t)o * KTOT + (size_t)kbase * 256 + c;

    for (int kkl = 0; kkl < Kp; kkl++)
        dh[(size_t)kkl * 256] = __float2half_rn(src[kkl]);
}

// ---------------------------------------------------------------------------
// Kernel 3: feature transpose [c][hw] -> [hw][c]
// ---------------------------------------------------------------------------
__global__ void k_ft(const float* __restrict__ f0, const float* __restrict__ f1)
{
    __shared__ float t[32][33];
    int f = blockIdx.z;
    const float* __restrict__ src = f ? f1 : f0;
    int hw0 = blockIdx.x * 32, c0 = blockIdx.y * 32;
    #pragma unroll
    for (int i = 0; i < 4; i++) {
        int c = c0 + threadIdx.y + i * 8;
        t[threadIdx.y + i * 8][threadIdx.x] = src[(size_t)c * HWSZ + hw0 + threadIdx.x];
    }
    __syncthreads();
    #pragma unroll
    for (int i = 0; i < 4; i++) {
        int hw = hw0 + threadIdx.y + i * 8;
        g_ft[f][(size_t)hw * 256 + c0 + threadIdx.x] = t[threadIdx.x][threadIdx.y + i * 8];
    }
}

// ---------------------------------------------------------------------------
// Kernel 4: pipelined fp16 HMMA GEMM with fused bilinear gather.
//   9 block-diagonal sub-GEMMs via blockIdx.y. Block M256 x N64 x K64,
//   256 threads = 8 warps (4M x 2N), warp tile 64x32, 2 CTA/SM overlap.
//   Double-buffered 2x40KB smem; A via cp.async, B gathered+fp16-rounded.
//   Single product per kstep (A fp16 rounding adds ~4e-5 rel err).
// ---------------------------------------------------------------------------
__global__ void __launch_bounds__(256, 2) k_mma()
{
    const int SUBMAP[9] = {2, 5, 8, 1, 4, 7, 0, 3, 6};  // heavy (k7) first
    const int P0_[3] = {0, 9, 34};
    const int NP_[3] = {9, 25, 49};

    extern __shared__ __align__(128) char smem[];
    uint32_t sb = smem_to_u32(smem);

    int tid = threadIdx.x;
    int wid = tid >> 5;
    int lid = tid & 31;

    int sub = SUBMAP[blockIdx.y];
    int branch = sub / 3;
    int ks = sub - branch * 3;
    int p0 = P0_[ks];
    int np = NP_[ks];

    int n0 = blockIdx.x * 64;
    const float* __restrict__ ft = g_ft[branch == 0 ? 0 : 1];
    const __half* __restrict__ Ah = g_wa[branch];
    float* __restrict__ Cp = g_dfm[branch] + (size_t)ks * 256 * HWSZ;

    int wm = wid >> 1;            // 0..3 -> m offset wm*64
    int wn = wid & 1;             // 0..1 -> n offset wn*32

    // gather mapping: 4 threads per B row (16 channels each)
    int n_l = tid >> 2;           // 0..63
    int qg  = tid & 3;
    int n_g = n0 + n_l;

    // ldmatrix lane address components (128B rows, SW128)
    uint32_t a_row = wm * 64 + ((lid >> 3) & 1) * 8 + (lid & 7);
    uint32_t a_byt = (lid >> 4) * 16;
    uint32_t b_row = wn * 32 + (lid & 7) + ((lid >> 4) & 1) * 8;
    uint32_t b_byt = ((lid >> 3) & 1) * 16;

    float acc[4][4][4];
    #pragma unroll
    for (int i = 0; i < 4; i++)
        #pragma unroll
        for (int j = 0; j < 4; j++)
            #pragma unroll
            for (int r = 0; r < 4; r++) acc[i][j][r] = 0.f;

    int4   id4;
    float4 wv4;
    int nchunk = np * 4;                  // 4 x K64 chunks per point

    auto fill_A = [&](int k0, uint32_t stage_base) {
        // 256 rows x 64 ch fp16 = 128B/row; one row per thread, 8 x 16B
        const __half* Asrc = Ah + (size_t)tid * KTOT + k0;
        uint32_t dbase = stage_base + S_A;
        #pragma unroll
        for (int j = 0; j < 8; j++)
            cpa16(dbase + SWZ((uint32_t)(tid * 128 + j * 16)), Asrc + j * 8);
    };
    auto gather_B = [&](int c0v, uint32_t stage_base) {
        int cb = c0v + qg * 16;
        const float* t0 = ft + (size_t)id4.x * 256 + cb;
        const float* t1 = ft + (size_t)id4.y * 256 + cb;
        const float* t2 = ft + (size_t)id4.z * 256 + cb;
        const float* t3 = ft + (size_t)id4.w * 256 + cb;
        char* bp = smem + (stage_base - sb) + S_B;
        #pragma unroll
        for (int qq = 0; qq < 4; qq++) {
            float4 a = *reinterpret_cast<const float4*>(t0 + qq * 4);
            float4 b = *reinterpret_cast<const float4*>(t1 + qq * 4);
            float4 c = *reinterpret_cast<const float4*>(t2 + qq * 4);
            float4 d = *reinterpret_cast<const float4*>(t3 + qq * 4);
            float v0 = wv4.x*a.x + wv4.y*b.x + wv4.z*c.x + wv4.w*d.x;
            float v1 = wv4.x*a.y + wv4.y*b.y + wv4.z*c.y + wv4.w*d.y;
            float v2 = wv4.x*a.z + wv4.y*b.z + wv4.z*c.z + wv4.w*d.z;
            float v3 = wv4.x*a.w + wv4.y*b.w + wv4.z*c.w + wv4.w*d.w;
            __half2 h01 = __floats2half2_rn(v0, v1);
            __half2 h23 = __floats2half2_rn(v2, v3);
            uint32_t bof = SWZ((uint32_t)(n_l * 128 + (qg * 16 + qq * 4) * 2));
            uint2 hv;
            hv.x = *reinterpret_cast<uint32_t*>(&h01);
            hv.y = *reinterpret_cast<uint32_t*>(&h23);
            *reinterpret_cast<uint2*>(bp + bof) = hv;
        }
    };

    // ---------------- prologue: stage 0 = chunk 0 ----------------
    {
        int o = (p0 * HWSZ + n_g) * 4;
        id4 = *reinterpret_cast<const int4*>(&g_cidx[o]);
        wv4 = *reinterpret_cast<const float4*>(&g_cw[o]);
        fill_A(p0 * 256, sb);
        CPA_COMMIT();
        gather_B(0, sb);
        CPA_WAIT0();
    }
    __syncthreads();

    for (int ch = 0; ch < nchunk; ch++) {
        uint32_t cur_base = sb + (ch & 1) * STAGE;
        uint32_t nxt_base = sb + ((ch + 1) & 1) * STAGE;
        bool has_next = (ch + 1) < nchunk;
        int gp1 = p0 + ((ch + 1) >> 2);
        int c01 = ((ch + 1) & 3) * 64;

        if (has_next) {
            if (((ch + 1) & 3) == 0) {           // next chunk starts new point
                int o = (gp1 * HWSZ + n_g) * 4;
                id4 = *reinterpret_cast<const int4*>(&g_cidx[o]);
                wv4 = *reinterpret_cast<const float4*>(&g_cw[o]);
            } else if (qg == 0) {                // prefetch next tap slices
                pref_l1(ft + (size_t)id4.x * 256 + c01);
                pref_l1(ft + (size_t)id4.x * 256 + c01 + 32);
                pref_l1(ft + (size_t)id4.y * 256 + c01);
                pref_l1(ft + (size_t)id4.y * 256 + c01 + 32);
                pref_l1(ft + (size_t)id4.z * 256 + c01);
                pref_l1(ft + (size_t)id4.z * 256 + c01 + 32);
                pref_l1(ft + (size_t)id4.w * 256 + c01);
                pref_l1(ft + (size_t)id4.w * 256 + c01 + 32);
            }
            fill_A(gp1 * 256 + c01, nxt_base);
            CPA_COMMIT();
        }

        // ---- math on current stage: 4 ksteps x 16 mma ----
        #pragma unroll
        for (int ks2 = 0; ks2 < 4; ks2++) {
            uint32_t kb = ks2 * 32;
            uint32_t ah[4][4], bh[2][4];
            #pragma unroll
            for (int mi = 0; mi < 4; mi++)
                ldsm4(cur_base + S_A + SWZ((a_row + mi * 16) * 128 + kb + a_byt), ah[mi]);
            #pragma unroll
            for (int bj = 0; bj < 2; bj++)
                ldsm4(cur_base + S_B + SWZ((b_row + bj * 16) * 128 + kb + b_byt), bh[bj]);
            #pragma unroll
            for (int mi = 0; mi < 4; mi++)
                #pragma unroll
                for (int nj = 0; nj < 4; nj++)
                    mma16816(acc[mi][nj], ah[mi], bh[nj >> 1][(nj & 1) * 2],
                             bh[nj >> 1][(nj & 1) * 2 + 1]);
        }

        if (has_next) {
            gather_B(c01, nxt_base);
            CPA_WAIT0();
        }
        __syncthreads();
    }

    // ---- epilogue: relu + store ----
    int l4 = lid >> 2;
    int l2 = (lid & 3) * 2;
    #pragma unroll
    for (int mi = 0; mi < 4; mi++) {
        #pragma unroll
        for (int nj = 0; nj < 4; nj++) {
            int m = wm * 64 + mi * 16 + l4;
            int n = n0 + wn * 32 + nj * 8 + l2;
            float2 v0, v1;
            v0.x = fmaxf(acc[mi][nj][0], 0.f);
            v0.y = fmaxf(acc[mi][nj][1], 0.f);
            v1.x = fmaxf(acc[mi][nj][2], 0.f);
            v1.y = fmaxf(acc[mi][nj][3], 0.f);
            *reinterpret_cast<float2*>(Cp + (size_t)m * HWSZ + n) = v0;
            *reinterpret_cast<float2*>(Cp + (size_t)(m + 8) * HWSZ + n) = v1;
        }
    }
}

// ---------------------------------------------------------------------------
// Kernel 5: cls head.
// ---------------------------------------------------------------------------
__global__ void __launch_bounds__(256) k_head_cls(const float* __restrict__ wcls,
                                                  const float* __restrict__ bcls,
                                                  float* __restrict__ out)
{
    __shared__ float red[8][13 * 32];
    int tid = threadIdx.x;
    int cg = tid >> 5;
    int hwl = tid & 31;
    int hw = blockIdx.x * 32 + hwl;

    float acc[13];
    #pragma unroll
    for (int o = 0; o < 13; o++) acc[o] = 0.f;
    const float* __restrict__ d = g_dfm[0];
    int c0 = cg * 96;
    for (int c = c0; c < c0 + 96; c++) {
        float v = d[(size_t)c * HWSZ + hw];
        #pragma unroll
        for (int o = 0; o < 13; o++)
            acc[o] = fmaf(wcls[o * 768 + c], v, acc[o]);
    }
    #pragma unroll
    for (int o = 0; o < 13; o++) red[cg][o * 32 + hwl] = acc[o];
    __syncthreads();

    if (tid < 32) {
        #pragma unroll
        for (int o = 0; o < 13; o++) {
            float s = bcls[o];
            #pragma unroll
            for (int g = 0; g < 8; g++) s += red[g][o * 32 + tid];
            out[(size_t)o * HWSZ + blockIdx.x * 32 + tid] = s;
        }
    }
}

// ---------------------------------------------------------------------------
// Kernel 6: kpt + bbox heads + minmax bbox decode (fused).
// ---------------------------------------------------------------------------
__global__ void __launch_bounds__(256) k_head_pts(const float* __restrict__ wkpt,
                                                  const float* __restrict__ bkpt,
                                                  const float* __restrict__ wbb,
                                                  const float* __restrict__ bbb,
                                                  const float* __restrict__ kprev,
                                                  float* __restrict__ out)
{
    __shared__ float red[8][38 * 32];
    int tid = threadIdx.x;
    int cg = tid >> 5;
    int hwl = tid & 31;
    int hw = blockIdx.x * 32 + hwl;

    float acck[34], accb[4];
    #pragma unroll
    for (int o = 0; o < 34; o++) acck[o] = 0.f;
    #pragma unroll
    for (int o = 0; o < 4; o++)  accb[o] = 0.f;

    const float* __restrict__ dk = g_dfm[1];
    const float* __restrict__ db = g_dfm[2];
    int c0 = cg * 96;
    for (int c = c0; c < c0 + 96; c++) {
        float vk = dk[(size_t)c * HWSZ + hw];
        float vb = db[(size_t)c * HWSZ + hw];
        #pragma unroll
        for (int o = 0; o < 34; o++)
            acck[o] = fmaf(wkpt[o * 768 + c], vk, acck[o]);
        #pragma unroll
        for (int o = 0; o < 4; o++)
            accb[o] = fmaf(wbb[o * 768 + c], vb, accb[o]);
    }
    #pragma unroll
    for (int o = 0; o < 34; o++) red[cg][o * 32 + hwl] = acck[o];
    #pragma unroll
    for (int o = 0; o < 4; o++)  red[cg][(34 + o) * 32 + hwl] = accb[o];
    __syncthreads();

    if (tid < 32) {
        int hwg = blockIdx.x * 32 + tid;
        float k2[34], b2[4];
        #pragma unroll
        for (int o = 0; o < 34; o++) {
            float s = bkpt[o];
            #pragma unroll
            for (int g = 0; g < 8; g++) s += red[g][o * 32 + tid];
            s += kprev[(size_t)o * HWSZ + hwg];
            k2[o] = s;
            out[(size_t)(17 + o) * HWSZ + hwg] = s;
        }
        #pragma unroll
        for (int o = 0; o < 4; o++) {
            float s = bbb[o];
            #pragma unroll
            for (int g = 0; g < 8; g++) s += red[g][(34 + o) * 32 + tid];
            b2[o] = s;
        }

        float left = 1e30f, right = -1e30f, top = 1e30f, bot = -1e30f;
        #pragma unroll
        for (int i = 0; i < 17; i++) {
            float py = k2[2 * i];
            float px = k2[2 * i + 1];
            top   = fminf(top, py);   bot   = fmaxf(bot, py);
            left  = fminf(left, px);  right = fmaxf(right, px);
        }
        float cx = (left + right) * 0.5f;
        float cy = (top + bot) * 0.5f;
        float hwid = (cx - left) * expf(b2[0]);
        float hhei = (cy - top)  * expf(b2[1]);
        cx += b2[2];
        cy += b2[3];
        out[(size_t)(13 + 0) * HWSZ + hwg] = cx - hwid;
        out[(size_t)(13 + 1) * HWSZ + hwg] = cy - hhei;
        out[(size_t)(13 + 2) * HWSZ + hwg] = cx + hwid;
        out[(size_t)(13 + 3) * HWSZ + hwg] = cy + hhei;
    }
}

// ---------------------------------------------------------------------------
// Launch
// ---------------------------------------------------------------------------
extern "C" void kernel_launch(void* const* d_in, const int* in_sizes, int n_in,
                              void* d_out, int out_size)
{
    const float* cls_feat = (const float*)d_in[0];
    const float* pts_feat = (const float*)d_in[1];
    const float* kprev    = (const float*)d_in[2];
    const float* w_do     = (const float*)d_in[3];
    const float* b_do     = (const float*)d_in[4];
    const float* w_cls    = (const float*)d_in[14];
    const float* b_cls    = (const float*)d_in[15];
    const float* w_kpt    = (const float*)d_in[16];
    const float* b_kpt    = (const float*)d_in[17];
    const float* w_bbox   = (const float*)d_in[18];
    const float* b_bbox   = (const float*)d_in[19];
    float* out = (float*)d_out;

    // idempotent, immediate (not a stream op) — safe under graph capture
    cudaFuncSetAttribute(k_mma, cudaFuncAttributeMaxDynamicSharedMemorySize,
                         SMEM_DYN);

    k_corners<<<dim3(NPTS, HWSZ / 256), 256>>>(kprev, w_do, b_do);

    W9 ws;
    for (int i = 0; i < 9; i++) ws.p[i] = (const float*)d_in[5 + i];
    k_wt<<<dim3(256, 9), 256>>>(ws);

    k_ft<<<dim3(HWSZ / 32, 256 / 32, 2), dim3(32, 8)>>>(cls_feat, pts_feat);

    // 9 block-diagonal sub-GEMMs, M256 x N64 x K64, fp16 single-product,
    // 2 CTA/SM for load/math overlap
    k_mma<<<dim3(HWSZ / 64, 9), 256, SMEM_DYN>>>();

    k_head_cls<<<HWSZ / 32, 256>>>(w_cls, b_cls, out);
    k_head_pts<<<HWSZ / 32, 256>>>(w_kpt, b_kpt, w_bbox, b_bbox, kprev, out);
}

// round 13
// speedup vs baseline: 4.5090x; 1.0096x over previous
#include <cuda_runtime.h>
#include <cuda_fp16.h>
#include <math.h>
#include <stdint.h>

// ---------------------------------------------------------------------------
// Problem constants (B=1, C=256, H=W=64, FC=256, kernels 3/5/7 -> 83 points)
// ---------------------------------------------------------------------------
#define HWSZ 4096
#define NPTS 83
#define KTOT 21248         // 83*256 packed weight K layout

// ---------------------------------------------------------------------------
// Device scratch  (g_s = 348MB fp16 sampled tensor; rest small)
// ---------------------------------------------------------------------------
__device__ __align__(16) int   g_cidx[NPTS * HWSZ * 4];
__device__ __align__(16) float g_cw  [NPTS * HWSZ * 4];
__device__ __half g_wa[3][(size_t)256 * KTOT];            // fp16 weights [m][k]
__device__ __half g_fth[2][(size_t)HWSZ * 256];           // fp16 feat [hw][c]
__device__ __half g_s[2][(size_t)NPTS * HWSZ * 256];      // sampled S [p][hw][c]
__device__ float g_dfm[3][(size_t)768 * HWSZ];            // relu(deform conv)

// ---------------------------------------------------------------------------
// helpers
// ---------------------------------------------------------------------------
__device__ __forceinline__ uint32_t smem_to_u32(const void* p) {
    uint32_t a;
    asm("{ .reg .u64 t; cvta.to.shared.u64 t, %1; cvt.u32.u64 %0, t; }"
        : "=r"(a) : "l"(p));
    return a;
}
#define SWZ(o) ((o) ^ (((o) >> 3) & 0x70))

__device__ __forceinline__ void ldsm4(uint32_t addr, uint32_t* r) {
    asm volatile("ldmatrix.sync.aligned.m8n8.x4.shared.b16 {%0,%1,%2,%3}, [%4];"
        : "=r"(r[0]), "=r"(r[1]), "=r"(r[2]), "=r"(r[3]) : "r"(addr));
}
__device__ __forceinline__ void mma16816f(float* c, const uint32_t* a,
                                          uint32_t b0, uint32_t b1) {
    asm volatile(
        "mma.sync.aligned.m16n8k16.row.col.f32.f16.f16.f32 "
        "{%0,%1,%2,%3}, {%4,%5,%6,%7}, {%8,%9}, {%0,%1,%2,%3};"
        : "+f"(c[0]), "+f"(c[1]), "+f"(c[2]), "+f"(c[3])
        : "r"(a[0]), "r"(a[1]), "r"(a[2]), "r"(a[3]), "r"(b0), "r"(b1));
}
__device__ __forceinline__ void cpa16(uint32_t dst, const void* src) {
    asm volatile("cp.async.cg.shared.global [%0], [%1], 16;"
                 :: "r"(dst), "l"(src) : "memory");
}
#define CPA_COMMIT() asm volatile("cp.async.commit_group;" ::: "memory")
#define CPA_WAIT0()  asm volatile("cp.async.wait_group 0;" ::: "memory")

// per-stage smem: A 32KB | B 8KB = 40KB, x2 stages = 80KB (2 CTA/SM)
#define S_A 0
#define S_B 32768
#define STAGE 40960
#define SMEM_DYN (2 * STAGE)

// ---------------------------------------------------------------------------
// Kernel 1: fused offset 1x1 conv + bilinear corner table.
// ---------------------------------------------------------------------------
__global__ void k_corners(const float* __restrict__ kprev,
                          const float* __restrict__ w_do,
                          const float* __restrict__ b_do)
{
    int kk = blockIdx.x;
    int hw = blockIdx.y * 256 + threadIdx.x;
    int h = hw >> 6, w = hw & 63;

    int base, kkl;
    if (kk < 9)       { base = 0;  kkl = kk;      }
    else if (kk < 34) { base = 18; kkl = kk - 9;  }
    else              { base = 68; kkl = kk - 34; }
    int chy = base + 2 * kkl;
    int chx = chy + 1;

    float dy = b_do[chy], dx = b_do[chx];
    #pragma unroll 2
    for (int i = 0; i < 34; i++) {
        float v = kprev[i * HWSZ + hw];
        dy = fmaf(w_do[chy * 34 + i], v, dy);
        dx = fmaf(w_do[chx * 34 + i], v, dx);
    }

    float y = (float)h + dy;
    float x = (float)w + dx;
    float y0f = floorf(y), x0f = floorf(x);
    int y0 = (int)y0f, x0 = (int)x0f;
    float wy = y - y0f, wx = x - x0f;

    int   yi[4] = { y0, y0, y0 + 1, y0 + 1 };
    int   xi[4] = { x0, x0 + 1, x0, x0 + 1 };
    float wb[4] = { (1.f - wy) * (1.f - wx), (1.f - wy) * wx,
                    wy * (1.f - wx),         wy * wx };

    int o = (kk * HWSZ + hw) * 4;
    #pragma unroll
    for (int j = 0; j < 4; j++) {
        bool valid = (yi[j] >= 0) && (yi[j] < 64) && (xi[j] >= 0) && (xi[j] < 64);
        int yc = min(max(yi[j], 0), 63);
        int xc = min(max(xi[j], 0), 63);
        g_cidx[o + j] = yc * 64 + xc;
        g_cw  [o + j] = valid ? wb[j] : 0.0f;
    }
}

// ---------------------------------------------------------------------------
// Kernel 2: weight transpose to fp16 (division-free).
// ---------------------------------------------------------------------------
struct W9 { const float* p[9]; };

__global__ void k_wt(W9 ws)
{
    int sub = blockIdx.y;
    int branch = sub / 3;
    int ks = sub - branch * 3;
    int Kp    = (ks == 0) ? 9 : (ks == 1) ? 25 : 49;
    int kbase = (ks == 0) ? 0 : (ks == 1) ? 9  : 34;
    int o = blockIdx.x;
    int c = threadIdx.x;

    const float* src = ws.p[sub] + ((size_t)o * 256 + c) * Kp;
    __half* dh = g_wa[branch] + (size_t)o * KTOT + (size_t)kbase * 256 + c;

    for (int kkl = 0; kkl < Kp; kkl++)
        dh[(size_t)kkl * 256] = __float2half_rn(src[kkl]);
}

// ---------------------------------------------------------------------------
// Kernel 3: feature transpose [c][hw] -> fp16 [hw][c]
// ---------------------------------------------------------------------------
__global__ void k_ft(const float* __restrict__ f0, const float* __restrict__ f1)
{
    __shared__ float t[32][33];
    int f = blockIdx.z;
    const float* __restrict__ src = f ? f1 : f0;
    int hw0 = blockIdx.x * 32, c0 = blockIdx.y * 32;
    #pragma unroll
    for (int i = 0; i < 4; i++) {
        int c = c0 + threadIdx.y + i * 8;
        t[threadIdx.y + i * 8][threadIdx.x] = src[(size_t)c * HWSZ + hw0 + threadIdx.x];
    }
    __syncthreads();
    #pragma unroll
    for (int i = 0; i < 4; i++) {
        int hw = hw0 + threadIdx.y + i * 8;
        g_fth[f][(size_t)hw * 256 + c0 + threadIdx.x] =
            __float2half_rn(t[threadIdx.x][threadIdx.y + i * 8]);
    }
}

// ---------------------------------------------------------------------------
// Kernel 4: build sampled tensor S[f][p][hw][c] fp16.
//   grid (64 hw-tiles, 83 points, 2 feats), 256 threads (4 per hw row).
//   Gather from L2-resident g_fth, stage in smem, coalesced 128B stores.
// ---------------------------------------------------------------------------
__global__ void __launch_bounds__(256, 2) k_sg()
{
    __shared__ __half sout[64 * 256];     // 32KB
    int tid = threadIdx.x;
    int p = blockIdx.y, f = blockIdx.z;
    int hw0 = blockIdx.x * 64;
    int l = tid >> 2, qg = tid & 3;
    int hw = hw0 + l;

    int o = (p * HWSZ + hw) * 4;
    int4   id4 = *reinterpret_cast<const int4*>(&g_cidx[o]);
    float4 wv4 = *reinterpret_cast<const float4*>(&g_cw[o]);
    const __half* __restrict__ F = g_fth[f];
    const __half* t0 = F + (size_t)id4.x * 256;
    const __half* t1 = F + (size_t)id4.y * 256;
    const __half* t2 = F + (size_t)id4.z * 256;
    const __half* t3 = F + (size_t)id4.w * 256;

    // two 32-channel halves of this thread's 64-ch segment
    #pragma unroll
    for (int h = 0; h < 2; h++) {
        int cb = qg * 64 + h * 32;
        uint4 tp0[4], tp1[4], tp2[4], tp3[4];
        #pragma unroll
        for (int j = 0; j < 4; j++) {
            tp0[j] = *reinterpret_cast<const uint4*>(t0 + cb + j * 8);
            tp1[j] = *reinterpret_cast<const uint4*>(t1 + cb + j * 8);
            tp2[j] = *reinterpret_cast<const uint4*>(t2 + cb + j * 8);
            tp3[j] = *reinterpret_cast<const uint4*>(t3 + cb + j * 8);
        }
        #pragma unroll
        for (int j = 0; j < 4; j++) {
            const __half2* a2 = reinterpret_cast<const __half2*>(&tp0[j]);
            const __half2* b2 = reinterpret_cast<const __half2*>(&tp1[j]);
            const __half2* c2 = reinterpret_cast<const __half2*>(&tp2[j]);
            const __half2* d2 = reinterpret_cast<const __half2*>(&tp3[j]);
            uint4 outv;
            uint32_t* op = reinterpret_cast<uint32_t*>(&outv);
            #pragma unroll
            for (int k = 0; k < 4; k++) {
                float2 a = __half22float2(a2[k]);
                float2 b = __half22float2(b2[k]);
                float2 c = __half22float2(c2[k]);
                float2 d = __half22float2(d2[k]);
                float vx = wv4.x*a.x + wv4.y*b.x + wv4.z*c.x + wv4.w*d.x;
                float vy = wv4.x*a.y + wv4.y*b.y + wv4.z*c.y + wv4.w*d.y;
                __half2 hv = __floats2half2_rn(vx, vy);
                op[k] = *reinterpret_cast<uint32_t*>(&hv);
            }
            *reinterpret_cast<uint4*>(&sout[l * 256 + cb + j * 8]) = outv;
        }
    }
    __syncthreads();

    // coalesced copy smem -> g_s
    const uint4* s4 = reinterpret_cast<const uint4*>(sout);
    uint4* d4 = reinterpret_cast<uint4*>(g_s[f] + ((size_t)p * HWSZ + hw0) * 256);
    #pragma unroll
    for (int i = 0; i < 8; i++)
        d4[tid + i * 256] = s4[tid + i * 256];
}

// ---------------------------------------------------------------------------
// Kernel 5: pure cp.async fp16 HMMA GEMM (double-buffered).
//   9 block-diagonal sub-GEMMs via blockIdx.y. Block M256 x N64 x K64,
//   256 threads = 8 warps (4M x 2N), 2 CTA/SM. Both A and B via cp.async.
// ---------------------------------------------------------------------------
__global__ void __launch_bounds__(256, 2) k_mma()
{
    const int SUBMAP[9] = {2, 5, 8, 1, 4, 7, 0, 3, 6};  // heavy (k7) first
    const int P0_[3] = {0, 9, 34};
    const int NP_[3] = {9, 25, 49};

    extern __shared__ __align__(128) char smem[];
    uint32_t sb = smem_to_u32(smem);

    int tid = threadIdx.x;
    int wid = tid >> 5;
    int lid = tid & 31;

    int sub = SUBMAP[blockIdx.y];
    int branch = sub / 3;
    int ks = sub - branch * 3;
    int p0 = P0_[ks];
    int np = NP_[ks];

    int n0 = blockIdx.x * 64;
    const __half* __restrict__ Sf = g_s[branch == 0 ? 0 : 1];
    const __half* __restrict__ Ah = g_wa[branch];
    float* __restrict__ Cp = g_dfm[branch] + (size_t)ks * 256 * HWSZ;

    int wm = wid >> 1;
    int wn = wid & 1;

    // B fill mapping: 4 threads per row, 32B each
    int b_rowt = tid >> 2;
    int b_qg   = tid & 3;

    uint32_t a_row = wm * 64 + ((lid >> 3) & 1) * 8 + (lid & 7);
    uint32_t a_byt = (lid >> 4) * 16;
    uint32_t b_row = wn * 32 + (lid & 7) + ((lid >> 4) & 1) * 8;
    uint32_t b_byt = ((lid >> 3) & 1) * 16;

    float acc[4][4][4];
    #pragma unroll
    for (int i = 0; i < 4; i++)
        #pragma unroll
        for (int j = 0; j < 4; j++)
            #pragma unroll
            for (int r = 0; r < 4; r++) acc[i][j][r] = 0.f;

    int nchunk = np * 4;

    auto fill = [&](int gp, int c0v, uint32_t stage_base) {
        // B: 64 rows x 128B from S[(gp*HWSZ + n0+row)*256 + c0v]
        {
            const __half* src = Sf + ((size_t)gp * HWSZ + n0 + b_rowt) * 256
                                   + c0v + b_qg * 16;
            uint32_t d = stage_base + S_B;
            cpa16(d + SWZ((uint32_t)(b_rowt * 128 + b_qg * 32)), src);
            cpa16(d + SWZ((uint32_t)(b_rowt * 128 + b_qg * 32 + 16)), src + 8);
        }
        // A: 256 rows x 128B, one row per thread
        {
            const __half* Asrc = Ah + (size_t)tid * KTOT + gp * 256 + c0v;
            uint32_t d = stage_base + S_A;
            #pragma unroll
            for (int j = 0; j < 8; j++)
                cpa16(d + SWZ((uint32_t)(tid * 128 + j * 16)), Asrc + j * 8);
        }
    };

    // prologue
    fill(p0, 0, sb);
    CPA_COMMIT();
    CPA_WAIT0();
    __syncthreads();

    for (int ch = 0; ch < nchunk; ch++) {
        uint32_t cur_base = sb + (ch & 1) * STAGE;
        uint32_t nxt_base = sb + ((ch + 1) & 1) * STAGE;
        bool has_next = (ch + 1) < nchunk;

        if (has_next) {
            int gp1 = p0 + ((ch + 1) >> 2);
            int c01 = ((ch + 1) & 3) * 64;
            fill(gp1, c01, nxt_base);
            CPA_COMMIT();
        }

        // math on current stage: 4 ksteps x 16 mma
        #pragma unroll
        for (int ks2 = 0; ks2 < 4; ks2++) {
            uint32_t kb = ks2 * 32;
            uint32_t ah[4][4], bh[2][4];
            #pragma unroll
            for (int mi = 0; mi < 4; mi++)
                ldsm4(cur_base + S_A + SWZ((a_row + mi * 16) * 128 + kb + a_byt), ah[mi]);
            #pragma unroll
            for (int bj = 0; bj < 2; bj++)
                ldsm4(cur_base + S_B + SWZ((b_row + bj * 16) * 128 + kb + b_byt), bh[bj]);
            #pragma unroll
            for (int mi = 0; mi < 4; mi++)
                #pragma unroll
                for (int nj = 0; nj < 4; nj++)
                    mma16816f(acc[mi][nj], ah[mi], bh[nj >> 1][(nj & 1) * 2],
                              bh[nj >> 1][(nj & 1) * 2 + 1]);
        }

        if (has_next) CPA_WAIT0();
        __syncthreads();
    }

    // epilogue: relu + store
    int l4 = lid >> 2;
    int l2 = (lid & 3) * 2;
    #pragma unroll
    for (int mi = 0; mi < 4; mi++) {
        #pragma unroll
        for (int nj = 0; nj < 4; nj++) {
            int m = wm * 64 + mi * 16 + l4;
            int n = n0 + wn * 32 + nj * 8 + l2;
            float2 v0, v1;
            v0.x = fmaxf(acc[mi][nj][0], 0.f);
            v0.y = fmaxf(acc[mi][nj][1], 0.f);
            v1.x = fmaxf(acc[mi][nj][2], 0.f);
            v1.y = fmaxf(acc[mi][nj][3], 0.f);
            *reinterpret_cast<float2*>(Cp + (size_t)m * HWSZ + n) = v0;
            *reinterpret_cast<float2*>(Cp + (size_t)(m + 8) * HWSZ + n) = v1;
        }
    }
}

// ---------------------------------------------------------------------------
// Kernel 6: cls head.
// ---------------------------------------------------------------------------
__global__ void __launch_bounds__(256) k_head_cls(const float* __restrict__ wcls,
                                                  const float* __restrict__ bcls,
                                                  float* __restrict__ out)
{
    __shared__ float red[8][13 * 32];
    int tid = threadIdx.x;
    int cg = tid >> 5;
    int hwl = tid & 31;
    int hw = blockIdx.x * 32 + hwl;

    float acc[13];
    #pragma unroll
    for (int o = 0; o < 13; o++) acc[o] = 0.f;
    const float* __restrict__ d = g_dfm[0];
    int c0 = cg * 96;
    for (int c = c0; c < c0 + 96; c++) {
        float v = d[(size_t)c * HWSZ + hw];
        #pragma unroll
        for (int o = 0; o < 13; o++)
            acc[o] = fmaf(wcls[o * 768 + c], v, acc[o]);
    }
    #pragma unroll
    for (int o = 0; o < 13; o++) red[cg][o * 32 + hwl] = acc[o];
    __syncthreads();

    if (tid < 32) {
        #pragma unroll
        for (int o = 0; o < 13; o++) {
            float s = bcls[o];
            #pragma unroll
            for (int g = 0; g < 8; g++) s += red[g][o * 32 + tid];
            out[(size_t)o * HWSZ + blockIdx.x * 32 + tid] = s;
        }
    }
}

// ---------------------------------------------------------------------------
// Kernel 7: kpt + bbox heads + minmax bbox decode (fused).
// ---------------------------------------------------------------------------
__global__ void __launch_bounds__(256) k_head_pts(const float* __restrict__ wkpt,
                                                  const float* __restrict__ bkpt,
                                                  const float* __restrict__ wbb,
                                                  const float* __restrict__ bbb,
                                                  const float* __restrict__ kprev,
                                                  float* __restrict__ out)
{
    __shared__ float red[8][38 * 32];
    int tid = threadIdx.x;
    int cg = tid >> 5;
    int hwl = tid & 31;
    int hw = blockIdx.x * 32 + hwl;

    float acck[34], accb[4];
    #pragma unroll
    for (int o = 0; o < 34; o++) acck[o] = 0.f;
    #pragma unroll
    for (int o = 0; o < 4; o++)  accb[o] = 0.f;

    const float* __restrict__ dk = g_dfm[1];
    const float* __restrict__ db = g_dfm[2];
    int c0 = cg * 96;
    for (int c = c0; c < c0 + 96; c++) {
        float vk = dk[(size_t)c * HWSZ + hw];
        float vb = db[(size_t)c * HWSZ + hw];
        #pragma unroll
        for (int o = 0; o < 34; o++)
            acck[o] = fmaf(wkpt[o * 768 + c], vk, acck[o]);
        #pragma unroll
        for (int o = 0; o < 4; o++)
            accb[o] = fmaf(wbb[o * 768 + c], vb, accb[o]);
    }
    #pragma unroll
    for (int o = 0; o < 34; o++) red[cg][o * 32 + hwl] = acck[o];
    #pragma unroll
    for (int o = 0; o < 4; o++)  red[cg][(34 + o) * 32 + hwl] = accb[o];
    __syncthreads();

    if (tid < 32) {
        int hwg = blockIdx.x * 32 + tid;
        float k2[34], b2[4];
        #pragma unroll
        for (int o = 0; o < 34; o++) {
            float s = bkpt[o];
            #pragma unroll
            for (int g = 0; g < 8; g++) s += red[g][o * 32 + tid];
            s += kprev[(size_t)o * HWSZ + hwg];
            k2[o] = s;
            out[(size_t)(17 + o) * HWSZ + hwg] = s;
        }
        #pragma unroll
        for (int o = 0; o < 4; o++) {
            float s = bbb[o];
            #pragma unroll
            for (int g = 0; g < 8; g++) s += red[g][(34 + o) * 32 + tid];
            b2[o] = s;
        }

        float left = 1e30f, right = -1e30f, top = 1e30f, bot = -1e30f;
        #pragma unroll
        for (int i = 0; i < 17; i++) {
            float py = k2[2 * i];
            float px = k2[2 * i + 1];
            top   = fminf(top, py);   bot   = fmaxf(bot, py);
            left  = fminf(left, px);  right = fmaxf(right, px);
        }
        float cx = (left + right) * 0.5f;
        float cy = (top + bot) * 0.5f;
        float hwid = (cx - left) * expf(b2[0]);
        float hhei = (cy - top)  * expf(b2[1]);
        cx += b2[2];
        cy += b2[3];
        out[(size_t)(13 + 0) * HWSZ + hwg] = cx - hwid;
        out[(size_t)(13 + 1) * HWSZ + hwg] = cy - hhei;
        out[(size_t)(13 + 2) * HWSZ + hwg] = cx + hwid;
        out[(size_t)(13 + 3) * HWSZ + hwg] = cy + hhei;
    }
}

// ---------------------------------------------------------------------------
// Launch
// ---------------------------------------------------------------------------
extern "C" void kernel_launch(void* const* d_in, const int* in_sizes, int n_in,
                              void* d_out, int out_size)
{
    const float* cls_feat = (const float*)d_in[0];
    const float* pts_feat = (const float*)d_in[1];
    const float* kprev    = (const float*)d_in[2];
    const float* w_do     = (const float*)d_in[3];
    const float* b_do     = (const float*)d_in[4];
    const float* w_cls    = (const float*)d_in[14];
    const float* b_cls    = (const float*)d_in[15];
    const float* w_kpt    = (const float*)d_in[16];
    const float* b_kpt    = (const float*)d_in[17];
    const float* w_bbox   = (const float*)d_in[18];
    const float* b_bbox   = (const float*)d_in[19];
    float* out = (float*)d_out;

    cudaFuncSetAttribute(k_mma, cudaFuncAttributeMaxDynamicSharedMemorySize,
                         SMEM_DYN);

    k_corners<<<dim3(NPTS, HWSZ / 256), 256>>>(kprev, w_do, b_do);

    W9 ws;
    for (int i = 0; i < 9; i++) ws.p[i] = (const float*)d_in[5 + i];
    k_wt<<<dim3(256, 9), 256>>>(ws);

    k_ft<<<dim3(HWSZ / 32, 256 / 32, 2), dim3(32, 8)>>>(cls_feat, pts_feat);

    // materialize sampled tensor S (fp16)
    k_sg<<<dim3(HWSZ / 64, NPTS, 2), 256>>>();

    // 9 block-diagonal sub-GEMMs, pure cp.async fp16 GEMM
    k_mma<<<dim3(HWSZ / 64, 9), 256, SMEM_DYN>>>();

    k_head_cls<<<HWSZ / 32, 256>>>(w_cls, b_cls, out);
    k_head_pts<<<HWSZ / 32, 256>>>(w_kpt, b_kpt, w_bbox, b_bbox, kprev, out);
}

// round 14
// speedup vs baseline: 5.7369x; 1.2723x over previous
#include <cuda_runtime.h>
#include <cuda_fp16.h>
#include <math.h>
#include <stdint.h>

// ---------------------------------------------------------------------------
// Problem constants (B=1, C=256, H=W=64, FC=256, kernels 3/5/7 -> 83 points)
// ---------------------------------------------------------------------------
#define HWSZ 4096
#define NPTS 83
#define KTOT 21248         // 83*256 packed weight K layout

// ---------------------------------------------------------------------------
// Device scratch  (g_s = 348MB fp16 sampled tensor; rest small)
// ---------------------------------------------------------------------------
__device__ __align__(16) int   g_cidx[NPTS * HWSZ * 4];
__device__ __align__(16) float g_cw  [NPTS * HWSZ * 4];
__device__ __half g_wa[3][(size_t)256 * KTOT];            // fp16 weights [m][k]
__device__ __half g_fth[2][(size_t)HWSZ * 256];           // fp16 feat [hw][c]
__device__ __half g_s[2][(size_t)NPTS * HWSZ * 256];      // sampled S [p][hw][c]
__device__ float g_dfm[3][(size_t)768 * HWSZ];            // relu(deform conv)

// ---------------------------------------------------------------------------
// helpers
// ---------------------------------------------------------------------------
__device__ __forceinline__ uint32_t smem_to_u32(const void* p) {
    uint32_t a;
    asm("{ .reg .u64 t; cvta.to.shared.u64 t, %1; cvt.u32.u64 %0, t; }"
        : "=r"(a) : "l"(p));
    return a;
}
#define SWZ(o) ((o) ^ (((o) >> 3) & 0x70))

__device__ __forceinline__ void ldsm4(uint32_t addr, uint32_t* r) {
    asm volatile("ldmatrix.sync.aligned.m8n8.x4.shared.b16 {%0,%1,%2,%3}, [%4];"
        : "=r"(r[0]), "=r"(r[1]), "=r"(r[2]), "=r"(r[3]) : "r"(addr));
}
__device__ __forceinline__ void mma16816f(float* c, const uint32_t* a,
                                          uint32_t b0, uint32_t b1) {
    asm volatile(
        "mma.sync.aligned.m16n8k16.row.col.f32.f16.f16.f32 "
        "{%0,%1,%2,%3}, {%4,%5,%6,%7}, {%8,%9}, {%0,%1,%2,%3};"
        : "+f"(c[0]), "+f"(c[1]), "+f"(c[2]), "+f"(c[3])
        : "r"(a[0]), "r"(a[1]), "r"(a[2]), "r"(a[3]), "r"(b0), "r"(b1));
}
__device__ __forceinline__ void cpa16(uint32_t dst, const void* src) {
    asm volatile("cp.async.cg.shared.global [%0], [%1], 16;"
                 :: "r"(dst), "l"(src) : "memory");
}
#define CPA_COMMIT() asm volatile("cp.async.commit_group;" ::: "memory")
#define CPA_WAIT0()  asm volatile("cp.async.wait_group 0;" ::: "memory")

// per-stage smem: A 32KB | B 8KB = 40KB, x2 stages = 80KB (2 CTA/SM)
#define S_A 0
#define S_B 32768
#define STAGE 40960
#define SMEM_DYN (2 * STAGE)

// ---------------------------------------------------------------------------
// Kernel 1: fused offset 1x1 conv + bilinear corner table.
// ---------------------------------------------------------------------------
__global__ void k_corners(const float* __restrict__ kprev,
                          const float* __restrict__ w_do,
                          const float* __restrict__ b_do)
{
    int kk = blockIdx.x;
    int hw = blockIdx.y * 256 + threadIdx.x;
    int h = hw >> 6, w = hw & 63;

    int base, kkl;
    if (kk < 9)       { base = 0;  kkl = kk;      }
    else if (kk < 34) { base = 18; kkl = kk - 9;  }
    else              { base = 68; kkl = kk - 34; }
    int chy = base + 2 * kkl;
    int chx = chy + 1;

    float dy = b_do[chy], dx = b_do[chx];
    #pragma unroll 2
    for (int i = 0; i < 34; i++) {
        float v = kprev[i * HWSZ + hw];
        dy = fmaf(w_do[chy * 34 + i], v, dy);
        dx = fmaf(w_do[chx * 34 + i], v, dx);
    }

    float y = (float)h + dy;
    float x = (float)w + dx;
    float y0f = floorf(y), x0f = floorf(x);
    int y0 = (int)y0f, x0 = (int)x0f;
    float wy = y - y0f, wx = x - x0f;

    int   yi[4] = { y0, y0, y0 + 1, y0 + 1 };
    int   xi[4] = { x0, x0 + 1, x0, x0 + 1 };
    float wb[4] = { (1.f - wy) * (1.f - wx), (1.f - wy) * wx,
                    wy * (1.f - wx),         wy * wx };

    int o = (kk * HWSZ + hw) * 4;
    #pragma unroll
    for (int j = 0; j < 4; j++) {
        bool valid = (yi[j] >= 0) && (yi[j] < 64) && (xi[j] >= 0) && (xi[j] < 64);
        int yc = min(max(yi[j], 0), 63);
        int xc = min(max(xi[j], 0), 63);
        g_cidx[o + j] = yc * 64 + xc;
        g_cw  [o + j] = valid ? wb[j] : 0.0f;
    }
}

// ---------------------------------------------------------------------------
// Kernel 2: weight transpose to fp16 (division-free).
// ---------------------------------------------------------------------------
struct W9 { const float* p[9]; };

__global__ void k_wt(W9 ws)
{
    int sub = blockIdx.y;
    int branch = sub / 3;
    int ks = sub - branch * 3;
    int Kp    = (ks == 0) ? 9 : (ks == 1) ? 25 : 49;
    int kbase = (ks == 0) ? 0 : (ks == 1) ? 9  : 34;
    int o = blockIdx.x;
    int c = threadIdx.x;

    const float* src = ws.p[sub] + ((size_t)o * 256 + c) * Kp;
    __half* dh = g_wa[branch] + (size_t)o * KTOT + (size_t)kbase * 256 + c;

    for (int kkl = 0; kkl < Kp; kkl++)
        dh[(size_t)kkl * 256] = __float2half_rn(src[kkl]);
}

// ---------------------------------------------------------------------------
// Kernel 3: feature transpose [c][hw] -> fp16 [hw][c]
// ---------------------------------------------------------------------------
__global__ void k_ft(const float* __restrict__ f0, const float* __restrict__ f1)
{
    __shared__ float t[32][33];
    int f = blockIdx.z;
    const float* __restrict__ src = f ? f1 : f0;
    int hw0 = blockIdx.x * 32, c0 = blockIdx.y * 32;
    #pragma unroll
    for (int i = 0; i < 4; i++) {
        int c = c0 + threadIdx.y + i * 8;
        t[threadIdx.y + i * 8][threadIdx.x] = src[(size_t)c * HWSZ + hw0 + threadIdx.x];
    }
    __syncthreads();
    #pragma unroll
    for (int i = 0; i < 4; i++) {
        int hw = hw0 + threadIdx.y + i * 8;
        g_fth[f][(size_t)hw * 256 + c0 + threadIdx.x] =
            __float2half_rn(t[threadIdx.x][threadIdx.y + i * 8]);
    }
}

// ---------------------------------------------------------------------------
// Kernel 4: build sampled tensor S[f][p][hw][c] fp16 — WARP-PER-ROW.
//   grid (NPTS*128, 2): block = 256 thr = 8 warps; each warp does 4 rows.
//   Per row: 4 coalesced 512B tap reads (lane = 8 channels), fma, 512B store.
// ---------------------------------------------------------------------------
__global__ void __launch_bounds__(256) k_sg()
{
    int tid  = threadIdx.x;
    int wid  = tid >> 5;
    int lane = tid & 31;
    int bx = blockIdx.x;
    int p   = bx >> 7;              // 0..82
    int hw0 = (bx & 127) * 32;      // 32 rows per block
    int f = blockIdx.y;

    const __half* __restrict__ F = g_fth[f];
    __half* __restrict__ Sp = g_s[f] + ((size_t)p * HWSZ + hw0) * 256;

    #pragma unroll
    for (int i = 0; i < 4; i++) {
        int hwl = wid * 4 + i;          // 0..31 local row
        int hw = hw0 + hwl;
        int o = (p * HWSZ + hw) * 4;    // warp-uniform -> broadcast loads
        int4   id4 = *reinterpret_cast<const int4*>(&g_cidx[o]);
        float4 wv4 = *reinterpret_cast<const float4*>(&g_cw[o]);

        uint4 v0 = *reinterpret_cast<const uint4*>(F + (size_t)id4.x * 256 + lane * 8);
        uint4 v1 = *reinterpret_cast<const uint4*>(F + (size_t)id4.y * 256 + lane * 8);
        uint4 v2 = *reinterpret_cast<const uint4*>(F + (size_t)id4.z * 256 + lane * 8);
        uint4 v3 = *reinterpret_cast<const uint4*>(F + (size_t)id4.w * 256 + lane * 8);

        const __half2* a2 = reinterpret_cast<const __half2*>(&v0);
        const __half2* b2 = reinterpret_cast<const __half2*>(&v1);
        const __half2* c2 = reinterpret_cast<const __half2*>(&v2);
        const __half2* d2 = reinterpret_cast<const __half2*>(&v3);

        uint4 outv;
        uint32_t* op = reinterpret_cast<uint32_t*>(&outv);
        #pragma unroll
        for (int k = 0; k < 4; k++) {
            float2 a = __half22float2(a2[k]);
            float2 b = __half22float2(b2[k]);
            float2 c = __half22float2(c2[k]);
            float2 d = __half22float2(d2[k]);
            float vx = wv4.x*a.x + wv4.y*b.x + wv4.z*c.x + wv4.w*d.x;
            float vy = wv4.x*a.y + wv4.y*b.y + wv4.z*c.y + wv4.w*d.y;
            __half2 hv = __floats2half2_rn(vx, vy);
            op[k] = *reinterpret_cast<uint32_t*>(&hv);
        }
        *reinterpret_cast<uint4*>(Sp + (size_t)hwl * 256 + lane * 8) = outv;
    }
}

// ---------------------------------------------------------------------------
// Kernel 5: pure cp.async fp16 HMMA GEMM (double-buffered).
//   9 block-diagonal sub-GEMMs via blockIdx.y. Block M256 x N64 x K64,
//   256 threads = 8 warps (4M x 2N), 2 CTA/SM. Both A and B via cp.async.
// ---------------------------------------------------------------------------
__global__ void __launch_bounds__(256, 2) k_mma()
{
    const int SUBMAP[9] = {2, 5, 8, 1, 4, 7, 0, 3, 6};  // heavy (k7) first
    const int P0_[3] = {0, 9, 34};
    const int NP_[3] = {9, 25, 49};

    extern __shared__ __align__(128) char smem[];
    uint32_t sb = smem_to_u32(smem);

    int tid = threadIdx.x;
    int wid = tid >> 5;
    int lid = tid & 31;

    int sub = SUBMAP[blockIdx.y];
    int branch = sub / 3;
    int ks = sub - branch * 3;
    int p0 = P0_[ks];
    int np = NP_[ks];

    int n0 = blockIdx.x * 64;
    const __half* __restrict__ Sf = g_s[branch == 0 ? 0 : 1];
    const __half* __restrict__ Ah = g_wa[branch];
    float* __restrict__ Cp = g_dfm[branch] + (size_t)ks * 256 * HWSZ;

    int wm = wid >> 1;
    int wn = wid & 1;

    // B fill mapping: 4 threads per row, 32B each
    int b_rowt = tid >> 2;
    int b_qg   = tid & 3;

    uint32_t a_row = wm * 64 + ((lid >> 3) & 1) * 8 + (lid & 7);
    uint32_t a_byt = (lid >> 4) * 16;
    uint32_t b_row = wn * 32 + (lid & 7) + ((lid >> 4) & 1) * 8;
    uint32_t b_byt = ((lid >> 3) & 1) * 16;

    float acc[4][4][4];
    #pragma unroll
    for (int i = 0; i < 4; i++)
        #pragma unroll
        for (int j = 0; j < 4; j++)
            #pragma unroll
            for (int r = 0; r < 4; r++) acc[i][j][r] = 0.f;

    int nchunk = np * 4;

    auto fill = [&](int gp, int c0v, uint32_t stage_base) {
        // B: 64 rows x 128B from S[(gp*HWSZ + n0+row)*256 + c0v]
        {
            const __half* src = Sf + ((size_t)gp * HWSZ + n0 + b_rowt) * 256
                                   + c0v + b_qg * 16;
            uint32_t d = stage_base + S_B;
            cpa16(d + SWZ((uint32_t)(b_rowt * 128 + b_qg * 32)), src);
            cpa16(d + SWZ((uint32_t)(b_rowt * 128 + b_qg * 32 + 16)), src + 8);
        }
        // A: 256 rows x 128B, one row per thread
        {
            const __half* Asrc = Ah + (size_t)tid * KTOT + gp * 256 + c0v;
            uint32_t d = stage_base + S_A;
            #pragma unroll
            for (int j = 0; j < 8; j++)
                cpa16(d + SWZ((uint32_t)(tid * 128 + j * 16)), Asrc + j * 8);
        }
    };

    // prologue
    fill(p0, 0, sb);
    CPA_COMMIT();
    CPA_WAIT0();
    __syncthreads();

    for (int ch = 0; ch < nchunk; ch++) {
        uint32_t cur_base = sb + (ch & 1) * STAGE;
        uint32_t nxt_base = sb + ((ch + 1) & 1) * STAGE;
        bool has_next = (ch + 1) < nchunk;

        if (has_next) {
            int gp1 = p0 + ((ch + 1) >> 2);
            int c01 = ((ch + 1) & 3) * 64;
            fill(gp1, c01, nxt_base);
            CPA_COMMIT();
        }

        // math on current stage: 4 ksteps x 16 mma
        #pragma unroll
        for (int ks2 = 0; ks2 < 4; ks2++) {
            uint32_t kb = ks2 * 32;
            uint32_t ah[4][4], bh[2][4];
            #pragma unroll
            for (int mi = 0; mi < 4; mi++)
                ldsm4(cur_base + S_A + SWZ((a_row + mi * 16) * 128 + kb + a_byt), ah[mi]);
            #pragma unroll
            for (int bj = 0; bj < 2; bj++)
                ldsm4(cur_base + S_B + SWZ((b_row + bj * 16) * 128 + kb + b_byt), bh[bj]);
            #pragma unroll
            for (int mi = 0; mi < 4; mi++)
                #pragma unroll
                for (int nj = 0; nj < 4; nj++)
                    mma16816f(acc[mi][nj], ah[mi], bh[nj >> 1][(nj & 1) * 2],
                              bh[nj >> 1][(nj & 1) * 2 + 1]);
        }

        if (has_next) CPA_WAIT0();
        __syncthreads();
    }

    // epilogue: relu + store
    int l4 = lid >> 2;
    int l2 = (lid & 3) * 2;
    #pragma unroll
    for (int mi = 0; mi < 4; mi++) {
        #pragma unroll
        for (int nj = 0; nj < 4; nj++) {
            int m = wm * 64 + mi * 16 + l4;
            int n = n0 + wn * 32 + nj * 8 + l2;
            float2 v0, v1;
            v0.x = fmaxf(acc[mi][nj][0], 0.f);
            v0.y = fmaxf(acc[mi][nj][1], 0.f);
            v1.x = fmaxf(acc[mi][nj][2], 0.f);
            v1.y = fmaxf(acc[mi][nj][3], 0.f);
            *reinterpret_cast<float2*>(Cp + (size_t)m * HWSZ + n) = v0;
            *reinterpret_cast<float2*>(Cp + (size_t)(m + 8) * HWSZ + n) = v1;
        }
    }
}

// ---------------------------------------------------------------------------
// Kernel 6: cls head.
// ---------------------------------------------------------------------------
__global__ void __launch_bounds__(256) k_head_cls(const float* __restrict__ wcls,
                                                  const float* __restrict__ bcls,
                                                  float* __restrict__ out)
{
    __shared__ float red[8][13 * 32];
    int tid = threadIdx.x;
    int cg = tid >> 5;
    int hwl = tid & 31;
    int hw = blockIdx.x * 32 + hwl;

    float acc[13];
    #pragma unroll
    for (int o = 0; o < 13; o++) acc[o] = 0.f;
    const float* __restrict__ d = g_dfm[0];
    int c0 = cg * 96;
    for (int c = c0; c < c0 + 96; c++) {
        float v = d[(size_t)c * HWSZ + hw];
        #pragma unroll
        for (int o = 0; o < 13; o++)
            acc[o] = fmaf(wcls[o * 768 + c], v, acc[o]);
    }
    #pragma unroll
    for (int o = 0; o < 13; o++) red[cg][o * 32 + hwl] = acc[o];
    __syncthreads();

    if (tid < 32) {
        #pragma unroll
        for (int o = 0; o < 13; o++) {
            float s = bcls[o];
            #pragma unroll
            for (int g = 0; g < 8; g++) s += red[g][o * 32 + tid];
            out[(size_t)o * HWSZ + blockIdx.x * 32 + tid] = s;
        }
    }
}

// ---------------------------------------------------------------------------
// Kernel 7: kpt + bbox heads + minmax bbox decode (fused).
// ---------------------------------------------------------------------------
__global__ void __launch_bounds__(256) k_head_pts(const float* __restrict__ wkpt,
                                                  const float* __restrict__ bkpt,
                                                  const float* __restrict__ wbb,
                                                  const float* __restrict__ bbb,
                                                  const float* __restrict__ kprev,
                                                  float* __restrict__ out)
{
    __shared__ float red[8][38 * 32];
    int tid = threadIdx.x;
    int cg = tid >> 5;
    int hwl = tid & 31;
    int hw = blockIdx.x * 32 + hwl;

    float acck[34], accb[4];
    #pragma unroll
    for (int o = 0; o < 34; o++) acck[o] = 0.f;
    #pragma unroll
    for (int o = 0; o < 4; o++)  accb[o] = 0.f;

    const float* __restrict__ dk = g_dfm[1];
    const float* __restrict__ db = g_dfm[2];
    int c0 = cg * 96;
    for (int c = c0; c < c0 + 96; c++) {
        float vk = dk[(size_t)c * HWSZ + hw];
        float vb = db[(size_t)c * HWSZ + hw];
        #pragma unroll
        for (int o = 0; o < 34; o++)
            acck[o] = fmaf(wkpt[o * 768 + c], vk, acck[o]);
        #pragma unroll
        for (int o = 0; o < 4; o++)
            accb[o] = fmaf(wbb[o * 768 + c], vb, accb[o]);
    }
    #pragma unroll
    for (int o = 0; o < 34; o++) red[cg][o * 32 + hwl] = acck[o];
    #pragma unroll
    for (int o = 0; o < 4; o++)  red[cg][(34 + o) * 32 + hwl] = accb[o];
    __syncthreads();

    if (tid < 32) {
        int hwg = blockIdx.x * 32 + tid;
        float k2[34], b2[4];
        #pragma unroll
        for (int o = 0; o < 34; o++) {
            float s = bkpt[o];
            #pragma unroll
            for (int g = 0; g < 8; g++) s += red[g][o * 32 + tid];
            s += kprev[(size_t)o * HWSZ + hwg];
            k2[o] = s;
            out[(size_t)(17 + o) * HWSZ + hwg] = s;
        }
        #pragma unroll
        for (int o = 0; o < 4; o++) {
            float s = bbb[o];
            #pragma unroll
            for (int g = 0; g < 8; g++) s += red[g][(34 + o) * 32 + tid];
            b2[o] = s;
        }

        float left = 1e30f, right = -1e30f, top = 1e30f, bot = -1e30f;
        #pragma unroll
        for (int i = 0; i < 17; i++) {
            float py = k2[2 * i];
            float px = k2[2 * i + 1];
            top   = fminf(top, py);   bot   = fmaxf(bot, py);
            left  = fminf(left, px);  right = fmaxf(right, px);
        }
        float cx = (left + right) * 0.5f;
        float cy = (top + bot) * 0.5f;
        float hwid = (cx - left) * expf(b2[0]);
        float hhei = (cy - top)  * expf(b2[1]);
        cx += b2[2];
        cy += b2[3];
        out[(size_t)(13 + 0) * HWSZ + hwg] = cx - hwid;
        out[(size_t)(13 + 1) * HWSZ + hwg] = cy - hhei;
        out[(size_t)(13 + 2) * HWSZ + hwg] = cx + hwid;
        out[(size_t)(13 + 3) * HWSZ + hwg] = cy + hhei;
    }
}

// ---------------------------------------------------------------------------
// Launch
// ---------------------------------------------------------------------------
extern "C" void kernel_launch(void* const* d_in, const int* in_sizes, int n_in,
                              void* d_out, int out_size)
{
    const float* cls_feat = (const float*)d_in[0];
    const float* pts_feat = (const float*)d_in[1];
    const float* kprev    = (const float*)d_in[2];
    const float* w_do     = (const float*)d_in[3];
    const float* b_do     = (const float*)d_in[4];
    const float* w_cls    = (const float*)d_in[14];
    const float* b_cls    = (const float*)d_in[15];
    const float* w_kpt    = (const float*)d_in[16];
    const float* b_kpt    = (const float*)d_in[17];
    const float* w_bbox   = (const float*)d_in[18];
    const float* b_bbox   = (const float*)d_in[19];
    float* out = (float*)d_out;

    cudaFuncSetAttribute(k_mma, cudaFuncAttributeMaxDynamicSharedMemorySize,
                         SMEM_DYN);

    k_corners<<<dim3(NPTS, HWSZ / 256), 256>>>(kprev, w_do, b_do);

    W9 ws;
    for (int i = 0; i < 9; i++) ws.p[i] = (const float*)d_in[5 + i];
    k_wt<<<dim3(256, 9), 256>>>(ws);

    k_ft<<<dim3(HWSZ / 32, 256 / 32, 2), dim3(32, 8)>>>(cls_feat, pts_feat);

    // materialize sampled tensor S (fp16), warp-per-row coalesced gather
    k_sg<<<dim3(NPTS * 128, 2), 256>>>();

    // 9 block-diagonal sub-GEMMs, pure cp.async fp16 GEMM
    k_mma<<<dim3(HWSZ / 64, 9), 256, SMEM_DYN>>>();

    k_head_cls<<<HWSZ / 32, 256>>>(w_cls, b_cls, out);
    k_head_pts<<<HWSZ / 32, 256>>>(w_kpt, b_kpt, w_bbox, b_bbox, kprev, out);
}

// round 15
// speedup vs baseline: 7.6914x; 1.3407x over previous
#include <cuda_runtime.h>
#include <cuda_fp16.h>
#include <math.h>
#include <stdint.h>

// ---------------------------------------------------------------------------
// Problem constants (B=1, C=256, H=W=64, FC=256, kernels 3/5/7 -> 83 points)
// ---------------------------------------------------------------------------
#define HWSZ 4096
#define NPTS 83
#define KTOT 21248         // 83*256 packed weight K layout

// ---------------------------------------------------------------------------
// Device scratch  (g_s = 348MB fp16 sampled tensor; rest small)
// ---------------------------------------------------------------------------
__device__ __align__(16) int   g_cidx[NPTS * HWSZ * 4];
__device__ __align__(16) float g_cw  [NPTS * HWSZ * 4];
__device__ __half g_wa[3][(size_t)256 * KTOT];            // fp16 weights [m][k]
__device__ __half g_fth[2][(size_t)HWSZ * 256];           // fp16 feat [hw][c]
__device__ __half g_s[2][(size_t)NPTS * HWSZ * 256];      // sampled S [p][hw][c]
__device__ float g_dfm[3][(size_t)768 * HWSZ];            // relu(deform conv)

// ---------------------------------------------------------------------------
// helpers
// ---------------------------------------------------------------------------
__device__ __forceinline__ uint32_t smem_to_u32(const void* p) {
    uint32_t a;
    asm("{ .reg .u64 t; cvta.to.shared.u64 t, %1; cvt.u32.u64 %0, t; }"
        : "=r"(a) : "l"(p));
    return a;
}
#define SWZ(o) ((o) ^ (((o) >> 3) & 0x70))

__device__ __forceinline__ void ldsm4(uint32_t addr, uint32_t* r) {
    asm volatile("ldmatrix.sync.aligned.m8n8.x4.shared.b16 {%0,%1,%2,%3}, [%4];"
        : "=r"(r[0]), "=r"(r[1]), "=r"(r[2]), "=r"(r[3]) : "r"(addr));
}
__device__ __forceinline__ void mma16816f(float* c, const uint32_t* a,
                                          uint32_t b0, uint32_t b1) {
    asm volatile(
        "mma.sync.aligned.m16n8k16.row.col.f32.f16.f16.f32 "
        "{%0,%1,%2,%3}, {%4,%5,%6,%7}, {%8,%9}, {%0,%1,%2,%3};"
        : "+f"(c[0]), "+f"(c[1]), "+f"(c[2]), "+f"(c[3])
        : "r"(a[0]), "r"(a[1]), "r"(a[2]), "r"(a[3]), "r"(b0), "r"(b1));
}
__device__ __forceinline__ void cpa16(uint32_t dst, const void* src) {
    asm volatile("cp.async.cg.shared.global [%0], [%1], 16;"
                 :: "r"(dst), "l"(src) : "memory");
}
#define CPA_COMMIT() asm volatile("cp.async.commit_group;" ::: "memory")
#define CPA_WAIT0()  asm volatile("cp.async.wait_group 0;" ::: "memory")

// per-stage smem: A 16KB | B 16KB = 32KB, x2 stages = 64KB (2 CTA/SM)
#define S_A 0
#define S_B 16384
#define STAGE 32768
#define SMEM_DYN (2 * STAGE)

// ---------------------------------------------------------------------------
// Kernel 1: fused offset 1x1 conv + bilinear corner table.
// ---------------------------------------------------------------------------
__global__ void k_corners(const float* __restrict__ kprev,
                          const float* __restrict__ w_do,
                          const float* __restrict__ b_do)
{
    int kk = blockIdx.x;
    int hw = blockIdx.y * 256 + threadIdx.x;
    int h = hw >> 6, w = hw & 63;

    int base, kkl;
    if (kk < 9)       { base = 0;  kkl = kk;      }
    else if (kk < 34) { base = 18; kkl = kk - 9;  }
    else              { base = 68; kkl = kk - 34; }
    int chy = base + 2 * kkl;
    int chx = chy + 1;

    float dy = b_do[chy], dx = b_do[chx];
    #pragma unroll 2
    for (int i = 0; i < 34; i++) {
        float v = kprev[i * HWSZ + hw];
        dy = fmaf(w_do[chy * 34 + i], v, dy);
        dx = fmaf(w_do[chx * 34 + i], v, dx);
    }

    float y = (float)h + dy;
    float x = (float)w + dx;
    float y0f = floorf(y), x0f = floorf(x);
    int y0 = (int)y0f, x0 = (int)x0f;
    float wy = y - y0f, wx = x - x0f;

    int   yi[4] = { y0, y0, y0 + 1, y0 + 1 };
    int   xi[4] = { x0, x0 + 1, x0, x0 + 1 };
    float wb[4] = { (1.f - wy) * (1.f - wx), (1.f - wy) * wx,
                    wy * (1.f - wx),         wy * wx };

    int o = (kk * HWSZ + hw) * 4;
    #pragma unroll
    for (int j = 0; j < 4; j++) {
        bool valid = (yi[j] >= 0) && (yi[j] < 64) && (xi[j] >= 0) && (xi[j] < 64);
        int yc = min(max(yi[j], 0), 63);
        int xc = min(max(xi[j], 0), 63);
        g_cidx[o + j] = yc * 64 + xc;
        g_cw  [o + j] = valid ? wb[j] : 0.0f;
    }
}

// ---------------------------------------------------------------------------
// Kernel 2: weight transpose to fp16 (division-free).
// ---------------------------------------------------------------------------
struct W9 { const float* p[9]; };

__global__ void k_wt(W9 ws)
{
    int sub = blockIdx.y;
    int branch = sub / 3;
    int ks = sub - branch * 3;
    int Kp    = (ks == 0) ? 9 : (ks == 1) ? 25 : 49;
    int kbase = (ks == 0) ? 0 : (ks == 1) ? 9  : 34;
    int o = blockIdx.x;
    int c = threadIdx.x;

    const float* src = ws.p[sub] + ((size_t)o * 256 + c) * Kp;
    __half* dh = g_wa[branch] + (size_t)o * KTOT + (size_t)kbase * 256 + c;

    for (int kkl = 0; kkl < Kp; kkl++)
        dh[(size_t)kkl * 256] = __float2half_rn(src[kkl]);
}

// ---------------------------------------------------------------------------
// Kernel 3: feature transpose [c][hw] -> fp16 [hw][c]
// ---------------------------------------------------------------------------
__global__ void k_ft(const float* __restrict__ f0, const float* __restrict__ f1)
{
    __shared__ float t[32][33];
    int f = blockIdx.z;
    const float* __restrict__ src = f ? f1 : f0;
    int hw0 = blockIdx.x * 32, c0 = blockIdx.y * 32;
    #pragma unroll
    for (int i = 0; i < 4; i++) {
        int c = c0 + threadIdx.y + i * 8;
        t[threadIdx.y + i * 8][threadIdx.x] = src[(size_t)c * HWSZ + hw0 + threadIdx.x];
    }
    __syncthreads();
    #pragma unroll
    for (int i = 0; i < 4; i++) {
        int hw = hw0 + threadIdx.y + i * 8;
        g_fth[f][(size_t)hw * 256 + c0 + threadIdx.x] =
            __float2half_rn(t[threadIdx.x][threadIdx.y + i * 8]);
    }
}

// ---------------------------------------------------------------------------
// Kernel 4: build sampled tensor S[f][p][hw][c] fp16 — WARP-PER-ROW.
// ---------------------------------------------------------------------------
__global__ void __launch_bounds__(256) k_sg()
{
    int tid  = threadIdx.x;
    int wid  = tid >> 5;
    int lane = tid & 31;
    int bx = blockIdx.x;
    int p   = bx >> 7;              // 0..82
    int hw0 = (bx & 127) * 32;      // 32 rows per block
    int f = blockIdx.y;

    const __half* __restrict__ F = g_fth[f];
    __half* __restrict__ Sp = g_s[f] + ((size_t)p * HWSZ + hw0) * 256;

    #pragma unroll
    for (int i = 0; i < 4; i++) {
        int hwl = wid * 4 + i;
        int hw = hw0 + hwl;
        int o = (p * HWSZ + hw) * 4;    // warp-uniform -> broadcast loads
        int4   id4 = *reinterpret_cast<const int4*>(&g_cidx[o]);
        float4 wv4 = *reinterpret_cast<const float4*>(&g_cw[o]);

        uint4 v0 = *reinterpret_cast<const uint4*>(F + (size_t)id4.x * 256 + lane * 8);
        uint4 v1 = *reinterpret_cast<const uint4*>(F + (size_t)id4.y * 256 + lane * 8);
        uint4 v2 = *reinterpret_cast<const uint4*>(F + (size_t)id4.z * 256 + lane * 8);
        uint4 v3 = *reinterpret_cast<const uint4*>(F + (size_t)id4.w * 256 + lane * 8);

        const __half2* a2 = reinterpret_cast<const __half2*>(&v0);
        const __half2* b2 = reinterpret_cast<const __half2*>(&v1);
        const __half2* c2 = reinterpret_cast<const __half2*>(&v2);
        const __half2* d2 = reinterpret_cast<const __half2*>(&v3);

        uint4 outv;
        uint32_t* op = reinterpret_cast<uint32_t*>(&outv);
        #pragma unroll
        for (int k = 0; k < 4; k++) {
            float2 a = __half22float2(a2[k]);
            float2 b = __half22float2(b2[k]);
            float2 c = __half22float2(c2[k]);
            float2 d = __half22float2(d2[k]);
            float vx = wv4.x*a.x + wv4.y*b.x + wv4.z*c.x + wv4.w*d.x;
            float vy = wv4.x*a.y + wv4.y*b.y + wv4.z*c.y + wv4.w*d.y;
            __half2 hv = __floats2half2_rn(vx, vy);
            op[k] = *reinterpret_cast<uint32_t*>(&hv);
        }
        *reinterpret_cast<uint4*>(Sp + (size_t)hwl * 256 + lane * 8) = outv;
    }
}

// ---------------------------------------------------------------------------
// Kernel 5: pure cp.async fp16 HMMA GEMM (double-buffered).
//   9 block-diagonal sub-GEMMs. Block M128 x N128 x K64, 256 threads =
//   8 warps (2M x 4N), warp tile 64x32, 2 CTA/SM. Grid (32n, 2m, 9sub).
//   Stage = A 16KB + B 16KB; A L2 traffic 4x lower than M256xN64 config.
// ---------------------------------------------------------------------------
__global__ void __launch_bounds__(256, 2) k_mma()
{
    const int SUBMAP[9] = {2, 5, 8, 1, 4, 7, 0, 3, 6};  // heavy (k7) first
    const int P0_[3] = {0, 9, 34};
    const int NP_[3] = {9, 25, 49};

    extern __shared__ __align__(128) char smem[];
    uint32_t sb = smem_to_u32(smem);

    int tid = threadIdx.x;
    int wid = tid >> 5;
    int lid = tid & 31;

    int sub = SUBMAP[blockIdx.z];
    int branch = sub / 3;
    int ks = sub - branch * 3;
    int p0 = P0_[ks];
    int np = NP_[ks];

    int n0 = blockIdx.x * 128;
    int m0 = blockIdx.y * 128;
    const __half* __restrict__ Sf = g_s[branch == 0 ? 0 : 1];
    const __half* __restrict__ Ah = g_wa[branch];
    float* __restrict__ Cp = g_dfm[branch] + (size_t)ks * 256 * HWSZ;

    int wm = wid >> 2;            // 0..1 -> m offset wm*64
    int wn = wid & 3;             // 0..3 -> n offset wn*32

    // fill mapping: 2 threads per 128B row (64B each)
    int f_row = tid >> 1;         // 0..127
    int f_seg = (tid & 1) * 4;    // 0 or 4 (16B units)

    uint32_t a_row = wm * 64 + ((lid >> 3) & 1) * 8 + (lid & 7);
    uint32_t a_byt = (lid >> 4) * 16;
    uint32_t b_row = wn * 32 + (lid & 7) + ((lid >> 4) & 1) * 8;
    uint32_t b_byt = ((lid >> 3) & 1) * 16;

    float acc[4][4][4];
    #pragma unroll
    for (int i = 0; i < 4; i++)
        #pragma unroll
        for (int j = 0; j < 4; j++)
            #pragma unroll
            for (int r = 0; r < 4; r++) acc[i][j][r] = 0.f;

    int nchunk = np * 4;

    auto fill = [&](int gp, int c0v, uint32_t stage_base) {
        // A: 128 rows (m0..m0+127) x 128B
        {
            const __half* src = Ah + (size_t)(m0 + f_row) * KTOT + gp * 256
                                   + c0v + f_seg * 8;
            uint32_t d = stage_base + S_A;
            #pragma unroll
            for (int j = 0; j < 4; j++)
                cpa16(d + SWZ((uint32_t)(f_row * 128 + (f_seg + j) * 16)),
                      src + j * 8);
        }
        // B: 128 rows (n0..n0+127) x 128B
        {
            const __half* src = Sf + ((size_t)gp * HWSZ + n0 + f_row) * 256
                                   + c0v + f_seg * 8;
            uint32_t d = stage_base + S_B;
            #pragma unroll
            for (int j = 0; j < 4; j++)
                cpa16(d + SWZ((uint32_t)(f_row * 128 + (f_seg + j) * 16)),
                      src + j * 8);
        }
    };

    // prologue
    fill(p0, 0, sb);
    CPA_COMMIT();
    CPA_WAIT0();
    __syncthreads();

    for (int ch = 0; ch < nchunk; ch++) {
        uint32_t cur_base = sb + (ch & 1) * STAGE;
        uint32_t nxt_base = sb + ((ch + 1) & 1) * STAGE;
        bool has_next = (ch + 1) < nchunk;

        if (has_next) {
            int gp1 = p0 + ((ch + 1) >> 2);
            int c01 = ((ch + 1) & 3) * 64;
            fill(gp1, c01, nxt_base);
            CPA_COMMIT();
        }

        // math on current stage: 4 ksteps x 16 mma per warp
        #pragma unroll
        for (int ks2 = 0; ks2 < 4; ks2++) {
            uint32_t kb = ks2 * 32;
            uint32_t ah[4][4], bh[2][4];
            #pragma unroll
            for (int mi = 0; mi < 4; mi++)
                ldsm4(cur_base + S_A + SWZ((a_row + mi * 16) * 128 + kb + a_byt), ah[mi]);
            #pragma unroll
            for (int bj = 0; bj < 2; bj++)
                ldsm4(cur_base + S_B + SWZ((b_row + bj * 16) * 128 + kb + b_byt), bh[bj]);
            #pragma unroll
            for (int mi = 0; mi < 4; mi++)
                #pragma unroll
                for (int nj = 0; nj < 4; nj++)
                    mma16816f(acc[mi][nj], ah[mi], bh[nj >> 1][(nj & 1) * 2],
                              bh[nj >> 1][(nj & 1) * 2 + 1]);
        }

        if (has_next) CPA_WAIT0();
        __syncthreads();
    }

    // epilogue: relu + store
    int l4 = lid >> 2;
    int l2 = (lid & 3) * 2;
    #pragma unroll
    for (int mi = 0; mi < 4; mi++) {
        #pragma unroll
        for (int nj = 0; nj < 4; nj++) {
            int m = m0 + wm * 64 + mi * 16 + l4;
            int n = n0 + wn * 32 + nj * 8 + l2;
            float2 v0, v1;
            v0.x = fmaxf(acc[mi][nj][0], 0.f);
            v0.y = fmaxf(acc[mi][nj][1], 0.f);
            v1.x = fmaxf(acc[mi][nj][2], 0.f);
            v1.y = fmaxf(acc[mi][nj][3], 0.f);
            *reinterpret_cast<float2*>(Cp + (size_t)m * HWSZ + n) = v0;
            *reinterpret_cast<float2*>(Cp + (size_t)(m + 8) * HWSZ + n) = v1;
        }
    }
}

// ---------------------------------------------------------------------------
// Kernel 6: cls head.
// ---------------------------------------------------------------------------
__global__ void __launch_bounds__(256) k_head_cls(const float* __restrict__ wcls,
                                                  const float* __restrict__ bcls,
                                                  float* __restrict__ out)
{
    __shared__ float red[8][13 * 32];
    int tid = threadIdx.x;
    int cg = tid >> 5;
    int hwl = tid & 31;
    int hw = blockIdx.x * 32 + hwl;

    float acc[13];
    #pragma unroll
    for (int o = 0; o < 13; o++) acc[o] = 0.f;
    const float* __restrict__ d = g_dfm[0];
    int c0 = cg * 96;
    for (int c = c0; c < c0 + 96; c++) {
        float v = d[(size_t)c * HWSZ + hw];
        #pragma unroll
        for (int o = 0; o < 13; o++)
            acc[o] = fmaf(wcls[o * 768 + c], v, acc[o]);
    }
    #pragma unroll
    for (int o = 0; o < 13; o++) red[cg][o * 32 + hwl] = acc[o];
    __syncthreads();

    if (tid < 32) {
        #pragma unroll
        for (int o = 0; o < 13; o++) {
            float s = bcls[o];
            #pragma unroll
            for (int g = 0; g < 8; g++) s += red[g][o * 32 + tid];
            out[(size_t)o * HWSZ + blockIdx.x * 32 + tid] = s;
        }
    }
}

// ---------------------------------------------------------------------------
// Kernel 7: kpt + bbox heads + minmax bbox decode (fused).
// ---------------------------------------------------------------------------
__global__ void __launch_bounds__(256) k_head_pts(const float* __restrict__ wkpt,
                                                  const float* __restrict__ bkpt,
                                                  const float* __restrict__ wbb,
                                                  const float* __restrict__ bbb,
                                                  const float* __restrict__ kprev,
                                                  float* __restrict__ out)
{
    __shared__ float red[8][38 * 32];
    int tid = threadIdx.x;
    int cg = tid >> 5;
    int hwl = tid & 31;
    int hw = blockIdx.x * 32 + hwl;

    float acck[34], accb[4];
    #pragma unroll
    for (int o = 0; o < 34; o++) acck[o] = 0.f;
    #pragma unroll
    for (int o = 0; o < 4; o++)  accb[o] = 0.f;

    const float* __restrict__ dk = g_dfm[1];
    const float* __restrict__ db = g_dfm[2];
    int c0 = cg * 96;
    for (int c = c0; c < c0 + 96; c++) {
        float vk = dk[(size_t)c * HWSZ + hw];
        float vb = db[(size_t)c * HWSZ + hw];
        #pragma unroll
        for (int o = 0; o < 34; o++)
            acck[o] = fmaf(wkpt[o * 768 + c], vk, acck[o]);
        #pragma unroll
        for (int o = 0; o < 4; o++)
            accb[o] = fmaf(wbb[o * 768 + c], vb, accb[o]);
    }
    #pragma unroll
    for (int o = 0; o < 34; o++) red[cg][o * 32 + hwl] = acck[o];
    #pragma unroll
    for (int o = 0; o < 4; o++)  red[cg][(34 + o) * 32 + hwl] = accb[o];
    __syncthreads();

    if (tid < 32) {
        int hwg = blockIdx.x * 32 + tid;
        float k2[34], b2[4];
        #pragma unroll
        for (int o = 0; o < 34; o++) {
            float s = bkpt[o];
            #pragma unroll
            for (int g = 0; g < 8; g++) s += red[g][o * 32 + tid];
            s += kprev[(size_t)o * HWSZ + hwg];
            k2[o] = s;
            out[(size_t)(17 + o) * HWSZ + hwg] = s;
        }
        #pragma unroll
        for (int o = 0; o < 4; o++) {
            float s = bbb[o];
            #pragma unroll
            for (int g = 0; g < 8; g++) s += red[g][(34 + o) * 32 + tid];
            b2[o] = s;
        }

        float left = 1e30f, right = -1e30f, top = 1e30f, bot = -1e30f;
        #pragma unroll
        for (int i = 0; i < 17; i++) {
            float py = k2[2 * i];
            float px = k2[2 * i + 1];
            top   = fminf(top, py);   bot   = fmaxf(bot, py);
            left  = fminf(left, px);  right = fmaxf(right, px);
        }
        float cx = (left + right) * 0.5f;
        float cy = (top + bot) * 0.5f;
        float hwid = (cx - left) * expf(b2[0]);
        float hhei = (cy - top)  * expf(b2[1]);
        cx += b2[2];
        cy += b2[3];
        out[(size_t)(13 + 0) * HWSZ + hwg] = cx - hwid;
        out[(size_t)(13 + 1) * HWSZ + hwg] = cy - hhei;
        out[(size_t)(13 + 2) * HWSZ + hwg] = cx + hwid;
        out[(size_t)(13 + 3) * HWSZ + hwg] = cy + hhei;
    }
}

// ---------------------------------------------------------------------------
// Launch
// ---------------------------------------------------------------------------
extern "C" void kernel_launch(void* const* d_in, const int* in_sizes, int n_in,
                              void* d_out, int out_size)
{
    const float* cls_feat = (const float*)d_in[0];
    const float* pts_feat = (const float*)d_in[1];
    const float* kprev    = (const float*)d_in[2];
    const float* w_do     = (const float*)d_in[3];
    const float* b_do     = (const float*)d_in[4];
    const float* w_cls    = (const float*)d_in[14];
    const float* b_cls    = (const float*)d_in[15];
    const float* w_kpt    = (const float*)d_in[16];
    const float* b_kpt    = (const float*)d_in[17];
    const float* w_bbox   = (const float*)d_in[18];
    const float* b_bbox   = (const float*)d_in[19];
    float* out = (float*)d_out;

    cudaFuncSetAttribute(k_mma, cudaFuncAttributeMaxDynamicSharedMemorySize,
                         SMEM_DYN);

    k_corners<<<dim3(NPTS, HWSZ / 256), 256>>>(kprev, w_do, b_do);

    W9 ws;
    for (int i = 0; i < 9; i++) ws.p[i] = (const float*)d_in[5 + i];
    k_wt<<<dim3(256, 9), 256>>>(ws);

    k_ft<<<dim3(HWSZ / 32, 256 / 32, 2), dim3(32, 8)>>>(cls_feat, pts_feat);

    // materialize sampled tensor S (fp16), warp-per-row coalesced gather
    k_sg<<<dim3(NPTS * 128, 2), 256>>>();

    // 9 block-diagonal sub-GEMMs, M128 x N128 x K64, pure cp.async fp16
    k_mma<<<dim3(HWSZ / 128, 2, 9), 256, SMEM_DYN>>>();

    k_head_cls<<<HWSZ / 32, 256>>>(w_cls, b_cls, out);
    k_head_pts<<<HWSZ / 32, 256>>>(w_kpt, b_kpt, w_bbox, b_bbox, kprev, out);
}

// round 16
// speedup vs baseline: 7.7282x; 1.0048x over previous
#include <cuda_runtime.h>
#include <cuda_fp16.h>
#include <math.h>
#include <stdint.h>

// ---------------------------------------------------------------------------
// Problem constants (B=1, C=256, H=W=64, FC=256, kernels 3/5/7 -> 83 points)
// ---------------------------------------------------------------------------
#define HWSZ 4096
#define NPTS 83
#define KTOT 21248         // 83*256 packed weight K layout

// ---------------------------------------------------------------------------
// Device scratch  (g_s = 348MB fp16 sampled tensor; rest small)
// ---------------------------------------------------------------------------
__device__ __align__(16) int   g_cidx[NPTS * HWSZ * 4];
__device__ __align__(16) float g_cw  [NPTS * HWSZ * 4];
__device__ __half g_wa[3][(size_t)256 * KTOT];            // fp16 weights [m][k]
__device__ __half g_fth[2][(size_t)HWSZ * 256];           // fp16 feat [hw][c]
__device__ __half g_s[2][(size_t)NPTS * HWSZ * 256];      // sampled S [p][hw][c]
__device__ __half g_dfm[3][(size_t)768 * HWSZ];           // relu(deform conv), fp16

// ---------------------------------------------------------------------------
// helpers
// ---------------------------------------------------------------------------
__device__ __forceinline__ uint32_t smem_to_u32(const void* p) {
    uint32_t a;
    asm("{ .reg .u64 t; cvta.to.shared.u64 t, %1; cvt.u32.u64 %0, t; }"
        : "=r"(a) : "l"(p));
    return a;
}
#define SWZ(o) ((o) ^ (((o) >> 3) & 0x70))

__device__ __forceinline__ void ldsm4(uint32_t addr, uint32_t* r) {
    asm volatile("ldmatrix.sync.aligned.m8n8.x4.shared.b16 {%0,%1,%2,%3}, [%4];"
        : "=r"(r[0]), "=r"(r[1]), "=r"(r[2]), "=r"(r[3]) : "r"(addr));
}
__device__ __forceinline__ void mma16816f(float* c, const uint32_t* a,
                                          uint32_t b0, uint32_t b1) {
    asm volatile(
        "mma.sync.aligned.m16n8k16.row.col.f32.f16.f16.f32 "
        "{%0,%1,%2,%3}, {%4,%5,%6,%7}, {%8,%9}, {%0,%1,%2,%3};"
        : "+f"(c[0]), "+f"(c[1]), "+f"(c[2]), "+f"(c[3])
        : "r"(a[0]), "r"(a[1]), "r"(a[2]), "r"(a[3]), "r"(b0), "r"(b1));
}
__device__ __forceinline__ void cpa16(uint32_t dst, const void* src) {
    asm volatile("cp.async.cg.shared.global [%0], [%1], 16;"
                 :: "r"(dst), "l"(src) : "memory");
}
#define CPA_COMMIT() asm volatile("cp.async.commit_group;" ::: "memory")
#define CPA_WAIT0()  asm volatile("cp.async.wait_group 0;" ::: "memory")
#define CPA_WAIT1()  asm volatile("cp.async.wait_group 1;" ::: "memory")

// per-stage smem: A 16KB | B 16KB = 32KB, x3 stages = 96KB (2 CTA/SM)
#define S_A 0
#define S_B 16384
#define STAGE 32768
#define SMEM_DYN (3 * STAGE)

// ---------------------------------------------------------------------------
// Kernel 1: fused offset 1x1 conv + bilinear corner table.
// ---------------------------------------------------------------------------
__global__ void k_corners(const float* __restrict__ kprev,
                          const float* __restrict__ w_do,
                          const float* __restrict__ b_do)
{
    int kk = blockIdx.x;
    int hw = blockIdx.y * 256 + threadIdx.x;
    int h = hw >> 6, w = hw & 63;

    int base, kkl;
    if (kk < 9)       { base = 0;  kkl = kk;      }
    else if (kk < 34) { base = 18; kkl = kk - 9;  }
    else              { base = 68; kkl = kk - 34; }
    int chy = base + 2 * kkl;
    int chx = chy + 1;

    float dy = b_do[chy], dx = b_do[chx];
    #pragma unroll 2
    for (int i = 0; i < 34; i++) {
        float v = kprev[i * HWSZ + hw];
        dy = fmaf(w_do[chy * 34 + i], v, dy);
        dx = fmaf(w_do[chx * 34 + i], v, dx);
    }

    float y = (float)h + dy;
    float x = (float)w + dx;
    float y0f = floorf(y), x0f = floorf(x);
    int y0 = (int)y0f, x0 = (int)x0f;
    float wy = y - y0f, wx = x - x0f;

    int   yi[4] = { y0, y0, y0 + 1, y0 + 1 };
    int   xi[4] = { x0, x0 + 1, x0, x0 + 1 };
    float wb[4] = { (1.f - wy) * (1.f - wx), (1.f - wy) * wx,
                    wy * (1.f - wx),         wy * wx };

    int o = (kk * HWSZ + hw) * 4;
    #pragma unroll
    for (int j = 0; j < 4; j++) {
        bool valid = (yi[j] >= 0) && (yi[j] < 64) && (xi[j] >= 0) && (xi[j] < 64);
        int yc = min(max(yi[j], 0), 63);
        int xc = min(max(xi[j], 0), 63);
        g_cidx[o + j] = yc * 64 + xc;
        g_cw  [o + j] = valid ? wb[j] : 0.0f;
    }
}

// ---------------------------------------------------------------------------
// Kernel 2: weight transpose to fp16 (division-free).
// ---------------------------------------------------------------------------
struct W9 { const float* p[9]; };

__global__ void k_wt(W9 ws)
{
    int sub = blockIdx.y;
    int branch = sub / 3;
    int ks = sub - branch * 3;
    int Kp    = (ks == 0) ? 9 : (ks == 1) ? 25 : 49;
    int kbase = (ks == 0) ? 0 : (ks == 1) ? 9  : 34;
    int o = blockIdx.x;
    int c = threadIdx.x;

    const float* src = ws.p[sub] + ((size_t)o * 256 + c) * Kp;
    __half* dh = g_wa[branch] + (size_t)o * KTOT + (size_t)kbase * 256 + c;

    for (int kkl = 0; kkl < Kp; kkl++)
        dh[(size_t)kkl * 256] = __float2half_rn(src[kkl]);
}

// ---------------------------------------------------------------------------
// Kernel 3: feature transpose [c][hw] -> fp16 [hw][c]
// ---------------------------------------------------------------------------
__global__ void k_ft(const float* __restrict__ f0, const float* __restrict__ f1)
{
    __shared__ float t[32][33];
    int f = blockIdx.z;
    const float* __restrict__ src = f ? f1 : f0;
    int hw0 = blockIdx.x * 32, c0 = blockIdx.y * 32;
    #pragma unroll
    for (int i = 0; i < 4; i++) {
        int c = c0 + threadIdx.y + i * 8;
        t[threadIdx.y + i * 8][threadIdx.x] = src[(size_t)c * HWSZ + hw0 + threadIdx.x];
    }
    __syncthreads();
    #pragma unroll
    for (int i = 0; i < 4; i++) {
        int hw = hw0 + threadIdx.y + i * 8;
        g_fth[f][(size_t)hw * 256 + c0 + threadIdx.x] =
            __float2half_rn(t[threadIdx.x][threadIdx.y + i * 8]);
    }
}

// ---------------------------------------------------------------------------
// Kernel 4: build sampled tensor S[f][p][hw][c] fp16 — WARP-PER-ROW.
// ---------------------------------------------------------------------------
__global__ void __launch_bounds__(256) k_sg()
{
    int tid  = threadIdx.x;
    int wid  = tid >> 5;
    int lane = tid & 31;
    int bx = blockIdx.x;
    int p   = bx >> 7;              // 0..82
    int hw0 = (bx & 127) * 32;      // 32 rows per block
    int f = blockIdx.y;

    const __half* __restrict__ F = g_fth[f];
    __half* __restrict__ Sp = g_s[f] + ((size_t)p * HWSZ + hw0) * 256;

    #pragma unroll
    for (int i = 0; i < 4; i++) {
        int hwl = wid * 4 + i;
        int hw = hw0 + hwl;
        int o = (p * HWSZ + hw) * 4;    // warp-uniform -> broadcast loads
        int4   id4 = *reinterpret_cast<const int4*>(&g_cidx[o]);
        float4 wv4 = *reinterpret_cast<const float4*>(&g_cw[o]);

        uint4 v0 = *reinterpret_cast<const uint4*>(F + (size_t)id4.x * 256 + lane * 8);
        uint4 v1 = *reinterpret_cast<const uint4*>(F + (size_t)id4.y * 256 + lane * 8);
        uint4 v2 = *reinterpret_cast<const uint4*>(F + (size_t)id4.z * 256 + lane * 8);
        uint4 v3 = *reinterpret_cast<const uint4*>(F + (size_t)id4.w * 256 + lane * 8);

        const __half2* a2 = reinterpret_cast<const __half2*>(&v0);
        const __half2* b2 = reinterpret_cast<const __half2*>(&v1);
        const __half2* c2 = reinterpret_cast<const __half2*>(&v2);
        const __half2* d2 = reinterpret_cast<const __half2*>(&v3);

        uint4 outv;
        uint32_t* op = reinterpret_cast<uint32_t*>(&outv);
        #pragma unroll
        for (int k = 0; k < 4; k++) {
            float2 a = __half22float2(a2[k]);
            float2 b = __half22float2(b2[k]);
            float2 c = __half22float2(c2[k]);
            float2 d = __half22float2(d2[k]);
            float vx = wv4.x*a.x + wv4.y*b.x + wv4.z*c.x + wv4.w*d.x;
            float vy = wv4.x*a.y + wv4.y*b.y + wv4.z*c.y + wv4.w*d.y;
            __half2 hv = __floats2half2_rn(vx, vy);
            op[k] = *reinterpret_cast<uint32_t*>(&hv);
        }
        *reinterpret_cast<uint4*>(Sp + (size_t)hwl * 256 + lane * 8) = outv;
    }
}

// ---------------------------------------------------------------------------
// Kernel 5: pure cp.async fp16 HMMA GEMM, 3-stage pipeline.
//   9 block-diagonal sub-GEMMs. Block M128 x N128 x K64, 256 threads =
//   8 warps (2M x 4N), warp tile 64x32, 2 CTA/SM. Grid (32n, 2m, 9sub).
// ---------------------------------------------------------------------------
__global__ void __launch_bounds__(256, 2) k_mma()
{
    const int SUBMAP[9] = {2, 5, 8, 1, 4, 7, 0, 3, 6};  // heavy (k7) first
    const int P0_[3] = {0, 9, 34};
    const int NP_[3] = {9, 25, 49};

    extern __shared__ __align__(128) char smem[];
    uint32_t sb = smem_to_u32(smem);

    int tid = threadIdx.x;
    int wid = tid >> 5;
    int lid = tid & 31;

    int sub = SUBMAP[blockIdx.z];
    int branch = sub / 3;
    int ks = sub - branch * 3;
    int p0 = P0_[ks];
    int np = NP_[ks];

    int n0 = blockIdx.x * 128;
    int m0 = blockIdx.y * 128;
    const __half* __restrict__ Sf = g_s[branch == 0 ? 0 : 1];
    const __half* __restrict__ Ah = g_wa[branch];
    __half* __restrict__ Cp = g_dfm[branch] + (size_t)ks * 256 * HWSZ;

    int wm = wid >> 2;            // 0..1 -> m offset wm*64
    int wn = wid & 3;             // 0..3 -> n offset wn*32

    // fill mapping: 2 threads per 128B row (64B each)
    int f_row = tid >> 1;         // 0..127
    int f_seg = (tid & 1) * 4;    // 0 or 4 (16B units)

    uint32_t a_row = wm * 64 + ((lid >> 3) & 1) * 8 + (lid & 7);
    uint32_t a_byt = (lid >> 4) * 16;
    uint32_t b_row = wn * 32 + (lid & 7) + ((lid >> 4) & 1) * 8;
    uint32_t b_byt = ((lid >> 3) & 1) * 16;

    float acc[4][4][4];
    #pragma unroll
    for (int i = 0; i < 4; i++)
        #pragma unroll
        for (int j = 0; j < 4; j++)
            #pragma unroll
            for (int r = 0; r < 4; r++) acc[i][j][r] = 0.f;

    int nchunk = np * 4;

    auto fill = [&](int ch, uint32_t stage_base) {
        int gp  = p0 + (ch >> 2);
        int c0v = (ch & 3) * 64;
        // A: 128 rows (m0..m0+127) x 128B
        {
            const __half* src = Ah + (size_t)(m0 + f_row) * KTOT + gp * 256
                                   + c0v + f_seg * 8;
            uint32_t d = stage_base + S_A;
            #pragma unroll
            for (int j = 0; j < 4; j++)
                cpa16(d + SWZ((uint32_t)(f_row * 128 + (f_seg + j) * 16)),
                      src + j * 8);
        }
        // B: 128 rows (n0..n0+127) x 128B
        {
            const __half* src = Sf + ((size_t)gp * HWSZ + n0 + f_row) * 256
                                   + c0v + f_seg * 8;
            uint32_t d = stage_base + S_B;
            #pragma unroll
            for (int j = 0; j < 4; j++)
                cpa16(d + SWZ((uint32_t)(f_row * 128 + (f_seg + j) * 16)),
                      src + j * 8);
        }
    };

    // prologue: fill stages 0 and 1
    fill(0, sb);
    CPA_COMMIT();
    if (nchunk > 1) { fill(1, sb + STAGE); }
    CPA_COMMIT();
    CPA_WAIT1();                  // stage 0 ready (1 group may remain in flight)
    __syncthreads();

    int stage = 0;
    for (int ch = 0; ch < nchunk; ch++) {
        uint32_t cur_base = sb + stage * STAGE;

        // issue fill for ch+2 into the stage being freed this iteration
        bool has_fill = (ch + 2) < nchunk;
        if (has_fill) {
            int nstage = stage + 2; if (nstage >= 3) nstage -= 3;
            fill(ch + 2, sb + nstage * STAGE);
            CPA_COMMIT();
        }

        // math on current stage: 4 ksteps x 16 mma per warp
        #pragma unroll
        for (int ks2 = 0; ks2 < 4; ks2++) {
            uint32_t kb = ks2 * 32;
            uint32_t ah[4][4], bh[2][4];
            #pragma unroll
            for (int mi = 0; mi < 4; mi++)
                ldsm4(cur_base + S_A + SWZ((a_row + mi * 16) * 128 + kb + a_byt), ah[mi]);
            #pragma unroll
            for (int bj = 0; bj < 2; bj++)
                ldsm4(cur_base + S_B + SWZ((b_row + bj * 16) * 128 + kb + b_byt), bh[bj]);
            #pragma unroll
            for (int mi = 0; mi < 4; mi++)
                #pragma unroll
                for (int nj = 0; nj < 4; nj++)
                    mma16816f(acc[mi][nj], ah[mi], bh[nj >> 1][(nj & 1) * 2],
                              bh[nj >> 1][(nj & 1) * 2 + 1]);
        }

        // ensure stage for ch+1 is complete before next math phase
        if (has_fill) { CPA_WAIT1(); } else { CPA_WAIT0(); }
        __syncthreads();
        stage = (stage + 1 == 3) ? 0 : stage + 1;
    }

    // epilogue: relu + fp16 store
    int l4 = lid >> 2;
    int l2 = (lid & 3) * 2;
    #pragma unroll
    for (int mi = 0; mi < 4; mi++) {
        #pragma unroll
        for (int nj = 0; nj < 4; nj++) {
            int m = m0 + wm * 64 + mi * 16 + l4;
            int n = n0 + wn * 32 + nj * 8 + l2;
            __half2 h0 = __floats2half2_rn(fmaxf(acc[mi][nj][0], 0.f),
                                           fmaxf(acc[mi][nj][1], 0.f));
            __half2 h1 = __floats2half2_rn(fmaxf(acc[mi][nj][2], 0.f),
                                           fmaxf(acc[mi][nj][3], 0.f));
            *reinterpret_cast<__half2*>(Cp + (size_t)m * HWSZ + n) = h0;
            *reinterpret_cast<__half2*>(Cp + (size_t)(m + 8) * HWSZ + n) = h1;
        }
    }
}

// ---------------------------------------------------------------------------
// Kernel 6: cls head (fp16 dfm input).
// ---------------------------------------------------------------------------
__global__ void __launch_bounds__(256) k_head_cls(const float* __restrict__ wcls,
                                                  const float* __restrict__ bcls,
                                                  float* __restrict__ out)
{
    __shared__ float red[8][13 * 32];
    int tid = threadIdx.x;
    int cg = tid >> 5;
    int hwl = tid & 31;
    int hw = blockIdx.x * 32 + hwl;

    float acc[13];
    #pragma unroll
    for (int o = 0; o < 13; o++) acc[o] = 0.f;
    const __half* __restrict__ d = g_dfm[0];
    int c0 = cg * 96;
    for (int c = c0; c < c0 + 96; c++) {
        float v = __half2float(d[(size_t)c * HWSZ + hw]);
        #pragma unroll
        for (int o = 0; o < 13; o++)
            acc[o] = fmaf(wcls[o * 768 + c], v, acc[o]);
    }
    #pragma unroll
    for (int o = 0; o < 13; o++) red[cg][o * 32 + hwl] = acc[o];
    __syncthreads();

    if (tid < 32) {
        #pragma unroll
        for (int o = 0; o < 13; o++) {
            float s = bcls[o];
            #pragma unroll
            for (int g = 0; g < 8; g++) s += red[g][o * 32 + tid];
            out[(size_t)o * HWSZ + blockIdx.x * 32 + tid] = s;
        }
    }
}

// ---------------------------------------------------------------------------
// Kernel 7: kpt + bbox heads + minmax bbox decode (fused, fp16 dfm input).
// ---------------------------------------------------------------------------
__global__ void __launch_bounds__(256) k_head_pts(const float* __restrict__ wkpt,
                                                  const float* __restrict__ bkpt,
                                                  const float* __restrict__ wbb,
                                                  const float* __restrict__ bbb,
                                                  const float* __restrict__ kprev,
                                                  float* __restrict__ out)
{
    __shared__ float red[8][38 * 32];
    int tid = threadIdx.x;
    int cg = tid >> 5;
    int hwl = tid & 31;
    int hw = blockIdx.x * 32 + hwl;

    float acck[34], accb[4];
    #pragma unroll
    for (int o = 0; o < 34; o++) acck[o] = 0.f;
    #pragma unroll
    for (int o = 0; o < 4; o++)  accb[o] = 0.f;

    const __half* __restrict__ dk = g_dfm[1];
    const __half* __restrict__ db = g_dfm[2];
    int c0 = cg * 96;
    for (int c = c0; c < c0 + 96; c++) {
        float vk = __half2float(dk[(size_t)c * HWSZ + hw]);
        float vb = __half2float(db[(size_t)c * HWSZ + hw]);
        #pragma unroll
        for (int o = 0; o < 34; o++)
            acck[o] = fmaf(wkpt[o * 768 + c], vk, acck[o]);
        #pragma unroll
        for (int o = 0; o < 4; o++)
            accb[o] = fmaf(wbb[o * 768 + c], vb, accb[o]);
    }
    #pragma unroll
    for (int o = 0; o < 34; o++) red[cg][o * 32 + hwl] = acck[o];
    #pragma unroll
    for (int o = 0; o < 4; o++)  red[cg][(34 + o) * 32 + hwl] = accb[o];
    __syncthreads();

    if (tid < 32) {
        int hwg = blockIdx.x * 32 + tid;
        float k2[34], b2[4];
        #pragma unroll
        for (int o = 0; o < 34; o++) {
            float s = bkpt[o];
            #pragma unroll
            for (int g = 0; g < 8; g++) s += red[g][o * 32 + tid];
            s += kprev[(size_t)o * HWSZ + hwg];
            k2[o] = s;
            out[(size_t)(17 + o) * HWSZ + hwg] = s;
        }
        #pragma unroll
        for (int o = 0; o < 4; o++) {
            float s = bbb[o];
            #pragma unroll
            for (int g = 0; g < 8; g++) s += red[g][(34 + o) * 32 + tid];
            b2[o] = s;
        }

        float left = 1e30f, right = -1e30f, top = 1e30f, bot = -1e30f;
        #pragma unroll
        for (int i = 0; i < 17; i++) {
            float py = k2[2 * i];
            float px = k2[2 * i + 1];
            top   = fminf(top, py);   bot   = fmaxf(bot, py);
            left  = fminf(left, px);  right = fmaxf(right, px);
        }
        float cx = (left + right) * 0.5f;
        float cy = (top + bot) * 0.5f;
        float hwid = (cx - left) * expf(b2[0]);
        float hhei = (cy - top)  * expf(b2[1]);
        cx += b2[2];
        cy += b2[3];
        out[(size_t)(13 + 0) * HWSZ + hwg] = cx - hwid;
        out[(size_t)(13 + 1) * HWSZ + hwg] = cy - hhei;
        out[(size_t)(13 + 2) * HWSZ + hwg] = cx + hwid;
        out[(size_t)(13 + 3) * HWSZ + hwg] = cy + hhei;
    }
}

// ---------------------------------------------------------------------------
// Launch
// ---------------------------------------------------------------------------
extern "C" void kernel_launch(void* const* d_in, const int* in_sizes, int n_in,
                              void* d_out, int out_size)
{
    const float* cls_feat = (const float*)d_in[0];
    const float* pts_feat = (const float*)d_in[1];
    const float* kprev    = (const float*)d_in[2];
    const float* w_do     = (const float*)d_in[3];
    const float* b_do     = (const float*)d_in[4];
    const float* w_cls    = (const float*)d_in[14];
    const float* b_cls    = (const float*)d_in[15];
    const float* w_kpt    = (const float*)d_in[16];
    const float* b_kpt    = (const float*)d_in[17];
    const float* w_bbox   = (const float*)d_in[18];
    const float* b_bbox   = (const float*)d_in[19];
    float* out = (float*)d_out;

    cudaFuncSetAttribute(k_mma, cudaFuncAttributeMaxDynamicSharedMemorySize,
                         SMEM_DYN);

    k_corners<<<dim3(NPTS, HWSZ / 256), 256>>>(kprev, w_do, b_do);

    W9 ws;
    for (int i = 0; i < 9; i++) ws.p[i] = (const float*)d_in[5 + i];
    k_wt<<<dim3(256, 9), 256>>>(ws);

    k_ft<<<dim3(HWSZ / 32, 256 / 32, 2), dim3(32, 8)>>>(cls_feat, pts_feat);

    // materialize sampled tensor S (fp16), warp-per-row coalesced gather
    k_sg<<<dim3(NPTS * 128, 2), 256>>>();

    // 9 block-diagonal sub-GEMMs, M128 x N128 x K64, 3-stage cp.async fp16
    k_mma<<<dim3(HWSZ / 128, 2, 9), 256, SMEM_DYN>>>();

    k_head_cls<<<HWSZ / 32, 256>>>(w_cls, b_cls, out);
    k_head_pts<<<HWSZ / 32, 256>>>(w_kpt, b_kpt, w_bbox, b_bbox, kprev, out);
}

// round 17
// speedup vs baseline: 8.6503x; 1.1193x over previous
#include <cuda_runtime.h>
#include <cuda_fp16.h>
#include <math.h>
#include <stdint.h>

// ---------------------------------------------------------------------------
// Problem constants (B=1, C=256, H=W=64, FC=256, kernels 3/5/7 -> 83 points)
// ---------------------------------------------------------------------------
#define HWSZ 4096
#define NPTS 83
#define KTOT 21248         // 83*256 packed weight K layout

// ---------------------------------------------------------------------------
// Device scratch  (g_s = 348MB fp16 sampled tensor; rest small)
// ---------------------------------------------------------------------------
__device__ __align__(16) int   g_cidx[NPTS * HWSZ * 4];
__device__ __align__(16) float g_cw  [NPTS * HWSZ * 4];
__device__ __half g_wa[3][(size_t)256 * KTOT];            // fp16 weights [m][k]
__device__ __half g_fth[2][(size_t)HWSZ * 256];           // fp16 feat [hw][c]
__device__ __half g_s[2][(size_t)NPTS * HWSZ * 256];      // sampled S [p][hw][c]
__device__ __half g_dfm[3][(size_t)768 * HWSZ];           // relu(deform conv), fp16

// ---------------------------------------------------------------------------
// helpers
// ---------------------------------------------------------------------------
__device__ __forceinline__ uint32_t smem_to_u32(const void* p) {
    uint32_t a;
    asm("{ .reg .u64 t; cvta.to.shared.u64 t, %1; cvt.u32.u64 %0, t; }"
        : "=r"(a) : "l"(p));
    return a;
}
#define SWZ(o) ((o) ^ (((o) >> 3) & 0x70))

__device__ __forceinline__ void ldsm4(uint32_t addr, uint32_t* r) {
    asm volatile("ldmatrix.sync.aligned.m8n8.x4.shared.b16 {%0,%1,%2,%3}, [%4];"
        : "=r"(r[0]), "=r"(r[1]), "=r"(r[2]), "=r"(r[3]) : "r"(addr));
}
__device__ __forceinline__ void mma16816f(float* c, const uint32_t* a,
                                          uint32_t b0, uint32_t b1) {
    asm volatile(
        "mma.sync.aligned.m16n8k16.row.col.f32.f16.f16.f32 "
        "{%0,%1,%2,%3}, {%4,%5,%6,%7}, {%8,%9}, {%0,%1,%2,%3};"
        : "+f"(c[0]), "+f"(c[1]), "+f"(c[2]), "+f"(c[3])
        : "r"(a[0]), "r"(a[1]), "r"(a[2]), "r"(a[3]), "r"(b0), "r"(b1));
}
__device__ __forceinline__ void cpa16(uint32_t dst, const void* src) {
    asm volatile("cp.async.cg.shared.global [%0], [%1], 16;"
                 :: "r"(dst), "l"(src) : "memory");
}
#define CPA_COMMIT() asm volatile("cp.async.commit_group;" ::: "memory")
#define CPA_WAIT0()  asm volatile("cp.async.wait_group 0;" ::: "memory")
#define CPA_WAIT1()  asm volatile("cp.async.wait_group 1;" ::: "memory")

// per-stage smem: A 16KB | B 32KB = 48KB, x3 stages = 144KB (1 CTA/SM, 512 thr)
#define S_A 0
#define S_B 16384
#define STAGE 49152
#define SMEM_DYN (3 * STAGE)

// ---------------------------------------------------------------------------
// Kernel 1: fused offset 1x1 conv + bilinear corner table.
// ---------------------------------------------------------------------------
__global__ void k_corners(const float* __restrict__ kprev,
                          const float* __restrict__ w_do,
                          const float* __restrict__ b_do)
{
    int kk = blockIdx.x;
    int hw = blockIdx.y * 256 + threadIdx.x;
    int h = hw >> 6, w = hw & 63;

    int base, kkl;
    if (kk < 9)       { base = 0;  kkl = kk;      }
    else if (kk < 34) { base = 18; kkl = kk - 9;  }
    else              { base = 68; kkl = kk - 34; }
    int chy = base + 2 * kkl;
    int chx = chy + 1;

    float dy = b_do[chy], dx = b_do[chx];
    #pragma unroll 2
    for (int i = 0; i < 34; i++) {
        float v = kprev[i * HWSZ + hw];
        dy = fmaf(w_do[chy * 34 + i], v, dy);
        dx = fmaf(w_do[chx * 34 + i], v, dx);
    }

    float y = (float)h + dy;
    float x = (float)w + dx;
    float y0f = floorf(y), x0f = floorf(x);
    int y0 = (int)y0f, x0 = (int)x0f;
    float wy = y - y0f, wx = x - x0f;

    int   yi[4] = { y0, y0, y0 + 1, y0 + 1 };
    int   xi[4] = { x0, x0 + 1, x0, x0 + 1 };
    float wb[4] = { (1.f - wy) * (1.f - wx), (1.f - wy) * wx,
                    wy * (1.f - wx),         wy * wx };

    int o = (kk * HWSZ + hw) * 4;
    #pragma unroll
    for (int j = 0; j < 4; j++) {
        bool valid = (yi[j] >= 0) && (yi[j] < 64) && (xi[j] >= 0) && (xi[j] < 64);
        int yc = min(max(yi[j], 0), 63);
        int xc = min(max(xi[j], 0), 63);
        g_cidx[o + j] = yc * 64 + xc;
        g_cw  [o + j] = valid ? wb[j] : 0.0f;
    }
}

// ---------------------------------------------------------------------------
// Kernel 2: weight transpose to fp16 (division-free).
// ---------------------------------------------------------------------------
struct W9 { const float* p[9]; };

__global__ void k_wt(W9 ws)
{
    int sub = blockIdx.y;
    int branch = sub / 3;
    int ks = sub - branch * 3;
    int Kp    = (ks == 0) ? 9 : (ks == 1) ? 25 : 49;
    int kbase = (ks == 0) ? 0 : (ks == 1) ? 9  : 34;
    int o = blockIdx.x;
    int c = threadIdx.x;

    const float* src = ws.p[sub] + ((size_t)o * 256 + c) * Kp;
    __half* dh = g_wa[branch] + (size_t)o * KTOT + (size_t)kbase * 256 + c;

    for (int kkl = 0; kkl < Kp; kkl++)
        dh[(size_t)kkl * 256] = __float2half_rn(src[kkl]);
}

// ---------------------------------------------------------------------------
// Kernel 3: feature transpose [c][hw] -> fp16 [hw][c]
// ---------------------------------------------------------------------------
__global__ void k_ft(const float* __restrict__ f0, const float* __restrict__ f1)
{
    __shared__ float t[32][33];
    int f = blockIdx.z;
    const float* __restrict__ src = f ? f1 : f0;
    int hw0 = blockIdx.x * 32, c0 = blockIdx.y * 32;
    #pragma unroll
    for (int i = 0; i < 4; i++) {
        int c = c0 + threadIdx.y + i * 8;
        t[threadIdx.y + i * 8][threadIdx.x] = src[(size_t)c * HWSZ + hw0 + threadIdx.x];
    }
    __syncthreads();
    #pragma unroll
    for (int i = 0; i < 4; i++) {
        int hw = hw0 + threadIdx.y + i * 8;
        g_fth[f][(size_t)hw * 256 + c0 + threadIdx.x] =
            __float2half_rn(t[threadIdx.x][threadIdx.y + i * 8]);
    }
}

// ---------------------------------------------------------------------------
// Kernel 4: build sampled tensor S[f][p][hw][c] fp16 — WARP-PER-ROW.
// ---------------------------------------------------------------------------
__global__ void __launch_bounds__(256) k_sg()
{
    int tid  = threadIdx.x;
    int wid  = tid >> 5;
    int lane = tid & 31;
    int bx = blockIdx.x;
    int p   = bx >> 7;              // 0..82
    int hw0 = (bx & 127) * 32;      // 32 rows per block
    int f = blockIdx.y;

    const __half* __restrict__ F = g_fth[f];
    __half* __restrict__ Sp = g_s[f] + ((size_t)p * HWSZ + hw0) * 256;

    #pragma unroll
    for (int i = 0; i < 4; i++) {
        int hwl = wid * 4 + i;
        int hw = hw0 + hwl;
        int o = (p * HWSZ + hw) * 4;    // warp-uniform -> broadcast loads
        int4   id4 = *reinterpret_cast<const int4*>(&g_cidx[o]);
        float4 wv4 = *reinterpret_cast<const float4*>(&g_cw[o]);

        uint4 v0 = *reinterpret_cast<const uint4*>(F + (size_t)id4.x * 256 + lane * 8);
        uint4 v1 = *reinterpret_cast<const uint4*>(F + (size_t)id4.y * 256 + lane * 8);
        uint4 v2 = *reinterpret_cast<const uint4*>(F + (size_t)id4.z * 256 + lane * 8);
        uint4 v3 = *reinterpret_cast<const uint4*>(F + (size_t)id4.w * 256 + lane * 8);

        const __half2* a2 = reinterpret_cast<const __half2*>(&v0);
        const __half2* b2 = reinterpret_cast<const __half2*>(&v1);
        const __half2* c2 = reinterpret_cast<const __half2*>(&v2);
        const __half2* d2 = reinterpret_cast<const __half2*>(&v3);

        uint4 outv;
        uint32_t* op = reinterpret_cast<uint32_t*>(&outv);
        #pragma unroll
        for (int k = 0; k < 4; k++) {
            float2 a = __half22float2(a2[k]);
            float2 b = __half22float2(b2[k]);
            float2 c = __half22float2(c2[k]);
            float2 d = __half22float2(d2[k]);
            float vx = wv4.x*a.x + wv4.y*b.x + wv4.z*c.x + wv4.w*d.x;
            float vy = wv4.x*a.y + wv4.y*b.y + wv4.z*c.y + wv4.w*d.y;
            __half2 hv = __floats2half2_rn(vx, vy);
            op[k] = *reinterpret_cast<uint32_t*>(&hv);
        }
        *reinterpret_cast<uint4*>(Sp + (size_t)hwl * 256 + lane * 8) = outv;
    }
}

// ---------------------------------------------------------------------------
// Kernel 5: pure cp.async fp16 HMMA GEMM, 3-stage pipeline.
//   9 block-diagonal sub-GEMMs. Block M128 x N256 x K64, 512 threads =
//   16 warps (2M x 8N), warp tile 64x32, 1 CTA/SM but 32 warps/SM (50% occ).
//   Grid (16n, 2m, 9sub).
// ---------------------------------------------------------------------------
__global__ void __launch_bounds__(512, 1) k_mma()
{
    const int SUBMAP[9] = {2, 5, 8, 1, 4, 7, 0, 3, 6};  // heavy (k7) first
    const int P0_[3] = {0, 9, 34};
    const int NP_[3] = {9, 25, 49};

    extern __shared__ __align__(128) char smem[];
    uint32_t sb = smem_to_u32(smem);

    int tid = threadIdx.x;
    int wid = tid >> 5;
    int lid = tid & 31;

    int sub = SUBMAP[blockIdx.z];
    int branch = sub / 3;
    int ks = sub - branch * 3;
    int p0 = P0_[ks];
    int np = NP_[ks];

    int n0 = blockIdx.x * 256;
    int m0 = blockIdx.y * 128;
    const __half* __restrict__ Sf = g_s[branch == 0 ? 0 : 1];
    const __half* __restrict__ Ah = g_wa[branch];
    __half* __restrict__ Cp = g_dfm[branch] + (size_t)ks * 256 * HWSZ;

    int wm = wid >> 3;            // 0..1 -> m offset wm*64
    int wn = wid & 7;             // 0..7 -> n offset wn*32

    // fill mapping: A 128 rows x 128B -> 32B/thread; B 256 rows x 128B -> 64B/thread
    int fa_row = tid >> 2;            // 0..127
    int fa_seg = (tid & 3);           // *32B
    int fb_row = tid >> 1;            // 0..255
    int fb_seg = (tid & 1) * 4;       // 0 or 4 (16B units)

    uint32_t a_row = wm * 64 + ((lid >> 3) & 1) * 8 + (lid & 7);
    uint32_t a_byt = (lid >> 4) * 16;
    uint32_t b_row = wn * 32 + (lid & 7) + ((lid >> 4) & 1) * 8;
    uint32_t b_byt = ((lid >> 3) & 1) * 16;

    float acc[4][4][4];
    #pragma unroll
    for (int i = 0; i < 4; i++)
        #pragma unroll
        for (int j = 0; j < 4; j++)
            #pragma unroll
            for (int r = 0; r < 4; r++) acc[i][j][r] = 0.f;

    int nchunk = np * 4;

    auto fill = [&](int ch, uint32_t stage_base) {
        int gp  = p0 + (ch >> 2);
        int c0v = (ch & 3) * 64;
        // A: 128 rows (m0..m0+127) x 128B, 2 x 16B per thread
        {
            const __half* src = Ah + (size_t)(m0 + fa_row) * KTOT + gp * 256
                                   + c0v + fa_seg * 16;
            uint32_t d = stage_base + S_A;
            #pragma unroll
            for (int j = 0; j < 2; j++)
                cpa16(d + SWZ((uint32_t)(fa_row * 128 + (fa_seg * 2 + j) * 16)),
                      src + j * 8);
        }
        // B: 256 rows (n0..n0+255) x 128B, 4 x 16B per thread
        {
            const __half* src = Sf + ((size_t)gp * HWSZ + n0 + fb_row) * 256
                                   + c0v + fb_seg * 8;
            uint32_t d = stage_base + S_B;
            #pragma unroll
            for (int j = 0; j < 4; j++)
                cpa16(d + SWZ((uint32_t)(fb_row * 128 + (fb_seg + j) * 16)),
                      src + j * 8);
        }
    };

    // prologue: fill stages 0 and 1
    fill(0, sb);
    CPA_COMMIT();
    if (nchunk > 1) { fill(1, sb + STAGE); }
    CPA_COMMIT();
    CPA_WAIT1();
    __syncthreads();

    int stage = 0;
    for (int ch = 0; ch < nchunk; ch++) {
        uint32_t cur_base = sb + stage * STAGE;

        bool has_fill = (ch + 2) < nchunk;
        if (has_fill) {
            int nstage = stage + 2; if (nstage >= 3) nstage -= 3;
            fill(ch + 2, sb + nstage * STAGE);
            CPA_COMMIT();
        }

        // math on current stage: 4 ksteps x 16 mma per warp
        #pragma unroll
        for (int ks2 = 0; ks2 < 4; ks2++) {
            uint32_t kb = ks2 * 32;
            uint32_t ah[4][4], bh[2][4];
            #pragma unroll
            for (int mi = 0; mi < 4; mi++)
                ldsm4(cur_base + S_A + SWZ((a_row + mi * 16) * 128 + kb + a_byt), ah[mi]);
            #pragma unroll
            for (int bj = 0; bj < 2; bj++)
                ldsm4(cur_base + S_B + SWZ((b_row + bj * 16) * 128 + kb + b_byt), bh[bj]);
            #pragma unroll
            for (int mi = 0; mi < 4; mi++)
                #pragma unroll
                for (int nj = 0; nj < 4; nj++)
                    mma16816f(acc[mi][nj], ah[mi], bh[nj >> 1][(nj & 1) * 2],
                              bh[nj >> 1][(nj & 1) * 2 + 1]);
        }

        if (has_fill) { CPA_WAIT1(); } else { CPA_WAIT0(); }
        __syncthreads();
        stage = (stage + 1 == 3) ? 0 : stage + 1;
    }

    // epilogue: relu + fp16 store
    int l4 = lid >> 2;
    int l2 = (lid & 3) * 2;
    #pragma unroll
    for (int mi = 0; mi < 4; mi++) {
        #pragma unroll
        for (int nj = 0; nj < 4; nj++) {
            int m = m0 + wm * 64 + mi * 16 + l4;
            int n = n0 + wn * 32 + nj * 8 + l2;
            __half2 h0 = __floats2half2_rn(fmaxf(acc[mi][nj][0], 0.f),
                                           fmaxf(acc[mi][nj][1], 0.f));
            __half2 h1 = __floats2half2_rn(fmaxf(acc[mi][nj][2], 0.f),
                                           fmaxf(acc[mi][nj][3], 0.f));
            *reinterpret_cast<__half2*>(Cp + (size_t)m * HWSZ + n) = h0;
            *reinterpret_cast<__half2*>(Cp + (size_t)(m + 8) * HWSZ + n) = h1;
        }
    }
}

// ---------------------------------------------------------------------------
// Kernel 6: cls head (fp16 dfm input).
// ---------------------------------------------------------------------------
__global__ void __launch_bounds__(256) k_head_cls(const float* __restrict__ wcls,
                                                  const float* __restrict__ bcls,
                                                  float* __restrict__ out)
{
    __shared__ float red[8][13 * 32];
    int tid = threadIdx.x;
    int cg = tid >> 5;
    int hwl = tid & 31;
    int hw = blockIdx.x * 32 + hwl;

    float acc[13];
    #pragma unroll
    for (int o = 0; o < 13; o++) acc[o] = 0.f;
    const __half* __restrict__ d = g_dfm[0];
    int c0 = cg * 96;
    for (int c = c0; c < c0 + 96; c++) {
        float v = __half2float(d[(size_t)c * HWSZ + hw]);
        #pragma unroll
        for (int o = 0; o < 13; o++)
            acc[o] = fmaf(wcls[o * 768 + c], v, acc[o]);
    }
    #pragma unroll
    for (int o = 0; o < 13; o++) red[cg][o * 32 + hwl] = acc[o];
    __syncthreads();

    if (tid < 32) {
        #pragma unroll
        for (int o = 0; o < 13; o++) {
            float s = bcls[o];
            #pragma unroll
            for (int g = 0; g < 8; g++) s += red[g][o * 32 + tid];
            out[(size_t)o * HWSZ + blockIdx.x * 32 + tid] = s;
        }
    }
}

// ---------------------------------------------------------------------------
// Kernel 7: kpt + bbox heads + minmax bbox decode (fused, fp16 dfm input).
// ---------------------------------------------------------------------------
__global__ void __launch_bounds__(256) k_head_pts(const float* __restrict__ wkpt,
                                                  const float* __restrict__ bkpt,
                                                  const float* __restrict__ wbb,
                                                  const float* __restrict__ bbb,
                                                  const float* __restrict__ kprev,
                                                  float* __restrict__ out)
{
    __shared__ float red[8][38 * 32];
    int tid = threadIdx.x;
    int cg = tid >> 5;
    int hwl = tid & 31;
    int hw = blockIdx.x * 32 + hwl;

    float acck[34], accb[4];
    #pragma unroll
    for (int o = 0; o < 34; o++) acck[o] = 0.f;
    #pragma unroll
    for (int o = 0; o < 4; o++)  accb[o] = 0.f;

    const __half* __restrict__ dk = g_dfm[1];
    const __half* __restrict__ db = g_dfm[2];
    int c0 = cg * 96;
    for (int c = c0; c < c0 + 96; c++) {
        float vk = __half2float(dk[(size_t)c * HWSZ + hw]);
        float vb = __half2float(db[(size_t)c * HWSZ + hw]);
        #pragma unroll
        for (int o = 0; o < 34; o++)
            acck[o] = fmaf(wkpt[o * 768 + c], vk, acck[o]);
        #pragma unroll
        for (int o = 0; o < 4; o++)
            accb[o] = fmaf(wbb[o * 768 + c], vb, accb[o]);
    }
    #pragma unroll
    for (int o = 0; o < 34; o++) red[cg][o * 32 + hwl] = acck[o];
    #pragma unroll
    for (int o = 0; o < 4; o++)  red[cg][(34 + o) * 32 + hwl] = accb[o];
    __syncthreads();

    if (tid < 32) {
        int hwg = blockIdx.x * 32 + tid;
        float k2[34], b2[4];
        #pragma unroll
        for (int o = 0; o < 34; o++) {
            float s = bkpt[o];
            #pragma unroll
            for (int g = 0; g < 8; g++) s += red[g][o * 32 + tid];
            s += kprev[(size_t)o * HWSZ + hwg];
            k2[o] = s;
            out[(size_t)(17 + o) * HWSZ + hwg] = s;
        }
        #pragma unroll
        for (int o = 0; o < 4; o++) {
            float s = bbb[o];
            #pragma unroll
            for (int g = 0; g < 8; g++) s += red[g][(34 + o) * 32 + tid];
            b2[o] = s;
        }

        float left = 1e30f, right = -1e30f, top = 1e30f, bot = -1e30f;
        #pragma unroll
        for (int i = 0; i < 17; i++) {
            float py = k2[2 * i];
            float px = k2[2 * i + 1];
            top   = fminf(top, py);   bot   = fmaxf(bot, py);
            left  = fminf(left, px);  right = fmaxf(right, px);
        }
        float cx = (left + right) * 0.5f;
        float cy = (top + bot) * 0.5f;
        float hwid = (cx - left) * expf(b2[0]);
        float hhei = (cy - top)  * expf(b2[1]);
        cx += b2[2];
        cy += b2[3];
        out[(size_t)(13 + 0) * HWSZ + hwg] = cx - hwid;
        out[(size_t)(13 + 1) * HWSZ + hwg] = cy - hhei;
        out[(size_t)(13 + 2) * HWSZ + hwg] = cx + hwid;
        out[(size_t)(13 + 3) * HWSZ + hwg] = cy + hhei;
    }
}

// ---------------------------------------------------------------------------
// Launch
// ---------------------------------------------------------------------------
extern "C" void kernel_launch(void* const* d_in, const int* in_sizes, int n_in,
                              void* d_out, int out_size)
{
    const float* cls_feat = (const float*)d_in[0];
    const float* pts_feat = (const float*)d_in[1];
    const float* kprev    = (const float*)d_in[2];
    const float* w_do     = (const float*)d_in[3];
    const float* b_do     = (const float*)d_in[4];
    const float* w_cls    = (const float*)d_in[14];
    const float* b_cls    = (const float*)d_in[15];
    const float* w_kpt    = (const float*)d_in[16];
    const float* b_kpt    = (const float*)d_in[17];
    const float* w_bbox   = (const float*)d_in[18];
    const float* b_bbox   = (const float*)d_in[19];
    float* out = (float*)d_out;

    cudaFuncSetAttribute(k_mma, cudaFuncAttributeMaxDynamicSharedMemorySize,
                         SMEM_DYN);

    k_corners<<<dim3(NPTS, HWSZ / 256), 256>>>(kprev, w_do, b_do);

    W9 ws;
    for (int i = 0; i < 9; i++) ws.p[i] = (const float*)d_in[5 + i];
    k_wt<<<dim3(256, 9), 256>>>(ws);

    k_ft<<<dim3(HWSZ / 32, 256 / 32, 2), dim3(32, 8)>>>(cls_feat, pts_feat);

    // materialize sampled tensor S (fp16), warp-per-row coalesced gather
    k_sg<<<dim3(NPTS * 128, 2), 256>>>();

    // 9 block-diagonal sub-GEMMs, M128 x N256 x K64, 512 thr, 3-stage cp.async
    k_mma<<<dim3(HWSZ / 256, 2, 9), 512, SMEM_DYN>>>();

    k_head_cls<<<HWSZ / 32, 256>>>(w_cls, b_cls, out);
    k_head_pts<<<HWSZ / 32, 256>>>(w_kpt, b_kpt, w_bbox, b_bbox, kprev, out);
}